// round 5
// baseline (speedup 1.0000x reference)
#include <cuda_runtime.h>
#include <cuda_bf16.h>
#include <math.h>
#include <stdint.h>

// ---------------------------------------------------------------------------
// Problem constants
// ---------------------------------------------------------------------------
#define BATCH   2
#define SEQ     2048
#define EMBED   1024
#define HEADS   16
#define DK      64
#define FFN     4096
#define MROWS   (BATCH * SEQ)          // 4096
#define LN_EPS  1e-5f
#define SSC     0.1803368801111204f    // 0.125 * log2(e)
#define HSZ     (MROWS * EMBED)        // 4M elements

// GEMM tiling: CTA 128x128, K-chunk 64, warp tile 32x64 (8 warps: 4m x 2n)
#define CTM 128
#define CTN 128
#define KTC 64
#define STG 65536                      // Ah 16K + Al 16K + Bh 16K + Bl 16K
#define SMEM_G (2 * STG)               // 128 KB double buffered

// Attention smem: Qh 16K + Ql 16K + 2 stages * (Kh+Kl+Vh+Vl = 32K)
#define SMEM_A (32768 + 2 * 32768)     // 96 KB

#define SW128(o) ((o) ^ (((o) >> 3) & 0x70))

// ---------------------------------------------------------------------------
// Scratch buffers (allocation-free: __device__ globals)
// ---------------------------------------------------------------------------
__device__ __nv_bfloat16 g_h_hi  [HSZ];
__device__ __nv_bfloat16 g_h_lo  [HSZ];
__device__ __nv_bfloat16 g_qkv_hi[3 * HSZ];   // q | k | v, each [B,H,S,DK]
__device__ __nv_bfloat16 g_qkv_lo[3 * HSZ];
__device__ __nv_bfloat16 g_ao_hi [HSZ];
__device__ __nv_bfloat16 g_ao_lo [HSZ];
__device__ float         g_x1    [HSZ];
__device__ __nv_bfloat16 g_h2_hi [HSZ];
__device__ __nv_bfloat16 g_h2_lo [HSZ];
__device__ __nv_bfloat16 g_f_hi  [MROWS * FFN];
__device__ __nv_bfloat16 g_f_lo  [MROWS * FFN];

__device__ __nv_bfloat16 g_wqkv_hi[3 * EMBED * EMBED];  // Wq | Wk | Wv
__device__ __nv_bfloat16 g_wqkv_lo[3 * EMBED * EMBED];
__device__ __nv_bfloat16 g_wo_hi[EMBED * EMBED];
__device__ __nv_bfloat16 g_wo_lo[EMBED * EMBED];
__device__ __nv_bfloat16 g_w1_hi[FFN * EMBED];
__device__ __nv_bfloat16 g_w1_lo[FFN * EMBED];
__device__ __nv_bfloat16 g_w2_hi[EMBED * FFN];
__device__ __nv_bfloat16 g_w2_lo[EMBED * FFN];
__device__ float         g_bqkv[3 * EMBED];

// ---------------------------------------------------------------------------
// helpers
// ---------------------------------------------------------------------------
static __device__ __forceinline__ uint32_t s2u(const void* p) {
    uint32_t a;
    asm("{ .reg .u64 t; cvta.to.shared.u64 t, %1; cvt.u32.u64 %0, t; }"
        : "=r"(a) : "l"(p));
    return a;
}
static __device__ __forceinline__ void cpa16(uint32_t s, const void* g) {
    asm volatile("cp.async.cg.shared.global [%0], [%1], 16;"
                 :: "r"(s), "l"(g) : "memory");
}
static __device__ __forceinline__ void ldsm4(uint32_t* f, uint32_t a) {
    asm volatile("ldmatrix.sync.aligned.m8n8.x4.shared.b16 {%0,%1,%2,%3}, [%4];"
                 : "=r"(f[0]), "=r"(f[1]), "=r"(f[2]), "=r"(f[3]) : "r"(a));
}
static __device__ __forceinline__ void ldsm4t(uint32_t* f, uint32_t a) {
    asm volatile("ldmatrix.sync.aligned.m8n8.x4.trans.shared.b16 {%0,%1,%2,%3}, [%4];"
                 : "=r"(f[0]), "=r"(f[1]), "=r"(f[2]), "=r"(f[3]) : "r"(a));
}
static __device__ __forceinline__ void mma16816(float* c, const uint32_t* a,
                                                uint32_t b0, uint32_t b1) {
    asm volatile(
        "mma.sync.aligned.m16n8k16.row.col.f32.bf16.bf16.f32 "
        "{%0,%1,%2,%3}, {%4,%5,%6,%7}, {%8,%9}, {%0,%1,%2,%3};"
        : "+f"(c[0]), "+f"(c[1]), "+f"(c[2]), "+f"(c[3])
        : "r"(a[0]), "r"(a[1]), "r"(a[2]), "r"(a[3]), "r"(b0), "r"(b1));
}
static __device__ __forceinline__ float ex2f(float x) {
    float y;
    asm("ex2.approx.f32 %0, %1;" : "=f"(y) : "f"(x));
    return y;
}
static __device__ __forceinline__ void split2(float v, __nv_bfloat16& h, __nv_bfloat16& l) {
    h = __float2bfloat16(v);
    l = __float2bfloat16(v - __bfloat162float(h));
}
static __device__ __forceinline__ void pack_hl(float x, float y,
                                               uint32_t& hi, uint32_t& lo) {
    __nv_bfloat16 hx, lx, hy, ly;
    split2(x, hx, lx);
    split2(y, hy, ly);
    __nv_bfloat162 H; H.x = hx; H.y = hy;
    __nv_bfloat162 L; L.x = lx; L.y = ly;
    hi = *(uint32_t*)&H;
    lo = *(uint32_t*)&L;
}

// ---------------------------------------------------------------------------
// One-shot weight split: all 6 matrices in one launch.
// Segments (in float4 units): wq 256K | wk 256K | wv 256K | wo 256K | w1 1M | w2 1M
// ---------------------------------------------------------------------------
#define NE4 (EMBED * EMBED / 4)       // 256K
#define NF4 (FFN * EMBED / 4)         // 1M
__global__ __launch_bounds__(256) void cvt_all(
    const float* __restrict__ wq, const float* __restrict__ wk,
    const float* __restrict__ wv, const float* __restrict__ wo,
    const float* __restrict__ w1, const float* __restrict__ w2,
    __nv_bfloat16* __restrict__ qkv_hi, __nv_bfloat16* __restrict__ qkv_lo,
    __nv_bfloat16* __restrict__ wo_hi,  __nv_bfloat16* __restrict__ wo_lo,
    __nv_bfloat16* __restrict__ w1_hi,  __nv_bfloat16* __restrict__ w1_lo,
    __nv_bfloat16* __restrict__ w2_hi,  __nv_bfloat16* __restrict__ w2_lo)
{
    int i = blockIdx.x * 256 + threadIdx.x;    // float4 index, < 3M
    const float* src;
    __nv_bfloat16 *dh, *dl;
    int j = i;
    if (i < 3 * NE4) {                          // fused qkv weights
        src = (i < NE4) ? wq : (i < 2 * NE4) ? wk : wv;
        j = (i < NE4) ? i : (i < 2 * NE4) ? i - NE4 : i - 2 * NE4;
        dh = qkv_hi + (size_t)(i - j) * 4; dl = qkv_lo + (size_t)(i - j) * 4;
    } else if (i < 4 * NE4) {
        src = wo; j = i - 3 * NE4; dh = wo_hi; dl = wo_lo;
    } else if (i < 4 * NE4 + NF4) {
        src = w1; j = i - 4 * NE4; dh = w1_hi; dl = w1_lo;
    } else {
        src = w2; j = i - 4 * NE4 - NF4; dh = w2_hi; dl = w2_lo;
    }
    float4 v = ((const float4*)src)[j];
    uint32_t h0, l0, h1, l1;
    pack_hl(v.x, v.y, h0, l0);
    pack_hl(v.z, v.w, h1, l1);
    uint2 H; H.x = h0; H.y = h1;
    uint2 L; L.x = l0; L.y = l1;
    ((uint2*)dh)[j] = H;
    ((uint2*)dl)[j] = L;
}

// ---------------------------------------------------------------------------
// LayerNorm: one block per row, writes (hi, lo) bf16
// ---------------------------------------------------------------------------
__global__ __launch_bounds__(256) void ln_kernel(
    const float* __restrict__ x, const float* __restrict__ g,
    const float* __restrict__ be, __nv_bfloat16* __restrict__ ohi,
    __nv_bfloat16* __restrict__ olo)
{
    const int N = EMBED;
    const size_t row = blockIdx.x;
    const float* xr = x + row * N;
    float s = 0.f, s2 = 0.f;
    #pragma unroll
    for (int i = threadIdx.x; i < N; i += 256) {
        float v = xr[i];
        s += v; s2 += v * v;
    }
    #pragma unroll
    for (int o = 16; o; o >>= 1) {
        s  += __shfl_xor_sync(0xffffffffu, s,  o);
        s2 += __shfl_xor_sync(0xffffffffu, s2, o);
    }
    __shared__ float red[16];
    __shared__ float mu_sh, rs_sh;
    int w = threadIdx.x >> 5, l = threadIdx.x & 31;
    if (l == 0) { red[w] = s; red[8 + w] = s2; }
    __syncthreads();
    if (threadIdx.x == 0) {
        float ts = 0.f, ts2 = 0.f;
        #pragma unroll
        for (int i = 0; i < 8; i++) { ts += red[i]; ts2 += red[8 + i]; }
        float mu  = ts / N;
        float var = ts2 / N - mu * mu;
        mu_sh = mu;
        rs_sh = rsqrtf(var + LN_EPS);
    }
    __syncthreads();
    float mu = mu_sh, rs = rs_sh;
    #pragma unroll
    for (int i = threadIdx.x; i < N; i += 256) {
        float y = (xr[i] - mu) * rs * g[i] + be[i];
        __nv_bfloat16 h, lo;
        split2(y, h, lo);
        ohi[row * N + i] = h;
        olo[row * N + i] = lo;
    }
}

// ---------------------------------------------------------------------------
// mma.sync split-bf16 GEMM: C[M,N] = A[M,K] @ W[N,K]^T (+bias,+relu,+res)
// CTA 128x128, warp tile 32x64, KTC 64, double-buffered cp.async.
// EPI: 2 = bias+res -> fp32; 5 = bias+relu -> (hi,lo);
//      6 = bias -> (hi,lo) fused-QKV head layout (N=3072)
// ---------------------------------------------------------------------------
template <int EPI>
__global__ __launch_bounds__(256, 1) void gemm_mma(
    const __nv_bfloat16* __restrict__ Ah, const __nv_bfloat16* __restrict__ Al,
    const __nv_bfloat16* __restrict__ Bh, const __nv_bfloat16* __restrict__ Bl,
    const float* __restrict__ bias, const float* __restrict__ res,
    float* __restrict__ Cf, __nv_bfloat16* __restrict__ Chi,
    __nv_bfloat16* __restrict__ Clo, int M, int N, int K)
{
    extern __shared__ char smem[];
    const uint32_t sb = s2u(smem);
    const int tid = threadIdx.x;
    const int lane = tid & 31, w = tid >> 5;
    const int bm = blockIdx.y * CTM, bn = blockIdx.x * CTN;
    const int wm = (w & 3) * 32, wn = (w >> 2) * 64;

    float acc[2][8][4];
    #pragma unroll
    for (int mt = 0; mt < 2; mt++)
        #pragma unroll
        for (int nt = 0; nt < 8; nt++)
            #pragma unroll
            for (int i = 0; i < 4; i++) acc[mt][nt][i] = 0.f;

    const int NC = K / KTC;

    auto load_chunk = [&](int c, int st) {
        const uint32_t s0 = sb + st * STG;
        const size_t k0 = (size_t)c * KTC;
        #pragma unroll
        for (int i = 0; i < 4; i++) {                 // A: 128 rows x 128B
            int idx = i * 256 + tid;
            int row = idx >> 3, c16 = idx & 7;
            uint32_t so = SW128((uint32_t)(row * 128 + c16 * 16));
            const size_t g = (size_t)(bm + row) * K + k0 + c16 * 8;
            cpa16(s0 + so,         Ah + g);
            cpa16(s0 + 16384 + so, Al + g);
        }
        #pragma unroll
        for (int i = 0; i < 4; i++) {                 // B: 128 rows x 128B
            int idx = i * 256 + tid;
            int row = idx >> 3, c16 = idx & 7;
            uint32_t so = SW128((uint32_t)(row * 128 + c16 * 16));
            const size_t g = (size_t)(bn + row) * K + k0 + c16 * 8;
            cpa16(s0 + 32768 + so, Bh + g);
            cpa16(s0 + 49152 + so, Bl + g);
        }
    };

    load_chunk(0, 0);
    asm volatile("cp.async.commit_group;" ::: "memory");

    for (int c = 0; c < NC; c++) {
        const int st = c & 1;
        if (c + 1 < NC) {
            load_chunk(c + 1, st ^ 1);
            asm volatile("cp.async.commit_group;" ::: "memory");
            asm volatile("cp.async.wait_group 1;" ::: "memory");
        } else {
            asm volatile("cp.async.wait_group 0;" ::: "memory");
        }
        __syncthreads();

        const uint32_t s0 = sb + st * STG;
        #pragma unroll
        for (int ks = 0; ks < 4; ks++) {
            uint32_t ah[2][4], alr[2][4], bh[4][4], blr[4][4];
            const int arow = wm + (lane & 15);
            const int akb  = ks * 32 + (lane >> 4) * 16;
            #pragma unroll
            for (int mt = 0; mt < 2; mt++) {
                uint32_t ao = SW128((uint32_t)((arow + mt * 16) * 128 + akb));
                ldsm4(ah[mt],  s0 + ao);
                ldsm4(alr[mt], s0 + 16384 + ao);
            }
            const int brow = wn + ((lane >> 4) << 3) + (lane & 7);
            const int bkb  = ks * 32 + ((lane >> 3) & 1) * 16;
            #pragma unroll
            for (int np = 0; np < 4; np++) {
                uint32_t bo = SW128((uint32_t)((brow + np * 16) * 128 + bkb));
                ldsm4(bh[np],  s0 + 32768 + bo);
                ldsm4(blr[np], s0 + 49152 + bo);
            }
            #pragma unroll
            for (int mt = 0; mt < 2; mt++) {
                #pragma unroll
                for (int nt = 0; nt < 8; nt++) {
                    const int np = nt >> 1, ro = (nt & 1) * 2;
                    mma16816(acc[mt][nt], ah[mt],  bh[np][ro],  bh[np][ro + 1]);
                    mma16816(acc[mt][nt], ah[mt],  blr[np][ro], blr[np][ro + 1]);
                    mma16816(acc[mt][nt], alr[mt], bh[np][ro],  bh[np][ro + 1]);
                }
            }
        }
        __syncthreads();
    }

    // ---- epilogue ----
    #pragma unroll
    for (int mt = 0; mt < 2; mt++) {
        #pragma unroll
        for (int nt = 0; nt < 8; nt++) {
            const int n = bn + wn + nt * 8 + (lane & 3) * 2;
            const float bs0 = bias[n], bs1 = bias[n + 1];
            #pragma unroll
            for (int hh = 0; hh < 2; hh++) {
                const size_t m = (size_t)bm + wm + mt * 16 + (lane >> 2) + hh * 8;
                float v0 = acc[mt][nt][hh * 2]     + bs0;
                float v1 = acc[mt][nt][hh * 2 + 1] + bs1;
                if (EPI == 5) { v0 = fmaxf(v0, 0.f); v1 = fmaxf(v1, 0.f); }
                if (EPI == 2) {
                    float2 rr = *(const float2*)(res + m * N + n);
                    v0 += rr.x; v1 += rr.y;
                }
                if (EPI == 5) {
                    uint32_t ph, pl;
                    pack_hl(v0, v1, ph, pl);
                    *(uint32_t*)(Chi + m * N + n) = ph;
                    *(uint32_t*)(Clo + m * N + n) = pl;
                } else if (EPI == 6) {
                    // n in [0,3072): which | head | dim
                    const int which = n >> 10;
                    const int h_ = (n >> 6) & (HEADS - 1), d_ = n & 63;
                    const int b_ = (int)(m >> 11), s_ = (int)(m & 2047);
                    const size_t di = (size_t)which * HSZ
                        + (((size_t)b_ * HEADS + h_) * SEQ + s_) * DK + d_;
                    uint32_t ph, pl;
                    pack_hl(v0, v1, ph, pl);
                    *(uint32_t*)(Chi + di) = ph;
                    *(uint32_t*)(Clo + di) = pl;
                } else {
                    float2 o; o.x = v0; o.y = v1;
                    *(float2*)(Cf + m * N + n) = o;
                }
            }
        }
    }
}

// ---------------------------------------------------------------------------
// Flash attention on tensor cores (split bf16, mma.sync).
// grid = (SEQ/128, HEADS, BATCH), 256 threads (8 warps, each owns 16 q rows).
// Q/K/V in [B,H,S,DK] (hi,lo) bf16. Output -> ao (hi,lo) in [B,S,E].
// ---------------------------------------------------------------------------
__global__ __launch_bounds__(256) void attn_mma(
    const __nv_bfloat16* __restrict__ Qh, const __nv_bfloat16* __restrict__ Ql,
    const __nv_bfloat16* __restrict__ Kh, const __nv_bfloat16* __restrict__ Kl,
    const __nv_bfloat16* __restrict__ Vh, const __nv_bfloat16* __restrict__ Vl,
    __nv_bfloat16* __restrict__ Ohi, __nv_bfloat16* __restrict__ Olo)
{
    extern __shared__ char smem[];
    const uint32_t sb  = s2u(smem);
    const uint32_t sQh = sb, sQl = sb + 16384;
    const int tid = threadIdx.x, lane = tid & 31, w = tid >> 5;
    const int qt = blockIdx.x, hd = blockIdx.y, b = blockIdx.z;
    const size_t hb = ((size_t)b * HEADS + hd) * SEQ * DK;
    const int m0 = qt * 128;
    const int wm = w * 16;

    #pragma unroll
    for (int i = 0; i < 4; i++) {
        int idx = i * 256 + tid;
        int row = idx >> 3, c16 = idx & 7;
        uint32_t so = SW128((uint32_t)(row * 128 + c16 * 16));
        const size_t g = hb + (size_t)(m0 + row) * DK + c16 * 8;
        cpa16(sQh + so, Qh + g);
        cpa16(sQl + so, Ql + g);
    }
    auto load_kv = [&](int c, int st) {
        const uint32_t s0 = sb + 32768 + st * 32768;
        const int k0 = c * 64;
        #pragma unroll
        for (int i = 0; i < 2; i++) {
            int idx = i * 256 + tid;
            int row = idx >> 3, c16 = idx & 7;
            uint32_t so = SW128((uint32_t)(row * 128 + c16 * 16));
            const size_t g = hb + (size_t)(k0 + row) * DK + c16 * 8;
            cpa16(s0 + so,         Kh + g);
            cpa16(s0 + 8192 + so,  Kl + g);
            cpa16(s0 + 16384 + so, Vh + g);
            cpa16(s0 + 24576 + so, Vl + g);
        }
    };
    load_kv(0, 0);
    asm volatile("cp.async.commit_group;" ::: "memory");

    uint32_t qhf[4][4], qlf[4][4];
    float o[8][4];
    #pragma unroll
    for (int j = 0; j < 8; j++)
        #pragma unroll
        for (int i = 0; i < 4; i++) o[j][i] = 0.f;
    float mr0 = -1e30f, mr1 = -1e30f, l0 = 0.f, l1 = 0.f;

    const int NC = SEQ / 64;
    for (int c = 0; c < NC; c++) {
        const int st = c & 1;
        if (c + 1 < NC) {
            load_kv(c + 1, st ^ 1);
            asm volatile("cp.async.commit_group;" ::: "memory");
            asm volatile("cp.async.wait_group 1;" ::: "memory");
        } else {
            asm volatile("cp.async.wait_group 0;" ::: "memory");
        }
        __syncthreads();

        if (c == 0) {
            #pragma unroll
            for (int ks = 0; ks < 4; ks++) {
                uint32_t ao = SW128((uint32_t)((wm + (lane & 15)) * 128
                                               + ks * 32 + (lane >> 4) * 16));
                ldsm4(qhf[ks], sQh + ao);
                ldsm4(qlf[ks], sQl + ao);
            }
        }
        const uint32_t s0 = sb + 32768 + st * 32768;

        // ---- S = Q K^T ----
        float sacc[8][4];
        #pragma unroll
        for (int j = 0; j < 8; j++)
            #pragma unroll
            for (int i = 0; i < 4; i++) sacc[j][i] = 0.f;

        #pragma unroll
        for (int ks = 0; ks < 4; ks++) {
            const int brow = ((lane >> 4) << 3) + (lane & 7);
            const int bkb  = ks * 32 + ((lane >> 3) & 1) * 16;
            #pragma unroll
            for (int np = 0; np < 4; np++) {
                uint32_t kh[4], kl[4];
                uint32_t bo = SW128((uint32_t)((brow + np * 16) * 128 + bkb));
                ldsm4(kh, s0 + bo);
                ldsm4(kl, s0 + 8192 + bo);
                mma16816(sacc[np * 2],     qhf[ks], kh[0], kh[1]);
                mma16816(sacc[np * 2],     qhf[ks], kl[0], kl[1]);
                mma16816(sacc[np * 2],     qlf[ks], kh[0], kh[1]);
                mma16816(sacc[np * 2 + 1], qhf[ks], kh[2], kh[3]);
                mma16816(sacc[np * 2 + 1], qhf[ks], kl[2], kl[3]);
                mma16816(sacc[np * 2 + 1], qlf[ks], kh[2], kh[3]);
            }
        }

        // ---- online softmax ----
        float cm0 = -1e30f, cm1 = -1e30f;
        #pragma unroll
        for (int j = 0; j < 8; j++) {
            cm0 = fmaxf(cm0, fmaxf(sacc[j][0], sacc[j][1]));
            cm1 = fmaxf(cm1, fmaxf(sacc[j][2], sacc[j][3]));
        }
        #pragma unroll
        for (int off = 1; off <= 2; off <<= 1) {
            cm0 = fmaxf(cm0, __shfl_xor_sync(0xffffffffu, cm0, off));
            cm1 = fmaxf(cm1, __shfl_xor_sync(0xffffffffu, cm1, off));
        }
        const float mn0 = fmaxf(mr0, cm0), mn1 = fmaxf(mr1, cm1);
        const float a0 = ex2f((mr0 - mn0) * SSC);
        const float a1 = ex2f((mr1 - mn1) * SSC);
        mr0 = mn0; mr1 = mn1;
        float sum0 = 0.f, sum1 = 0.f;
        #pragma unroll
        for (int j = 0; j < 8; j++) {
            sacc[j][0] = ex2f((sacc[j][0] - mn0) * SSC);
            sacc[j][1] = ex2f((sacc[j][1] - mn0) * SSC);
            sacc[j][2] = ex2f((sacc[j][2] - mn1) * SSC);
            sacc[j][3] = ex2f((sacc[j][3] - mn1) * SSC);
            sum0 += sacc[j][0] + sacc[j][1];
            sum1 += sacc[j][2] + sacc[j][3];
        }
        #pragma unroll
        for (int off = 1; off <= 2; off <<= 1) {
            sum0 += __shfl_xor_sync(0xffffffffu, sum0, off);
            sum1 += __shfl_xor_sync(0xffffffffu, sum1, off);
        }
        l0 = l0 * a0 + sum0;
        l1 = l1 * a1 + sum1;
        #pragma unroll
        for (int j = 0; j < 8; j++) {
            o[j][0] *= a0; o[j][1] *= a0;
            o[j][2] *= a1; o[j][3] *= a1;
        }

        // ---- O += P V ----
        #pragma unroll
        for (int ks = 0; ks < 4; ks++) {
            uint32_t aph[4], apl[4];
            pack_hl(sacc[2 * ks][0],     sacc[2 * ks][1],     aph[0], apl[0]);
            pack_hl(sacc[2 * ks][2],     sacc[2 * ks][3],     aph[1], apl[1]);
            pack_hl(sacc[2 * ks + 1][0], sacc[2 * ks + 1][1], aph[2], apl[2]);
            pack_hl(sacc[2 * ks + 1][2], sacc[2 * ks + 1][3], aph[3], apl[3]);
            const int vrow = ks * 16 + ((lane >> 3) & 1) * 8 + (lane & 7);
            #pragma unroll
            for (int np = 0; np < 4; np++) {
                uint32_t vh[4], vl[4];
                uint32_t vo = SW128((uint32_t)(vrow * 128 + np * 32
                                               + (lane >> 4) * 16));
                ldsm4t(vh, s0 + 16384 + vo);
                ldsm4t(vl, s0 + 24576 + vo);
                mma16816(o[np * 2],     aph, vh[0], vh[1]);
                mma16816(o[np * 2],     aph, vl[0], vl[1]);
                mma16816(o[np * 2],     apl, vh[0], vh[1]);
                mma16816(o[np * 2 + 1], aph, vh[2], vh[3]);
                mma16816(o[np * 2 + 1], aph, vl[2], vl[3]);
                mma16816(o[np * 2 + 1], apl, vh[2], vh[3]);
            }
        }
        __syncthreads();
    }

    // ---- epilogue ----
    const float inv0 = 1.f / l0, inv1 = 1.f / l1;
    const int s0r = m0 + wm + (lane >> 2);
    const size_t r0 = (size_t)b * SEQ + s0r;
    const size_t r1 = r0 + 8;
    #pragma unroll
    for (int f = 0; f < 8; f++) {
        const int col = hd * DK + f * 8 + 2 * (lane & 3);
        uint32_t ph, pl;
        pack_hl(o[f][0] * inv0, o[f][1] * inv0, ph, pl);
        *(uint32_t*)(Ohi + r0 * EMBED + col) = ph;
        *(uint32_t*)(Olo + r0 * EMBED + col) = pl;
        pack_hl(o[f][2] * inv1, o[f][3] * inv1, ph, pl);
        *(uint32_t*)(Ohi + r1 * EMBED + col) = ph;
        *(uint32_t*)(Olo + r1 * EMBED + col) = pl;
    }
}

// ---------------------------------------------------------------------------
// Launch
// ---------------------------------------------------------------------------
extern "C" void kernel_launch(void* const* d_in, const int* in_sizes, int n_in,
                              void* d_out, int out_size)
{
    const float* x   = (const float*)d_in[0];
    const float* Wq  = (const float*)d_in[1];
    const float* bq  = (const float*)d_in[2];
    const float* Wk  = (const float*)d_in[3];
    const float* bk  = (const float*)d_in[4];
    const float* Wv  = (const float*)d_in[5];
    const float* bv  = (const float*)d_in[6];
    const float* Wo  = (const float*)d_in[7];
    const float* bo  = (const float*)d_in[8];
    const float* W1  = (const float*)d_in[9];
    const float* b1  = (const float*)d_in[10];
    const float* W2  = (const float*)d_in[11];
    const float* b2  = (const float*)d_in[12];
    const float* g1  = (const float*)d_in[13];
    const float* be1 = (const float*)d_in[14];
    const float* g2  = (const float*)d_in[15];
    const float* be2 = (const float*)d_in[16];
    float* out = (float*)d_out;

    __nv_bfloat16 *h_hi, *h_lo, *qkv_hi, *qkv_lo, *ao_hi, *ao_lo;
    __nv_bfloat16 *h2_hi, *h2_lo, *f_hi, *f_lo;
    __nv_bfloat16 *wqkv_hi, *wqkv_lo, *wo_hi, *wo_lo, *w1_hi, *w1_lo, *w2_hi, *w2_lo;
    float *x1, *bqkv;
    cudaGetSymbolAddress((void**)&h_hi,    g_h_hi);
    cudaGetSymbolAddress((void**)&h_lo,    g_h_lo);
    cudaGetSymbolAddress((void**)&qkv_hi,  g_qkv_hi);
    cudaGetSymbolAddress((void**)&qkv_lo,  g_qkv_lo);
    cudaGetSymbolAddress((void**)&ao_hi,   g_ao_hi);
    cudaGetSymbolAddress((void**)&ao_lo,   g_ao_lo);
    cudaGetSymbolAddress((void**)&x1,      g_x1);
    cudaGetSymbolAddress((void**)&h2_hi,   g_h2_hi);
    cudaGetSymbolAddress((void**)&h2_lo,   g_h2_lo);
    cudaGetSymbolAddress((void**)&f_hi,    g_f_hi);
    cudaGetSymbolAddress((void**)&f_lo,    g_f_lo);
    cudaGetSymbolAddress((void**)&wqkv_hi, g_wqkv_hi);
    cudaGetSymbolAddress((void**)&wqkv_lo, g_wqkv_lo);
    cudaGetSymbolAddress((void**)&wo_hi,   g_wo_hi);
    cudaGetSymbolAddress((void**)&wo_lo,   g_wo_lo);
    cudaGetSymbolAddress((void**)&w1_hi,   g_w1_hi);
    cudaGetSymbolAddress((void**)&w1_lo,   g_w1_lo);
    cudaGetSymbolAddress((void**)&w2_hi,   g_w2_hi);
    cudaGetSymbolAddress((void**)&w2_lo,   g_w2_lo);
    cudaGetSymbolAddress((void**)&bqkv,    g_bqkv);

    cudaFuncSetAttribute(gemm_mma<2>, cudaFuncAttributeMaxDynamicSharedMemorySize, SMEM_G);
    cudaFuncSetAttribute(gemm_mma<5>, cudaFuncAttributeMaxDynamicSharedMemorySize, SMEM_G);
    cudaFuncSetAttribute(gemm_mma<6>, cudaFuncAttributeMaxDynamicSharedMemorySize, SMEM_G);
    cudaFuncSetAttribute(attn_mma, cudaFuncAttributeMaxDynamicSharedMemorySize, SMEM_A);

    // bias concat (device-to-device, graph-capturable)
    cudaMemcpyAsync(bqkv,             bq, EMBED * sizeof(float), cudaMemcpyDeviceToDevice, 0);
    cudaMemcpyAsync(bqkv + EMBED,     bk, EMBED * sizeof(float), cudaMemcpyDeviceToDevice, 0);
    cudaMemcpyAsync(bqkv + 2 * EMBED, bv, EMBED * sizeof(float), cudaMemcpyDeviceToDevice, 0);

    // all weight splits in one kernel: 3M float4 elements
    cvt_all<<<(4 * NE4 + 2 * NF4) / 256, 256>>>(
        Wq, Wk, Wv, Wo, W1, W2,
        wqkv_hi, wqkv_lo, wo_hi, wo_lo, w1_hi, w1_lo, w2_hi, w2_lo);

    // LN1 -> (hi, lo)
    ln_kernel<<<MROWS, 256>>>(x, g1, be1, h_hi, h_lo);

    // Fused QKV projection -> head-layout (hi, lo)
    {
        dim3 grid(3 * EMBED / CTN, MROWS / CTM);
        gemm_mma<6><<<grid, 256, SMEM_G>>>(h_hi, h_lo, wqkv_hi, wqkv_lo, bqkv,
                                           nullptr, nullptr, qkv_hi, qkv_lo,
                                           MROWS, 3 * EMBED, EMBED);
    }

    // Attention -> ao (hi, lo)
    {
        dim3 grid(SEQ / 128, HEADS, BATCH);
        attn_mma<<<grid, 256, SMEM_A>>>(qkv_hi, qkv_lo,
                                        qkv_hi + HSZ, qkv_lo + HSZ,
                                        qkv_hi + 2 * HSZ, qkv_lo + 2 * HSZ,
                                        ao_hi, ao_lo);
    }

    // O projection + residual: x1 = x + ao @ Wo^T + bo
    {
        dim3 grid(EMBED / CTN, MROWS / CTM);
        gemm_mma<2><<<grid, 256, SMEM_G>>>(ao_hi, ao_lo, wo_hi, wo_lo, bo, x,
                                           x1, nullptr, nullptr, MROWS, EMBED, EMBED);
    }

    // LN2 -> (hi, lo)
    ln_kernel<<<MROWS, 256>>>(x1, g2, be2, h2_hi, h2_lo);

    // FFN1 + relu -> f (hi, lo)
    {
        dim3 grid(FFN / CTN, MROWS / CTM);
        gemm_mma<5><<<grid, 256, SMEM_G>>>(h2_hi, h2_lo, w1_hi, w1_lo, b1, nullptr,
                                           nullptr, f_hi, f_lo, MROWS, FFN, EMBED);
    }

    // FFN2 + residual -> out
    {
        dim3 grid(EMBED / CTN, MROWS / CTM);
        gemm_mma<2><<<grid, 256, SMEM_G>>>(f_hi, f_lo, w2_hi, w2_lo, b2, x1,
                                           out, nullptr, nullptr, MROWS, EMBED, FFN);
    }
}

// round 6
// speedup vs baseline: 1.0108x; 1.0108x over previous
#include <cuda_runtime.h>
#include <cuda_bf16.h>
#include <math.h>
#include <stdint.h>

// ---------------------------------------------------------------------------
// Problem constants
// ---------------------------------------------------------------------------
#define BATCH   2
#define SEQ     2048
#define EMBED   1024
#define HEADS   16
#define DK      64
#define FFN     4096
#define MROWS   (BATCH * SEQ)          // 4096
#define LN_EPS  1e-5f
#define SSC     0.1803368801111204f    // 0.125 * log2(e)
#define HSZ     (MROWS * EMBED)        // 4M elements

// GEMM tiling: CTA 128x128, K-chunk 32, warp tile 32x64 (8 warps: 4m x 2n)
#define CTM 128
#define CTN 128
#define KTC 32
#define STG 32768                      // Ah 8K + Al 8K + Bh 8K + Bl 8K
#define SMEM_G (2 * STG)               // 64 KB double buffered -> 2 CTA/SM

// Attention smem: 2 stages x (Kh+Kl+Vh+Vl = 32K) = 64 KB; Q reuses stage 0
#define SMEM_A (2 * 32768)

#define SW128(o) ((o) ^ (((o) >> 3) & 0x70))
#define SW64(o)  ((o) ^ (((o) >> 3) & 0x30))

// ---------------------------------------------------------------------------
// Scratch buffers (allocation-free: __device__ globals)
// ---------------------------------------------------------------------------
__device__ __nv_bfloat16 g_h_hi  [HSZ];
__device__ __nv_bfloat16 g_h_lo  [HSZ];
__device__ __nv_bfloat16 g_qkv_hi[3 * HSZ];   // q | k | v, each [B,H,S,DK]
__device__ __nv_bfloat16 g_qkv_lo[3 * HSZ];
__device__ __nv_bfloat16 g_ao_hi [HSZ];
__device__ __nv_bfloat16 g_ao_lo [HSZ];
__device__ float         g_x1    [HSZ];
__device__ __nv_bfloat16 g_h2_hi [HSZ];
__device__ __nv_bfloat16 g_h2_lo [HSZ];
__device__ __nv_bfloat16 g_f_hi  [MROWS * FFN];
__device__ __nv_bfloat16 g_f_lo  [MROWS * FFN];

__device__ __nv_bfloat16 g_wqkv_hi[3 * EMBED * EMBED];  // Wq | Wk | Wv
__device__ __nv_bfloat16 g_wqkv_lo[3 * EMBED * EMBED];
__device__ __nv_bfloat16 g_wo_hi[EMBED * EMBED];
__device__ __nv_bfloat16 g_wo_lo[EMBED * EMBED];
__device__ __nv_bfloat16 g_w1_hi[FFN * EMBED];
__device__ __nv_bfloat16 g_w1_lo[FFN * EMBED];
__device__ __nv_bfloat16 g_w2_hi[EMBED * FFN];
__device__ __nv_bfloat16 g_w2_lo[EMBED * FFN];
__device__ float         g_bqkv[3 * EMBED];

// ---------------------------------------------------------------------------
// helpers
// ---------------------------------------------------------------------------
static __device__ __forceinline__ uint32_t s2u(const void* p) {
    uint32_t a;
    asm("{ .reg .u64 t; cvta.to.shared.u64 t, %1; cvt.u32.u64 %0, t; }"
        : "=r"(a) : "l"(p));
    return a;
}
static __device__ __forceinline__ void cpa16(uint32_t s, const void* g) {
    asm volatile("cp.async.cg.shared.global [%0], [%1], 16;"
                 :: "r"(s), "l"(g) : "memory");
}
static __device__ __forceinline__ void ldsm4(uint32_t* f, uint32_t a) {
    asm volatile("ldmatrix.sync.aligned.m8n8.x4.shared.b16 {%0,%1,%2,%3}, [%4];"
                 : "=r"(f[0]), "=r"(f[1]), "=r"(f[2]), "=r"(f[3]) : "r"(a));
}
static __device__ __forceinline__ void ldsm4t(uint32_t* f, uint32_t a) {
    asm volatile("ldmatrix.sync.aligned.m8n8.x4.trans.shared.b16 {%0,%1,%2,%3}, [%4];"
                 : "=r"(f[0]), "=r"(f[1]), "=r"(f[2]), "=r"(f[3]) : "r"(a));
}
static __device__ __forceinline__ void mma16816(float* c, const uint32_t* a,
                                                uint32_t b0, uint32_t b1) {
    asm volatile(
        "mma.sync.aligned.m16n8k16.row.col.f32.bf16.bf16.f32 "
        "{%0,%1,%2,%3}, {%4,%5,%6,%7}, {%8,%9}, {%0,%1,%2,%3};"
        : "+f"(c[0]), "+f"(c[1]), "+f"(c[2]), "+f"(c[3])
        : "r"(a[0]), "r"(a[1]), "r"(a[2]), "r"(a[3]), "r"(b0), "r"(b1));
}
static __device__ __forceinline__ float ex2f(float x) {
    float y;
    asm("ex2.approx.f32 %0, %1;" : "=f"(y) : "f"(x));
    return y;
}
static __device__ __forceinline__ void split2(float v, __nv_bfloat16& h, __nv_bfloat16& l) {
    h = __float2bfloat16(v);
    l = __float2bfloat16(v - __bfloat162float(h));
}
static __device__ __forceinline__ void pack_hl(float x, float y,
                                               uint32_t& hi, uint32_t& lo) {
    __nv_bfloat16 hx, lx, hy, ly;
    split2(x, hx, lx);
    split2(y, hy, ly);
    __nv_bfloat162 H; H.x = hx; H.y = hy;
    __nv_bfloat162 L; L.x = lx; L.y = ly;
    hi = *(uint32_t*)&H;
    lo = *(uint32_t*)&L;
}

// ---------------------------------------------------------------------------
// One-shot weight split: all 6 matrices in one launch.
// ---------------------------------------------------------------------------
#define NE4 (EMBED * EMBED / 4)       // 256K
#define NF4 (FFN * EMBED / 4)         // 1M
__global__ __launch_bounds__(256) void cvt_all(
    const float* __restrict__ wq, const float* __restrict__ wk,
    const float* __restrict__ wv, const float* __restrict__ wo,
    const float* __restrict__ w1, const float* __restrict__ w2,
    __nv_bfloat16* __restrict__ qkv_hi, __nv_bfloat16* __restrict__ qkv_lo,
    __nv_bfloat16* __restrict__ wo_hi,  __nv_bfloat16* __restrict__ wo_lo,
    __nv_bfloat16* __restrict__ w1_hi,  __nv_bfloat16* __restrict__ w1_lo,
    __nv_bfloat16* __restrict__ w2_hi,  __nv_bfloat16* __restrict__ w2_lo)
{
    int i = blockIdx.x * 256 + threadIdx.x;    // float4 index, < 3M
    const float* src;
    __nv_bfloat16 *dh, *dl;
    int j = i;
    if (i < 3 * NE4) {                          // fused qkv weights
        src = (i < NE4) ? wq : (i < 2 * NE4) ? wk : wv;
        j = (i < NE4) ? i : (i < 2 * NE4) ? i - NE4 : i - 2 * NE4;
        dh = qkv_hi + (size_t)(i - j) * 4; dl = qkv_lo + (size_t)(i - j) * 4;
    } else if (i < 4 * NE4) {
        src = wo; j = i - 3 * NE4; dh = wo_hi; dl = wo_lo;
    } else if (i < 4 * NE4 + NF4) {
        src = w1; j = i - 4 * NE4; dh = w1_hi; dl = w1_lo;
    } else {
        src = w2; j = i - 4 * NE4 - NF4; dh = w2_hi; dl = w2_lo;
    }
    float4 v = ((const float4*)src)[j];
    uint32_t h0, l0, h1, l1;
    pack_hl(v.x, v.y, h0, l0);
    pack_hl(v.z, v.w, h1, l1);
    uint2 H; H.x = h0; H.y = h1;
    uint2 L; L.x = l0; L.y = l1;
    ((uint2*)dh)[j] = H;
    ((uint2*)dl)[j] = L;
}

// ---------------------------------------------------------------------------
// LayerNorm: one block per row, writes (hi, lo) bf16
// ---------------------------------------------------------------------------
__global__ __launch_bounds__(256) void ln_kernel(
    const float* __restrict__ x, const float* __restrict__ g,
    const float* __restrict__ be, __nv_bfloat16* __restrict__ ohi,
    __nv_bfloat16* __restrict__ olo)
{
    const int N = EMBED;
    const size_t row = blockIdx.x;
    const float* xr = x + row * N;
    float s = 0.f, s2 = 0.f;
    #pragma unroll
    for (int i = threadIdx.x; i < N; i += 256) {
        float v = xr[i];
        s += v; s2 += v * v;
    }
    #pragma unroll
    for (int o = 16; o; o >>= 1) {
        s  += __shfl_xor_sync(0xffffffffu, s,  o);
        s2 += __shfl_xor_sync(0xffffffffu, s2, o);
    }
    __shared__ float red[16];
    __shared__ float mu_sh, rs_sh;
    int w = threadIdx.x >> 5, l = threadIdx.x & 31;
    if (l == 0) { red[w] = s; red[8 + w] = s2; }
    __syncthreads();
    if (threadIdx.x == 0) {
        float ts = 0.f, ts2 = 0.f;
        #pragma unroll
        for (int i = 0; i < 8; i++) { ts += red[i]; ts2 += red[8 + i]; }
        float mu  = ts / N;
        float var = ts2 / N - mu * mu;
        mu_sh = mu;
        rs_sh = rsqrtf(var + LN_EPS);
    }
    __syncthreads();
    float mu = mu_sh, rs = rs_sh;
    #pragma unroll
    for (int i = threadIdx.x; i < N; i += 256) {
        float y = (xr[i] - mu) * rs * g[i] + be[i];
        __nv_bfloat16 h, lo;
        split2(y, h, lo);
        ohi[row * N + i] = h;
        olo[row * N + i] = lo;
    }
}

// ---------------------------------------------------------------------------
// mma.sync split-bf16 GEMM: C[M,N] = A[M,K] @ W[N,K]^T (+bias,+relu,+res)
// CTA 128x128, warp tile 32x64, KTC 32 (SW64 rows), double-buffered cp.async,
// 64 KB smem -> 2 CTAs/SM.
// EPI: 2 = bias+res -> fp32; 5 = bias+relu -> (hi,lo);
//      6 = bias -> (hi,lo) fused-QKV head layout (N=3072)
// ---------------------------------------------------------------------------
template <int EPI>
__global__ __launch_bounds__(256, 2) void gemm_mma(
    const __nv_bfloat16* __restrict__ Ah, const __nv_bfloat16* __restrict__ Al,
    const __nv_bfloat16* __restrict__ Bh, const __nv_bfloat16* __restrict__ Bl,
    const float* __restrict__ bias, const float* __restrict__ res,
    float* __restrict__ Cf, __nv_bfloat16* __restrict__ Chi,
    __nv_bfloat16* __restrict__ Clo, int M, int N, int K)
{
    extern __shared__ char smem[];
    const uint32_t sb = s2u(smem);
    const int tid = threadIdx.x;
    const int lane = tid & 31, w = tid >> 5;
    const int bm = blockIdx.y * CTM, bn = blockIdx.x * CTN;
    const int wm = (w & 3) * 32, wn = (w >> 2) * 64;

    float acc[2][8][4];
    #pragma unroll
    for (int mt = 0; mt < 2; mt++)
        #pragma unroll
        for (int nt = 0; nt < 8; nt++)
            #pragma unroll
            for (int i = 0; i < 4; i++) acc[mt][nt][i] = 0.f;

    const int NC = K / KTC;

    auto load_chunk = [&](int c, int st) {
        const uint32_t s0 = sb + st * STG;
        const size_t k0 = (size_t)c * KTC;
        #pragma unroll
        for (int i = 0; i < 2; i++) {                 // A: 128 rows x 64B
            int idx = i * 256 + tid;
            int row = idx >> 2, c4 = idx & 3;
            uint32_t so = SW64((uint32_t)(row * 64 + c4 * 16));
            const size_t g = (size_t)(bm + row) * K + k0 + c4 * 8;
            cpa16(s0 + so,        Ah + g);
            cpa16(s0 + 8192 + so, Al + g);
        }
        #pragma unroll
        for (int i = 0; i < 2; i++) {                 // B: 128 rows x 64B
            int idx = i * 256 + tid;
            int row = idx >> 2, c4 = idx & 3;
            uint32_t so = SW64((uint32_t)(row * 64 + c4 * 16));
            const size_t g = (size_t)(bn + row) * K + k0 + c4 * 8;
            cpa16(s0 + 16384 + so, Bh + g);
            cpa16(s0 + 24576 + so, Bl + g);
        }
    };

    load_chunk(0, 0);
    asm volatile("cp.async.commit_group;" ::: "memory");

    for (int c = 0; c < NC; c++) {
        const int st = c & 1;
        if (c + 1 < NC) {
            load_chunk(c + 1, st ^ 1);
            asm volatile("cp.async.commit_group;" ::: "memory");
            asm volatile("cp.async.wait_group 1;" ::: "memory");
        } else {
            asm volatile("cp.async.wait_group 0;" ::: "memory");
        }
        __syncthreads();

        const uint32_t s0 = sb + st * STG;
        #pragma unroll
        for (int ks = 0; ks < 2; ks++) {
            uint32_t ah[2][4], alr[2][4], bh[4][4], blr[4][4];
            const int arow = wm + (lane & 15);
            const int akb  = ks * 32 + (lane >> 4) * 16;
            #pragma unroll
            for (int mt = 0; mt < 2; mt++) {
                uint32_t ao = SW64((uint32_t)((arow + mt * 16) * 64 + akb));
                ldsm4(ah[mt],  s0 + ao);
                ldsm4(alr[mt], s0 + 8192 + ao);
            }
            const int brow = wn + ((lane >> 4) << 3) + (lane & 7);
            const int bkb  = ks * 32 + ((lane >> 3) & 1) * 16;
            #pragma unroll
            for (int np = 0; np < 4; np++) {
                uint32_t bo = SW64((uint32_t)((brow + np * 16) * 64 + bkb));
                ldsm4(bh[np],  s0 + 16384 + bo);
                ldsm4(blr[np], s0 + 24576 + bo);
            }
            #pragma unroll
            for (int mt = 0; mt < 2; mt++) {
                #pragma unroll
                for (int nt = 0; nt < 8; nt++) {
                    const int np = nt >> 1, ro = (nt & 1) * 2;
                    mma16816(acc[mt][nt], ah[mt],  bh[np][ro],  bh[np][ro + 1]);
                    mma16816(acc[mt][nt], ah[mt],  blr[np][ro], blr[np][ro + 1]);
                    mma16816(acc[mt][nt], alr[mt], bh[np][ro],  bh[np][ro + 1]);
                }
            }
        }
        __syncthreads();
    }

    // ---- epilogue ----
    #pragma unroll
    for (int mt = 0; mt < 2; mt++) {
        #pragma unroll
        for (int nt = 0; nt < 8; nt++) {
            const int n = bn + wn + nt * 8 + (lane & 3) * 2;
            const float bs0 = bias[n], bs1 = bias[n + 1];
            #pragma unroll
            for (int hh = 0; hh < 2; hh++) {
                const size_t m = (size_t)bm + wm + mt * 16 + (lane >> 2) + hh * 8;
                float v0 = acc[mt][nt][hh * 2]     + bs0;
                float v1 = acc[mt][nt][hh * 2 + 1] + bs1;
                if (EPI == 5) { v0 = fmaxf(v0, 0.f); v1 = fmaxf(v1, 0.f); }
                if (EPI == 2) {
                    float2 rr = *(const float2*)(res + m * N + n);
                    v0 += rr.x; v1 += rr.y;
                }
                if (EPI == 5) {
                    uint32_t ph, pl;
                    pack_hl(v0, v1, ph, pl);
                    *(uint32_t*)(Chi + m * N + n) = ph;
                    *(uint32_t*)(Clo + m * N + n) = pl;
                } else if (EPI == 6) {
                    const int which = n >> 10;
                    const int h_ = (n >> 6) & (HEADS - 1), d_ = n & 63;
                    const int b_ = (int)(m >> 11), s_ = (int)(m & 2047);
                    const size_t di = (size_t)which * HSZ
                        + (((size_t)b_ * HEADS + h_) * SEQ + s_) * DK + d_;
                    uint32_t ph, pl;
                    pack_hl(v0, v1, ph, pl);
                    *(uint32_t*)(Chi + di) = ph;
                    *(uint32_t*)(Clo + di) = pl;
                } else {
                    float2 o; o.x = v0; o.y = v1;
                    *(float2*)(Cf + m * N + n) = o;
                }
            }
        }
    }
}

// ---------------------------------------------------------------------------
// Flash attention on tensor cores (split bf16, mma.sync).
// grid = (SEQ/128, HEADS, BATCH), 256 threads (8 warps, each owns 16 q rows).
// Smem: Q staged through stage-0 region (reused), then 2x32KB KV pipeline
// with 2-deep prefetch -> 64 KB total, 2 CTAs/SM.
// ---------------------------------------------------------------------------
__global__ __launch_bounds__(256, 2) void attn_mma(
    const __nv_bfloat16* __restrict__ Qh, const __nv_bfloat16* __restrict__ Ql,
    const __nv_bfloat16* __restrict__ Kh, const __nv_bfloat16* __restrict__ Kl,
    const __nv_bfloat16* __restrict__ Vh, const __nv_bfloat16* __restrict__ Vl,
    __nv_bfloat16* __restrict__ Ohi, __nv_bfloat16* __restrict__ Olo)
{
    extern __shared__ char smem[];
    const uint32_t sb  = s2u(smem);
    const int tid = threadIdx.x, lane = tid & 31, w = tid >> 5;
    const int qt = blockIdx.x, hd = blockIdx.y, b = blockIdx.z;
    const size_t hb = ((size_t)b * HEADS + hd) * SEQ * DK;
    const int m0 = qt * 128;
    const int wm = w * 16;

    // ---- Q phase: stage through smem (stage-0 region), park in registers ----
    {
        const uint32_t sQh = sb, sQl = sb + 16384;
        #pragma unroll
        for (int i = 0; i < 4; i++) {
            int idx = i * 256 + tid;
            int row = idx >> 3, c16 = idx & 7;
            uint32_t so = SW128((uint32_t)(row * 128 + c16 * 16));
            const size_t g = hb + (size_t)(m0 + row) * DK + c16 * 8;
            cpa16(sQh + so, Qh + g);
            cpa16(sQl + so, Ql + g);
        }
        asm volatile("cp.async.commit_group;" ::: "memory");
        asm volatile("cp.async.wait_group 0;" ::: "memory");
        __syncthreads();
    }
    uint32_t qhf[4][4], qlf[4][4];
    #pragma unroll
    for (int ks = 0; ks < 4; ks++) {
        uint32_t ao = SW128((uint32_t)((wm + (lane & 15)) * 128
                                       + ks * 32 + (lane >> 4) * 16));
        ldsm4(qhf[ks], sb + ao);
        ldsm4(qlf[ks], sb + 16384 + ao);
    }
    __syncthreads();   // all warps done reading Q before stage 0 is overwritten

    auto load_kv = [&](int c, int st) {
        const uint32_t s0 = sb + st * 32768;
        const int k0 = c * 64;
        #pragma unroll
        for (int i = 0; i < 2; i++) {
            int idx = i * 256 + tid;
            int row = idx >> 3, c16 = idx & 7;
            uint32_t so = SW128((uint32_t)(row * 128 + c16 * 16));
            const size_t g = hb + (size_t)(k0 + row) * DK + c16 * 8;
            cpa16(s0 + so,         Kh + g);
            cpa16(s0 + 8192 + so,  Kl + g);
            cpa16(s0 + 16384 + so, Vh + g);
            cpa16(s0 + 24576 + so, Vl + g);
        }
        asm volatile("cp.async.commit_group;" ::: "memory");
    };
    load_kv(0, 0);
    load_kv(1, 1);

    float o[8][4];
    #pragma unroll
    for (int j = 0; j < 8; j++)
        #pragma unroll
        for (int i = 0; i < 4; i++) o[j][i] = 0.f;
    float mr0 = -1e30f, mr1 = -1e30f, l0 = 0.f, l1 = 0.f;

    const int NC = SEQ / 64;
    for (int c = 0; c < NC; c++) {
        const int st = c & 1;
        if (c + 2 < NC) {
            asm volatile("cp.async.wait_group 1;" ::: "memory");
        } else {
            asm volatile("cp.async.wait_group 0;" ::: "memory");
        }
        __syncthreads();
        const uint32_t s0 = sb + st * 32768;

        // ---- S = Q K^T ----
        float sacc[8][4];
        #pragma unroll
        for (int j = 0; j < 8; j++)
            #pragma unroll
            for (int i = 0; i < 4; i++) sacc[j][i] = 0.f;

        #pragma unroll
        for (int ks = 0; ks < 4; ks++) {
            const int brow = ((lane >> 4) << 3) + (lane & 7);
            const int bkb  = ks * 32 + ((lane >> 3) & 1) * 16;
            #pragma unroll
            for (int np = 0; np < 4; np++) {
                uint32_t kh[4], kl[4];
                uint32_t bo = SW128((uint32_t)((brow + np * 16) * 128 + bkb));
                ldsm4(kh, s0 + bo);
                ldsm4(kl, s0 + 8192 + bo);
                mma16816(sacc[np * 2],     qhf[ks], kh[0], kh[1]);
                mma16816(sacc[np * 2],     qhf[ks], kl[0], kl[1]);
                mma16816(sacc[np * 2],     qlf[ks], kh[0], kh[1]);
                mma16816(sacc[np * 2 + 1], qhf[ks], kh[2], kh[3]);
                mma16816(sacc[np * 2 + 1], qhf[ks], kl[2], kl[3]);
                mma16816(sacc[np * 2 + 1], qlf[ks], kh[2], kh[3]);
            }
        }

        // ---- online softmax ----
        float cm0 = -1e30f, cm1 = -1e30f;
        #pragma unroll
        for (int j = 0; j < 8; j++) {
            cm0 = fmaxf(cm0, fmaxf(sacc[j][0], sacc[j][1]));
            cm1 = fmaxf(cm1, fmaxf(sacc[j][2], sacc[j][3]));
        }
        #pragma unroll
        for (int off = 1; off <= 2; off <<= 1) {
            cm0 = fmaxf(cm0, __shfl_xor_sync(0xffffffffu, cm0, off));
            cm1 = fmaxf(cm1, __shfl_xor_sync(0xffffffffu, cm1, off));
        }
        const float mn0 = fmaxf(mr0, cm0), mn1 = fmaxf(mr1, cm1);
        const float a0 = ex2f((mr0 - mn0) * SSC);
        const float a1 = ex2f((mr1 - mn1) * SSC);
        mr0 = mn0; mr1 = mn1;
        float sum0 = 0.f, sum1 = 0.f;
        #pragma unroll
        for (int j = 0; j < 8; j++) {
            sacc[j][0] = ex2f((sacc[j][0] - mn0) * SSC);
            sacc[j][1] = ex2f((sacc[j][1] - mn0) * SSC);
            sacc[j][2] = ex2f((sacc[j][2] - mn1) * SSC);
            sacc[j][3] = ex2f((sacc[j][3] - mn1) * SSC);
            sum0 += sacc[j][0] + sacc[j][1];
            sum1 += sacc[j][2] + sacc[j][3];
        }
        #pragma unroll
        for (int off = 1; off <= 2; off <<= 1) {
            sum0 += __shfl_xor_sync(0xffffffffu, sum0, off);
            sum1 += __shfl_xor_sync(0xffffffffu, sum1, off);
        }
        l0 = l0 * a0 + sum0;
        l1 = l1 * a1 + sum1;
        #pragma unroll
        for (int j = 0; j < 8; j++) {
            o[j][0] *= a0; o[j][1] *= a0;
            o[j][2] *= a1; o[j][3] *= a1;
        }

        // ---- O += P V ----
        #pragma unroll
        for (int ks = 0; ks < 4; ks++) {
            uint32_t aph[4], apl[4];
            pack_hl(sacc[2 * ks][0],     sacc[2 * ks][1],     aph[0], apl[0]);
            pack_hl(sacc[2 * ks][2],     sacc[2 * ks][3],     aph[1], apl[1]);
            pack_hl(sacc[2 * ks + 1][0], sacc[2 * ks + 1][1], aph[2], apl[2]);
            pack_hl(sacc[2 * ks + 1][2], sacc[2 * ks + 1][3], aph[3], apl[3]);
            const int vrow = ks * 16 + ((lane >> 3) & 1) * 8 + (lane & 7);
            #pragma unroll
            for (int np = 0; np < 4; np++) {
                uint32_t vh[4], vl[4];
                uint32_t vo = SW128((uint32_t)(vrow * 128 + np * 32
                                               + (lane >> 4) * 16));
                ldsm4t(vh, s0 + 16384 + vo);
                ldsm4t(vl, s0 + 24576 + vo);
                mma16816(o[np * 2],     aph, vh[0], vh[1]);
                mma16816(o[np * 2],     aph, vl[0], vl[1]);
                mma16816(o[np * 2],     apl, vh[0], vh[1]);
                mma16816(o[np * 2 + 1], aph, vh[2], vh[3]);
                mma16816(o[np * 2 + 1], aph, vl[2], vl[3]);
                mma16816(o[np * 2 + 1], apl, vh[2], vh[3]);
            }
        }
        __syncthreads();
        if (c + 2 < NC) load_kv(c + 2, st);
    }

    // ---- epilogue ----
    const float inv0 = 1.f / l0, inv1 = 1.f / l1;
    const int s0r = m0 + wm + (lane >> 2);
    const size_t r0 = (size_t)b * SEQ + s0r;
    const size_t r1 = r0 + 8;
    #pragma unroll
    for (int f = 0; f < 8; f++) {
        const int col = hd * DK + f * 8 + 2 * (lane & 3);
        uint32_t ph, pl;
        pack_hl(o[f][0] * inv0, o[f][1] * inv0, ph, pl);
        *(uint32_t*)(Ohi + r0 * EMBED + col) = ph;
        *(uint32_t*)(Olo + r0 * EMBED + col) = pl;
        pack_hl(o[f][2] * inv1, o[f][3] * inv1, ph, pl);
        *(uint32_t*)(Ohi + r1 * EMBED + col) = ph;
        *(uint32_t*)(Olo + r1 * EMBED + col) = pl;
    }
}

// ---------------------------------------------------------------------------
// Launch
// ---------------------------------------------------------------------------
extern "C" void kernel_launch(void* const* d_in, const int* in_sizes, int n_in,
                              void* d_out, int out_size)
{
    const float* x   = (const float*)d_in[0];
    const float* Wq  = (const float*)d_in[1];
    const float* bq  = (const float*)d_in[2];
    const float* Wk  = (const float*)d_in[3];
    const float* bk  = (const float*)d_in[4];
    const float* Wv  = (const float*)d_in[5];
    const float* bv  = (const float*)d_in[6];
    const float* Wo  = (const float*)d_in[7];
    const float* bo  = (const float*)d_in[8];
    const float* W1  = (const float*)d_in[9];
    const float* b1  = (const float*)d_in[10];
    const float* W2  = (const float*)d_in[11];
    const float* b2  = (const float*)d_in[12];
    const float* g1  = (const float*)d_in[13];
    const float* be1 = (const float*)d_in[14];
    const float* g2  = (const float*)d_in[15];
    const float* be2 = (const float*)d_in[16];
    float* out = (float*)d_out;

    __nv_bfloat16 *h_hi, *h_lo, *qkv_hi, *qkv_lo, *ao_hi, *ao_lo;
    __nv_bfloat16 *h2_hi, *h2_lo, *f_hi, *f_lo;
    __nv_bfloat16 *wqkv_hi, *wqkv_lo, *wo_hi, *wo_lo, *w1_hi, *w1_lo, *w2_hi, *w2_lo;
    float *x1, *bqkv;
    cudaGetSymbolAddress((void**)&h_hi,    g_h_hi);
    cudaGetSymbolAddress((void**)&h_lo,    g_h_lo);
    cudaGetSymbolAddress((void**)&qkv_hi,  g_qkv_hi);
    cudaGetSymbolAddress((void**)&qkv_lo,  g_qkv_lo);
    cudaGetSymbolAddress((void**)&ao_hi,   g_ao_hi);
    cudaGetSymbolAddress((void**)&ao_lo,   g_ao_lo);
    cudaGetSymbolAddress((void**)&x1,      g_x1);
    cudaGetSymbolAddress((void**)&h2_hi,   g_h2_hi);
    cudaGetSymbolAddress((void**)&h2_lo,   g_h2_lo);
    cudaGetSymbolAddress((void**)&f_hi,    g_f_hi);
    cudaGetSymbolAddress((void**)&f_lo,    g_f_lo);
    cudaGetSymbolAddress((void**)&wqkv_hi, g_wqkv_hi);
    cudaGetSymbolAddress((void**)&wqkv_lo, g_wqkv_lo);
    cudaGetSymbolAddress((void**)&wo_hi,   g_wo_hi);
    cudaGetSymbolAddress((void**)&wo_lo,   g_wo_lo);
    cudaGetSymbolAddress((void**)&w1_hi,   g_w1_hi);
    cudaGetSymbolAddress((void**)&w1_lo,   g_w1_lo);
    cudaGetSymbolAddress((void**)&w2_hi,   g_w2_hi);
    cudaGetSymbolAddress((void**)&w2_lo,   g_w2_lo);
    cudaGetSymbolAddress((void**)&bqkv,    g_bqkv);

    cudaFuncSetAttribute(gemm_mma<2>, cudaFuncAttributeMaxDynamicSharedMemorySize, SMEM_G);
    cudaFuncSetAttribute(gemm_mma<5>, cudaFuncAttributeMaxDynamicSharedMemorySize, SMEM_G);
    cudaFuncSetAttribute(gemm_mma<6>, cudaFuncAttributeMaxDynamicSharedMemorySize, SMEM_G);
    cudaFuncSetAttribute(attn_mma, cudaFuncAttributeMaxDynamicSharedMemorySize, SMEM_A);

    // bias concat (device-to-device, graph-capturable)
    cudaMemcpyAsync(bqkv,             bq, EMBED * sizeof(float), cudaMemcpyDeviceToDevice, 0);
    cudaMemcpyAsync(bqkv + EMBED,     bk, EMBED * sizeof(float), cudaMemcpyDeviceToDevice, 0);
    cudaMemcpyAsync(bqkv + 2 * EMBED, bv, EMBED * sizeof(float), cudaMemcpyDeviceToDevice, 0);

    // all weight splits in one kernel: 3M float4 elements
    cvt_all<<<(4 * NE4 + 2 * NF4) / 256, 256>>>(
        Wq, Wk, Wv, Wo, W1, W2,
        wqkv_hi, wqkv_lo, wo_hi, wo_lo, w1_hi, w1_lo, w2_hi, w2_lo);

    // LN1 -> (hi, lo)
    ln_kernel<<<MROWS, 256>>>(x, g1, be1, h_hi, h_lo);

    // Fused QKV projection -> head-layout (hi, lo)
    {
        dim3 grid(3 * EMBED / CTN, MROWS / CTM);
        gemm_mma<6><<<grid, 256, SMEM_G>>>(h_hi, h_lo, wqkv_hi, wqkv_lo, bqkv,
                                           nullptr, nullptr, qkv_hi, qkv_lo,
                                           MROWS, 3 * EMBED, EMBED);
    }

    // Attention -> ao (hi, lo)
    {
        dim3 grid(SEQ / 128, HEADS, BATCH);
        attn_mma<<<grid, 256, SMEM_A>>>(qkv_hi, qkv_lo,
                                        qkv_hi + HSZ, qkv_lo + HSZ,
                                        qkv_hi + 2 * HSZ, qkv_lo + 2 * HSZ,
                                        ao_hi, ao_lo);
    }

    // O projection + residual: x1 = x + ao @ Wo^T + bo
    {
        dim3 grid(EMBED / CTN, MROWS / CTM);
        gemm_mma<2><<<grid, 256, SMEM_G>>>(ao_hi, ao_lo, wo_hi, wo_lo, bo, x,
                                           x1, nullptr, nullptr, MROWS, EMBED, EMBED);
    }

    // LN2 -> (hi, lo)
    ln_kernel<<<MROWS, 256>>>(x1, g2, be2, h2_hi, h2_lo);

    // FFN1 + relu -> f (hi, lo)
    {
        dim3 grid(FFN / CTN, MROWS / CTM);
        gemm_mma<5><<<grid, 256, SMEM_G>>>(h2_hi, h2_lo, w1_hi, w1_lo, b1, nullptr,
                                           nullptr, f_hi, f_lo, MROWS, FFN, EMBED);
    }

    // FFN2 + residual -> out
    {
        dim3 grid(EMBED / CTN, MROWS / CTM);
        gemm_mma<2><<<grid, 256, SMEM_G>>>(f_hi, f_lo, w2_hi, w2_lo, b2, x1,
                                           out, nullptr, nullptr, MROWS, EMBED, FFN);
    }
}

// round 9
// speedup vs baseline: 1.1132x; 1.1013x over previous
#include <cuda_runtime.h>
#include <cuda_bf16.h>
#include <cuda_fp16.h>
#include <math.h>
#include <stdint.h>

// ---------------------------------------------------------------------------
// Problem constants
// ---------------------------------------------------------------------------
#define BATCH   2
#define SEQ     2048
#define EMBED   1024
#define HEADS   16
#define DK      64
#define FFN     4096
#define MROWS   (BATCH * SEQ)          // 4096
#define LN_EPS  1e-5f
#define SSC     0.1803368801111204f    // 0.125 * log2(e)
#define HSZ     (MROWS * EMBED)        // 4M elements

// GEMM tiling: CTA 128x128, K-chunk 32, warp tile 32x64 (8 warps: 4m x 2n)
#define CTM 128
#define CTN 128
#define KTC 32
#define STG 32768                      // Ah 8K + Al 8K + Bh 8K + Bl 8K
#define SMEM_G (3 * STG)               // 96 KB, 3-stage -> 2 CTA/SM

// Attention: Q 16K (fp16 128 rows x 128B) + 3 stages x (K 8K + Vh 8K + Vl 8K)
#define ASTG 24576
#define SMEM_A (16384 + 3 * ASTG)      // 88 KB -> 2 CTA/SM

#define SW128(o) ((o) ^ (((o) >> 3) & 0x70))
#define SW64(o)  ((o) ^ (((o) >> 3) & 0x30))

// ---------------------------------------------------------------------------
// Scratch buffers (allocation-free: __device__ globals)
// ---------------------------------------------------------------------------
__device__ __nv_bfloat16 g_h_hi [HSZ];
__device__ __nv_bfloat16 g_h_lo [HSZ];
__device__ __half        g_qk   [2 * HSZ];   // q | k, fp16, [B,H,S,DK]
__device__ __nv_bfloat16 g_v_hi [HSZ];       // v bf16 hi/lo, [B,H,S,DK]
__device__ __nv_bfloat16 g_v_lo [HSZ];
__device__ __nv_bfloat16 g_ao_hi[HSZ];
__device__ __nv_bfloat16 g_ao_lo[HSZ];
__device__ float         g_x1   [HSZ];
__device__ __nv_bfloat16 g_h2_hi[HSZ];
__device__ __nv_bfloat16 g_h2_lo[HSZ];
__device__ __nv_bfloat16 g_f_hi [MROWS * FFN];
__device__ __nv_bfloat16 g_f_lo [MROWS * FFN];

__device__ __nv_bfloat16 g_wqkv_hi[3 * EMBED * EMBED];  // Wq | Wk | Wv
__device__ __nv_bfloat16 g_wqkv_lo[3 * EMBED * EMBED];
__device__ __nv_bfloat16 g_wo_hi[EMBED * EMBED];
__device__ __nv_bfloat16 g_wo_lo[EMBED * EMBED];
__device__ __nv_bfloat16 g_w1_hi[FFN * EMBED];
__device__ __nv_bfloat16 g_w1_lo[FFN * EMBED];
__device__ __nv_bfloat16 g_w2_hi[EMBED * FFN];
__device__ __nv_bfloat16 g_w2_lo[EMBED * FFN];
__device__ float         g_bqkv[3 * EMBED];

// ---------------------------------------------------------------------------
// helpers
// ---------------------------------------------------------------------------
static __device__ __forceinline__ uint32_t s2u(const void* p) {
    uint32_t a;
    asm("{ .reg .u64 t; cvta.to.shared.u64 t, %1; cvt.u32.u64 %0, t; }"
        : "=r"(a) : "l"(p));
    return a;
}
static __device__ __forceinline__ void cpa16(uint32_t s, const void* g) {
    asm volatile("cp.async.cg.shared.global [%0], [%1], 16;"
                 :: "r"(s), "l"(g) : "memory");
}
static __device__ __forceinline__ void ldsm4(uint32_t* f, uint32_t a) {
    asm volatile("ldmatrix.sync.aligned.m8n8.x4.shared.b16 {%0,%1,%2,%3}, [%4];"
                 : "=r"(f[0]), "=r"(f[1]), "=r"(f[2]), "=r"(f[3]) : "r"(a));
}
static __device__ __forceinline__ void ldsm4t(uint32_t* f, uint32_t a) {
    asm volatile("ldmatrix.sync.aligned.m8n8.x4.trans.shared.b16 {%0,%1,%2,%3}, [%4];"
                 : "=r"(f[0]), "=r"(f[1]), "=r"(f[2]), "=r"(f[3]) : "r"(a));
}
static __device__ __forceinline__ void mma_bf16(float* c, const uint32_t* a,
                                                uint32_t b0, uint32_t b1) {
    asm volatile(
        "mma.sync.aligned.m16n8k16.row.col.f32.bf16.bf16.f32 "
        "{%0,%1,%2,%3}, {%4,%5,%6,%7}, {%8,%9}, {%0,%1,%2,%3};"
        : "+f"(c[0]), "+f"(c[1]), "+f"(c[2]), "+f"(c[3])
        : "r"(a[0]), "r"(a[1]), "r"(a[2]), "r"(a[3]), "r"(b0), "r"(b1));
}
static __device__ __forceinline__ void mma_f16(float* c, const uint32_t* a,
                                               uint32_t b0, uint32_t b1) {
    asm volatile(
        "mma.sync.aligned.m16n8k16.row.col.f32.f16.f16.f32 "
        "{%0,%1,%2,%3}, {%4,%5,%6,%7}, {%8,%9}, {%0,%1,%2,%3};"
        : "+f"(c[0]), "+f"(c[1]), "+f"(c[2]), "+f"(c[3])
        : "r"(a[0]), "r"(a[1]), "r"(a[2]), "r"(a[3]), "r"(b0), "r"(b1));
}
static __device__ __forceinline__ float ex2f(float x) {
    float y;
    asm("ex2.approx.f32 %0, %1;" : "=f"(y) : "f"(x));
    return y;
}
static __device__ __forceinline__ void split2(float v, __nv_bfloat16& h, __nv_bfloat16& l) {
    h = __float2bfloat16(v);
    l = __float2bfloat16(v - __bfloat162float(h));
}
static __device__ __forceinline__ void pack_hl(float x, float y,
                                               uint32_t& hi, uint32_t& lo) {
    __nv_bfloat16 hx, lx, hy, ly;
    split2(x, hx, lx);
    split2(y, hy, ly);
    __nv_bfloat162 H; H.x = hx; H.y = hy;
    __nv_bfloat162 L; L.x = lx; L.y = ly;
    hi = *(uint32_t*)&H;
    lo = *(uint32_t*)&L;
}
static __device__ __forceinline__ uint32_t pack2h(float x, float y) {
    __half2 h = __floats2half2_rn(x, y);
    return *(uint32_t*)&h;
}

// ---------------------------------------------------------------------------
// One-shot weight split (fp32 -> bf16 hi + bf16 lo), all matrices
// ---------------------------------------------------------------------------
#define NE4 (EMBED * EMBED / 4)       // 256K
#define NF4 (FFN * EMBED / 4)         // 1M
__global__ __launch_bounds__(256) void cvt_all(
    const float* __restrict__ wq, const float* __restrict__ wk,
    const float* __restrict__ wv, const float* __restrict__ wo,
    const float* __restrict__ w1, const float* __restrict__ w2,
    __nv_bfloat16* __restrict__ qkv_hi, __nv_bfloat16* __restrict__ qkv_lo,
    __nv_bfloat16* __restrict__ wo_hi,  __nv_bfloat16* __restrict__ wo_lo,
    __nv_bfloat16* __restrict__ w1_hi,  __nv_bfloat16* __restrict__ w1_lo,
    __nv_bfloat16* __restrict__ w2_hi,  __nv_bfloat16* __restrict__ w2_lo)
{
    int i = blockIdx.x * 256 + threadIdx.x;    // float4 index, < 3M
    const float* src;
    __nv_bfloat16 *dh, *dl;
    int j;
    if (i < 3 * NE4) {
        src = (i < NE4) ? wq : (i < 2 * NE4) ? wk : wv;
        j = (i < NE4) ? i : (i < 2 * NE4) ? i - NE4 : i - 2 * NE4;
        dh = qkv_hi + (size_t)(i - j) * 4; dl = qkv_lo + (size_t)(i - j) * 4;
    } else if (i < 4 * NE4) {
        src = wo; j = i - 3 * NE4; dh = wo_hi; dl = wo_lo;
    } else if (i < 4 * NE4 + NF4) {
        src = w1; j = i - 4 * NE4; dh = w1_hi; dl = w1_lo;
    } else {
        src = w2; j = i - 4 * NE4 - NF4; dh = w2_hi; dl = w2_lo;
    }
    float4 v = ((const float4*)src)[j];
    uint32_t h0, l0, h1, l1;
    pack_hl(v.x, v.y, h0, l0);
    pack_hl(v.z, v.w, h1, l1);
    uint2 H; H.x = h0; H.y = h1;
    uint2 L; L.x = l0; L.y = l1;
    ((uint2*)dh)[j] = H;
    ((uint2*)dl)[j] = L;
}

// ---------------------------------------------------------------------------
// LayerNorm: one block per row, writes (hi, lo) bf16
// ---------------------------------------------------------------------------
__global__ __launch_bounds__(256) void ln_kernel(
    const float* __restrict__ x, const float* __restrict__ g,
    const float* __restrict__ be, __nv_bfloat16* __restrict__ ohi,
    __nv_bfloat16* __restrict__ olo)
{
    const int N = EMBED;
    const size_t row = blockIdx.x;
    const float* xr = x + row * N;
    float s = 0.f, s2 = 0.f;
    #pragma unroll
    for (int i = threadIdx.x; i < N; i += 256) {
        float v = xr[i];
        s += v; s2 += v * v;
    }
    #pragma unroll
    for (int off = 16; off; off >>= 1) {
        s  += __shfl_xor_sync(0xffffffffu, s,  off);
        s2 += __shfl_xor_sync(0xffffffffu, s2, off);
    }
    __shared__ float red[16];
    __shared__ float mu_sh, rs_sh;
    int w = threadIdx.x >> 5, l = threadIdx.x & 31;
    if (l == 0) { red[w] = s; red[8 + w] = s2; }
    __syncthreads();
    if (threadIdx.x == 0) {
        float ts = 0.f, ts2 = 0.f;
        #pragma unroll
        for (int i = 0; i < 8; i++) { ts += red[i]; ts2 += red[8 + i]; }
        float mu  = ts / N;
        float var = ts2 / N - mu * mu;
        mu_sh = mu;
        rs_sh = rsqrtf(var + LN_EPS);
    }
    __syncthreads();
    float mu = mu_sh, rs = rs_sh;
    #pragma unroll
    for (int i = threadIdx.x; i < N; i += 256) {
        float y = (xr[i] - mu) * rs * g[i] + be[i];
        __nv_bfloat16 h, lo;
        split2(y, h, lo);
        ohi[row * N + i] = h;
        olo[row * N + i] = lo;
    }
}

// ---------------------------------------------------------------------------
// bf16-split GEMM: C[M,N] = A[M,K] @ W[N,K]^T (+bias,+relu,+res), 3 MMAs.
// CTA 128x128, warp tile 32x64, KTC 32 (SW64), 3-stage cp.async, 1 sync/iter.
// EPI: 2 = bias+res -> fp32; 5 = bias+relu -> (hi,lo) bf16;
//      6 = fused QKV (N=3072): q,k -> fp16 single; v -> bf16 (hi,lo); head layout
// ---------------------------------------------------------------------------
template <int EPI>
__global__ __launch_bounds__(256, 2) void gemm_mma(
    const __nv_bfloat16* __restrict__ Ah, const __nv_bfloat16* __restrict__ Al,
    const __nv_bfloat16* __restrict__ Bh, const __nv_bfloat16* __restrict__ Bl,
    const float* __restrict__ bias, const float* __restrict__ res,
    float* __restrict__ Cf, __nv_bfloat16* __restrict__ Chi,
    __nv_bfloat16* __restrict__ Clo, __half* __restrict__ Cq,
    int M, int N, int K)
{
    extern __shared__ char smem[];
    const uint32_t sb = s2u(smem);
    const int tid = threadIdx.x;
    const int lane = tid & 31, w = tid >> 5;
    const int bm = blockIdx.y * CTM, bn = blockIdx.x * CTN;
    const int wm = (w & 3) * 32, wn = (w >> 2) * 64;

    float acc[2][8][4];
    #pragma unroll
    for (int mt = 0; mt < 2; mt++)
        #pragma unroll
        for (int nt = 0; nt < 8; nt++)
            #pragma unroll
            for (int i = 0; i < 4; i++) acc[mt][nt][i] = 0.f;

    const int NC = K / KTC;

    auto load_chunk = [&](int c, int st) {
        const uint32_t s0 = sb + st * STG;
        const size_t k0 = (size_t)c * KTC;
        #pragma unroll
        for (int i = 0; i < 2; i++) {                 // A: 128 rows x 64B
            int idx = i * 256 + tid;
            int row = idx >> 2, c4 = idx & 3;
            uint32_t so = SW64((uint32_t)(row * 64 + c4 * 16));
            const size_t g = (size_t)(bm + row) * K + k0 + c4 * 8;
            cpa16(s0 + so,        Ah + g);
            cpa16(s0 + 8192 + so, Al + g);
        }
        #pragma unroll
        for (int i = 0; i < 2; i++) {                 // B: 128 rows x 64B
            int idx = i * 256 + tid;
            int row = idx >> 2, c4 = idx & 3;
            uint32_t so = SW64((uint32_t)(row * 64 + c4 * 16));
            const size_t g = (size_t)(bn + row) * K + k0 + c4 * 8;
            cpa16(s0 + 16384 + so, Bh + g);
            cpa16(s0 + 24576 + so, Bl + g);
        }
        asm volatile("cp.async.commit_group;" ::: "memory");
    };

    load_chunk(0, 0);
    load_chunk(1, 1);

    for (int c = 0; c < NC; c++) {
        if (c + 1 < NC) {
            asm volatile("cp.async.wait_group 1;" ::: "memory");
        } else {
            asm volatile("cp.async.wait_group 0;" ::: "memory");
        }
        __syncthreads();
        if (c + 2 < NC) load_chunk(c + 2, (c + 2) % 3);

        const uint32_t s0 = sb + (c % 3) * STG;
        #pragma unroll
        for (int ks = 0; ks < 2; ks++) {
            uint32_t ah[2][4], alr[2][4], bh[4][4], blr[4][4];
            const int arow = wm + (lane & 15);
            const int akb  = ks * 32 + (lane >> 4) * 16;
            #pragma unroll
            for (int mt = 0; mt < 2; mt++) {
                uint32_t ao = SW64((uint32_t)((arow + mt * 16) * 64 + akb));
                ldsm4(ah[mt],  s0 + ao);
                ldsm4(alr[mt], s0 + 8192 + ao);
            }
            const int brow = wn + ((lane >> 4) << 3) + (lane & 7);
            const int bkb  = ks * 32 + ((lane >> 3) & 1) * 16;
            #pragma unroll
            for (int np = 0; np < 4; np++) {
                uint32_t bo = SW64((uint32_t)((brow + np * 16) * 64 + bkb));
                ldsm4(bh[np],  s0 + 16384 + bo);
                ldsm4(blr[np], s0 + 24576 + bo);
            }
            #pragma unroll
            for (int mt = 0; mt < 2; mt++) {
                #pragma unroll
                for (int nt = 0; nt < 8; nt++) {
                    const int np = nt >> 1, ro = (nt & 1) * 2;
                    mma_bf16(acc[mt][nt], ah[mt],  bh[np][ro],  bh[np][ro + 1]);
                    mma_bf16(acc[mt][nt], ah[mt],  blr[np][ro], blr[np][ro + 1]);
                    mma_bf16(acc[mt][nt], alr[mt], bh[np][ro],  bh[np][ro + 1]);
                }
            }
        }
    }

    // ---- epilogue ----
    #pragma unroll
    for (int mt = 0; mt < 2; mt++) {
        #pragma unroll
        for (int nt = 0; nt < 8; nt++) {
            const int n = bn + wn + nt * 8 + (lane & 3) * 2;
            const float2 bs = *(const float2*)(bias + n);
            #pragma unroll
            for (int hh = 0; hh < 2; hh++) {
                const size_t m = (size_t)bm + wm + mt * 16 + (lane >> 2) + hh * 8;
                float v0 = acc[mt][nt][hh * 2]     + bs.x;
                float v1 = acc[mt][nt][hh * 2 + 1] + bs.y;
                if (EPI == 5) { v0 = fmaxf(v0, 0.f); v1 = fmaxf(v1, 0.f); }
                if (EPI == 2) {
                    float2 rr = *(const float2*)(res + m * N + n);
                    v0 += rr.x; v1 += rr.y;
                }
                if (EPI == 5) {
                    uint32_t ph, pl;
                    pack_hl(v0, v1, ph, pl);
                    *(uint32_t*)(Chi + m * N + n) = ph;
                    *(uint32_t*)(Clo + m * N + n) = pl;
                } else if (EPI == 6) {
                    const int which = n >> 10;
                    const int h_ = (n >> 6) & (HEADS - 1), d_ = n & 63;
                    const int b_ = (int)(m >> 11), s_ = (int)(m & 2047);
                    const size_t di = (((size_t)b_ * HEADS + h_) * SEQ + s_) * DK + d_;
                    if (which < 2) {
                        *(uint32_t*)(Cq + (size_t)which * HSZ + di) = pack2h(v0, v1);
                    } else {
                        uint32_t ph, pl;
                        pack_hl(v0, v1, ph, pl);
                        *(uint32_t*)(Chi + di) = ph;
                        *(uint32_t*)(Clo + di) = pl;
                    }
                } else {
                    float2 o; o.x = v0; o.y = v1;
                    *(float2*)(Cf + m * N + n) = o;
                }
            }
        }
    }
}

// ---------------------------------------------------------------------------
// Flash attention: QK^T in single fp16 (1 MMA), PV in bf16 split (3 MMAs).
// grid = (SEQ/128, HEADS, BATCH), 256 threads (8 warps, 16 q rows each).
// Smem: Q 16K (fp16) + 3-stage ring of (K fp16 8K | Vh 8K | Vl 8K).
// ---------------------------------------------------------------------------
__global__ __launch_bounds__(256, 2) void attn_mma(
    const __half* __restrict__ Q, const __half* __restrict__ K,
    const __nv_bfloat16* __restrict__ Vh, const __nv_bfloat16* __restrict__ Vl,
    __nv_bfloat16* __restrict__ Ohi, __nv_bfloat16* __restrict__ Olo)
{
    extern __shared__ char smem[];
    const uint32_t sb  = s2u(smem);
    const uint32_t sKV = sb + 16384;
    const int tid = threadIdx.x, lane = tid & 31, w = tid >> 5;
    const int qt = blockIdx.x, hd = blockIdx.y, b = blockIdx.z;
    const size_t hb = ((size_t)b * HEADS + hd) * SEQ * DK;
    const int m0 = qt * 128;
    const int wm = w * 16;

    // Q load: 128 rows x 128B = 16 KB (own cp.async group)
    #pragma unroll
    for (int i = 0; i < 4; i++) {
        int idx = i * 256 + tid;
        int row = idx >> 3, c16 = idx & 7;
        uint32_t so = SW128((uint32_t)(row * 128 + c16 * 16));
        cpa16(sb + so, Q + hb + (size_t)(m0 + row) * DK + c16 * 8);
    }
    asm volatile("cp.async.commit_group;" ::: "memory");

    auto load_kv = [&](int c, int st) {
        const uint32_t s0 = sKV + st * ASTG;
        const int k0 = c * 64;
        #pragma unroll
        for (int i = 0; i < 2; i++) {
            int idx = i * 256 + tid;
            int row = idx >> 3, c16 = idx & 7;
            uint32_t so = SW128((uint32_t)(row * 128 + c16 * 16));
            const size_t g = hb + (size_t)(k0 + row) * DK + c16 * 8;
            cpa16(s0 + so,         K  + g);
            cpa16(s0 + 8192 + so,  Vh + g);
            cpa16(s0 + 16384 + so, Vl + g);
        }
        asm volatile("cp.async.commit_group;" ::: "memory");
    };
    load_kv(0, 0);
    load_kv(1, 1);

    // wait for Q (2 kv groups still outstanding), park in registers
    asm volatile("cp.async.wait_group 2;" ::: "memory");
    __syncthreads();
    uint32_t qf[4][4];
    #pragma unroll
    for (int ks = 0; ks < 4; ks++) {
        uint32_t ao = SW128((uint32_t)((wm + (lane & 15)) * 128
                                       + ks * 32 + (lane >> 4) * 16));
        ldsm4(qf[ks], sb + ao);
    }

    float o[8][4];
    #pragma unroll
    for (int j = 0; j < 8; j++)
        #pragma unroll
        for (int i = 0; i < 4; i++) o[j][i] = 0.f;
    float mr0 = -1e30f, mr1 = -1e30f, l0 = 0.f, l1 = 0.f;

    const int NC = SEQ / 64;
    for (int c = 0; c < NC; c++) {
        if (c + 1 < NC) {
            asm volatile("cp.async.wait_group 1;" ::: "memory");
        } else {
            asm volatile("cp.async.wait_group 0;" ::: "memory");
        }
        __syncthreads();
        if (c + 2 < NC) load_kv(c + 2, (c + 2) % 3);
        const uint32_t s0 = sKV + (c % 3) * ASTG;

        // ---- S = Q K^T  (single fp16 MMA) ----
        float sacc[8][4];
        #pragma unroll
        for (int j = 0; j < 8; j++)
            #pragma unroll
            for (int i = 0; i < 4; i++) sacc[j][i] = 0.f;

        #pragma unroll
        for (int ks = 0; ks < 4; ks++) {
            const int brow = ((lane >> 4) << 3) + (lane & 7);
            const int bkb  = ks * 32 + ((lane >> 3) & 1) * 16;
            #pragma unroll
            for (int np = 0; np < 4; np++) {
                uint32_t kf[4];
                uint32_t bo = SW128((uint32_t)((brow + np * 16) * 128 + bkb));
                ldsm4(kf, s0 + bo);
                mma_f16(sacc[np * 2],     qf[ks], kf[0], kf[1]);
                mma_f16(sacc[np * 2 + 1], qf[ks], kf[2], kf[3]);
            }
        }

        // ---- online softmax ----
        float cm0 = -1e30f, cm1 = -1e30f;
        #pragma unroll
        for (int j = 0; j < 8; j++) {
            cm0 = fmaxf(cm0, fmaxf(sacc[j][0], sacc[j][1]));
            cm1 = fmaxf(cm1, fmaxf(sacc[j][2], sacc[j][3]));
        }
        #pragma unroll
        for (int off = 1; off <= 2; off <<= 1) {
            cm0 = fmaxf(cm0, __shfl_xor_sync(0xffffffffu, cm0, off));
            cm1 = fmaxf(cm1, __shfl_xor_sync(0xffffffffu, cm1, off));
        }
        const float mn0 = fmaxf(mr0, cm0), mn1 = fmaxf(mr1, cm1);
        const float a0 = ex2f((mr0 - mn0) * SSC);
        const float a1 = ex2f((mr1 - mn1) * SSC);
        mr0 = mn0; mr1 = mn1;
        float sum0 = 0.f, sum1 = 0.f;
        #pragma unroll
        for (int j = 0; j < 8; j++) {
            sacc[j][0] = ex2f((sacc[j][0] - mn0) * SSC);
            sacc[j][1] = ex2f((sacc[j][1] - mn0) * SSC);
            sacc[j][2] = ex2f((sacc[j][2] - mn1) * SSC);
            sacc[j][3] = ex2f((sacc[j][3] - mn1) * SSC);
            sum0 += sacc[j][0] + sacc[j][1];
            sum1 += sacc[j][2] + sacc[j][3];
        }
        #pragma unroll
        for (int off = 1; off <= 2; off <<= 1) {
            sum0 += __shfl_xor_sync(0xffffffffu, sum0, off);
            sum1 += __shfl_xor_sync(0xffffffffu, sum1, off);
        }
        l0 = l0 * a0 + sum0;
        l1 = l1 * a1 + sum1;
        #pragma unroll
        for (int j = 0; j < 8; j++) {
            o[j][0] *= a0; o[j][1] *= a0;
            o[j][2] *= a1; o[j][3] *= a1;
        }

        // ---- O += P V  (P split bf16, V bf16 hi/lo: 3 MMAs) ----
        #pragma unroll
        for (int ks = 0; ks < 4; ks++) {
            uint32_t aph[4], apl[4];
            pack_hl(sacc[2 * ks][0],     sacc[2 * ks][1],     aph[0], apl[0]);
            pack_hl(sacc[2 * ks][2],     sacc[2 * ks][3],     aph[1], apl[1]);
            pack_hl(sacc[2 * ks + 1][0], sacc[2 * ks + 1][1], aph[2], apl[2]);
            pack_hl(sacc[2 * ks + 1][2], sacc[2 * ks + 1][3], aph[3], apl[3]);
            const int vrow = ks * 16 + ((lane >> 3) & 1) * 8 + (lane & 7);
            #pragma unroll
            for (int np = 0; np < 4; np++) {
                uint32_t vh[4], vl[4];
                uint32_t vo = SW128((uint32_t)(vrow * 128 + np * 32
                                               + (lane >> 4) * 16));
                ldsm4t(vh, s0 + 8192 + vo);
                ldsm4t(vl, s0 + 16384 + vo);
                mma_bf16(o[np * 2],     aph, vh[0], vh[1]);
                mma_bf16(o[np * 2],     aph, vl[0], vl[1]);
                mma_bf16(o[np * 2],     apl, vh[0], vh[1]);
                mma_bf16(o[np * 2 + 1], aph, vh[2], vh[3]);
                mma_bf16(o[np * 2 + 1], aph, vl[2], vl[3]);
                mma_bf16(o[np * 2 + 1], apl, vh[2], vh[3]);
            }
        }
    }

    // ---- epilogue ----
    const float inv0 = 1.f / l0, inv1 = 1.f / l1;
    const int s0r = m0 + wm + (lane >> 2);
    const size_t r0 = (size_t)b * SEQ + s0r;
    const size_t r1 = r0 + 8;
    #pragma unroll
    for (int f = 0; f < 8; f++) {
        const int col = hd * DK + f * 8 + 2 * (lane & 3);
        uint32_t ph, pl;
        pack_hl(o[f][0] * inv0, o[f][1] * inv0, ph, pl);
        *(uint32_t*)(Ohi + r0 * EMBED + col) = ph;
        *(uint32_t*)(Olo + r0 * EMBED + col) = pl;
        pack_hl(o[f][2] * inv1, o[f][3] * inv1, ph, pl);
        *(uint32_t*)(Ohi + r1 * EMBED + col) = ph;
        *(uint32_t*)(Olo + r1 * EMBED + col) = pl;
    }
}

// ---------------------------------------------------------------------------
// Launch
// ---------------------------------------------------------------------------
extern "C" void kernel_launch(void* const* d_in, const int* in_sizes, int n_in,
                              void* d_out, int out_size)
{
    const float* x   = (const float*)d_in[0];
    const float* Wq  = (const float*)d_in[1];
    const float* bq  = (const float*)d_in[2];
    const float* Wk  = (const float*)d_in[3];
    const float* bk  = (const float*)d_in[4];
    const float* Wv  = (const float*)d_in[5];
    const float* bv  = (const float*)d_in[6];
    const float* Wo  = (const float*)d_in[7];
    const float* bo  = (const float*)d_in[8];
    const float* W1  = (const float*)d_in[9];
    const float* b1  = (const float*)d_in[10];
    const float* W2  = (const float*)d_in[11];
    const float* b2  = (const float*)d_in[12];
    const float* g1  = (const float*)d_in[13];
    const float* be1 = (const float*)d_in[14];
    const float* g2  = (const float*)d_in[15];
    const float* be2 = (const float*)d_in[16];
    float* out = (float*)d_out;

    __nv_bfloat16 *h_hi, *h_lo, *v_hi, *v_lo, *ao_hi, *ao_lo;
    __nv_bfloat16 *h2_hi, *h2_lo, *f_hi, *f_lo;
    __nv_bfloat16 *wqkv_hi, *wqkv_lo, *wo_hi, *wo_lo, *w1_hi, *w1_lo, *w2_hi, *w2_lo;
    __half *qk;
    float *x1, *bqkv;
    cudaGetSymbolAddress((void**)&h_hi,    g_h_hi);
    cudaGetSymbolAddress((void**)&h_lo,    g_h_lo);
    cudaGetSymbolAddress((void**)&qk,      g_qk);
    cudaGetSymbolAddress((void**)&v_hi,    g_v_hi);
    cudaGetSymbolAddress((void**)&v_lo,    g_v_lo);
    cudaGetSymbolAddress((void**)&ao_hi,   g_ao_hi);
    cudaGetSymbolAddress((void**)&ao_lo,   g_ao_lo);
    cudaGetSymbolAddress((void**)&x1,      g_x1);
    cudaGetSymbolAddress((void**)&h2_hi,   g_h2_hi);
    cudaGetSymbolAddress((void**)&h2_lo,   g_h2_lo);
    cudaGetSymbolAddress((void**)&f_hi,    g_f_hi);
    cudaGetSymbolAddress((void**)&f_lo,    g_f_lo);
    cudaGetSymbolAddress((void**)&wqkv_hi, g_wqkv_hi);
    cudaGetSymbolAddress((void**)&wqkv_lo, g_wqkv_lo);
    cudaGetSymbolAddress((void**)&wo_hi,   g_wo_hi);
    cudaGetSymbolAddress((void**)&wo_lo,   g_wo_lo);
    cudaGetSymbolAddress((void**)&w1_hi,   g_w1_hi);
    cudaGetSymbolAddress((void**)&w1_lo,   g_w1_lo);
    cudaGetSymbolAddress((void**)&w2_hi,   g_w2_hi);
    cudaGetSymbolAddress((void**)&w2_lo,   g_w2_lo);
    cudaGetSymbolAddress((void**)&bqkv,    g_bqkv);

    cudaFuncSetAttribute(gemm_mma<2>, cudaFuncAttributeMaxDynamicSharedMemorySize, SMEM_G);
    cudaFuncSetAttribute(gemm_mma<5>, cudaFuncAttributeMaxDynamicSharedMemorySize, SMEM_G);
    cudaFuncSetAttribute(gemm_mma<6>, cudaFuncAttributeMaxDynamicSharedMemorySize, SMEM_G);
    cudaFuncSetAttribute(attn_mma, cudaFuncAttributeMaxDynamicSharedMemorySize, SMEM_A);

    // bias concat (device-to-device, graph-capturable)
    cudaMemcpyAsync(bqkv,             bq, EMBED * sizeof(float), cudaMemcpyDeviceToDevice, 0);
    cudaMemcpyAsync(bqkv + EMBED,     bk, EMBED * sizeof(float), cudaMemcpyDeviceToDevice, 0);
    cudaMemcpyAsync(bqkv + 2 * EMBED, bv, EMBED * sizeof(float), cudaMemcpyDeviceToDevice, 0);

    // all weight splits in one kernel: 3M float4 elements
    cvt_all<<<(4 * NE4 + 2 * NF4) / 256, 256>>>(
        Wq, Wk, Wv, Wo, W1, W2,
        wqkv_hi, wqkv_lo, wo_hi, wo_lo, w1_hi, w1_lo, w2_hi, w2_lo);

    // LN1 -> (hi, lo)
    ln_kernel<<<MROWS, 256>>>(x, g1, be1, h_hi, h_lo);

    // Fused QKV projection -> q,k fp16 single; v bf16 (hi,lo); head layout
    {
        dim3 grid(3 * EMBED / CTN, MROWS / CTM);
        gemm_mma<6><<<grid, 256, SMEM_G>>>(h_hi, h_lo, wqkv_hi, wqkv_lo, bqkv,
                                           nullptr, nullptr, v_hi, v_lo, qk,
                                           MROWS, 3 * EMBED, EMBED);
    }

    // Attention -> ao (hi, lo)
    {
        dim3 grid(SEQ / 128, HEADS, BATCH);
        attn_mma<<<grid, 256, SMEM_A>>>(qk, qk + HSZ, v_hi, v_lo, ao_hi, ao_lo);
    }

    // O projection + residual: x1 = x + ao @ Wo^T + bo
    {
        dim3 grid(EMBED / CTN, MROWS / CTM);
        gemm_mma<2><<<grid, 256, SMEM_G>>>(ao_hi, ao_lo, wo_hi, wo_lo, bo, x,
                                           x1, nullptr, nullptr, nullptr,
                                           MROWS, EMBED, EMBED);
    }

    // LN2 -> (hi, lo)
    ln_kernel<<<MROWS, 256>>>(x1, g2, be2, h2_hi, h2_lo);

    // FFN1 + relu -> f (hi, lo)
    {
        dim3 grid(FFN / CTN, MROWS / CTM);
        gemm_mma<5><<<grid, 256, SMEM_G>>>(h2_hi, h2_lo, w1_hi, w1_lo, b1,
                                           nullptr, nullptr, f_hi, f_lo, nullptr,
                                           MROWS, FFN, EMBED);
    }

    // FFN2 + residual -> out
    {
        dim3 grid(EMBED / CTN, MROWS / CTM);
        gemm_mma<2><<<grid, 256, SMEM_G>>>(f_hi, f_lo, w2_hi, w2_lo, b2, x1,
                                           out, nullptr, nullptr, nullptr,
                                           MROWS, EMBED, FFN);
    }
}

// round 10
// speedup vs baseline: 1.2085x; 1.0856x over previous
#include <cuda_runtime.h>
#include <cuda_bf16.h>
#include <cuda_fp16.h>
#include <math.h>
#include <stdint.h>

// ---------------------------------------------------------------------------
// Problem constants
// ---------------------------------------------------------------------------
#define BATCH   2
#define SEQ     2048
#define EMBED   1024
#define HEADS   16
#define DK      64
#define FFN     4096
#define MROWS   (BATCH * SEQ)          // 4096
#define LN_EPS  1e-5f
#define SSC     0.1803368801111204f    // 0.125 * log2(e)
#define HSZ     (MROWS * EMBED)        // 4M elements

// GEMM tiling: CTA 128x128, K-chunk 32, warp tile 32x64 (8 warps: 4m x 2n)
#define CTM 128
#define CTN 128
#define KTC 32
#define STG 32768                      // Ah 8K + Al 8K + Bh 8K + Bl 8K
#define SMEM_G (3 * STG)               // 96 KB, 3-stage -> 2 CTA/SM

// Attention: Q 16K (fp16) + 3 stages x (K 8K + V 8K)
#define ASTG 16384
#define SMEM_A (16384 + 3 * ASTG)      // 64 KB -> 2 CTA/SM

#define SW128(o) ((o) ^ (((o) >> 3) & 0x70))
#define SW64(o)  ((o) ^ (((o) >> 3) & 0x30))

// ---------------------------------------------------------------------------
// Scratch buffers (allocation-free: __device__ globals)
// ---------------------------------------------------------------------------
__device__ __nv_bfloat16 g_h_hi [HSZ];
__device__ __nv_bfloat16 g_h_lo [HSZ];
__device__ __half        g_qkv  [3 * HSZ];   // q | k | v, fp16, [B,H,S,DK]
__device__ __nv_bfloat16 g_ao_hi[HSZ];
__device__ __nv_bfloat16 g_ao_lo[HSZ];
__device__ float         g_x1   [HSZ];
__device__ __nv_bfloat16 g_h2_hi[HSZ];
__device__ __nv_bfloat16 g_h2_lo[HSZ];
__device__ __nv_bfloat16 g_f_hi [MROWS * FFN];
__device__ __nv_bfloat16 g_f_lo [MROWS * FFN];

__device__ __nv_bfloat16 g_wqkv_hi[3 * EMBED * EMBED];  // Wq | Wk | Wv
__device__ __nv_bfloat16 g_wqkv_lo[3 * EMBED * EMBED];
__device__ __nv_bfloat16 g_wo_hi[EMBED * EMBED];
__device__ __nv_bfloat16 g_wo_lo[EMBED * EMBED];
__device__ __nv_bfloat16 g_w1_hi[FFN * EMBED];
__device__ __nv_bfloat16 g_w1_lo[FFN * EMBED];
__device__ __nv_bfloat16 g_w2_hi[EMBED * FFN];
__device__ __nv_bfloat16 g_w2_lo[EMBED * FFN];
__device__ float         g_bqkv[3 * EMBED];

// ---------------------------------------------------------------------------
// helpers
// ---------------------------------------------------------------------------
static __device__ __forceinline__ uint32_t s2u(const void* p) {
    uint32_t a;
    asm("{ .reg .u64 t; cvta.to.shared.u64 t, %1; cvt.u32.u64 %0, t; }"
        : "=r"(a) : "l"(p));
    return a;
}
static __device__ __forceinline__ void cpa16(uint32_t s, const void* g) {
    asm volatile("cp.async.cg.shared.global [%0], [%1], 16;"
                 :: "r"(s), "l"(g) : "memory");
}
static __device__ __forceinline__ void ldsm4(uint32_t* f, uint32_t a) {
    asm volatile("ldmatrix.sync.aligned.m8n8.x4.shared.b16 {%0,%1,%2,%3}, [%4];"
                 : "=r"(f[0]), "=r"(f[1]), "=r"(f[2]), "=r"(f[3]) : "r"(a));
}
static __device__ __forceinline__ void ldsm4t(uint32_t* f, uint32_t a) {
    asm volatile("ldmatrix.sync.aligned.m8n8.x4.trans.shared.b16 {%0,%1,%2,%3}, [%4];"
                 : "=r"(f[0]), "=r"(f[1]), "=r"(f[2]), "=r"(f[3]) : "r"(a));
}
static __device__ __forceinline__ void mma_bf16(float* c, const uint32_t* a,
                                                uint32_t b0, uint32_t b1) {
    asm volatile(
        "mma.sync.aligned.m16n8k16.row.col.f32.bf16.bf16.f32 "
        "{%0,%1,%2,%3}, {%4,%5,%6,%7}, {%8,%9}, {%0,%1,%2,%3};"
        : "+f"(c[0]), "+f"(c[1]), "+f"(c[2]), "+f"(c[3])
        : "r"(a[0]), "r"(a[1]), "r"(a[2]), "r"(a[3]), "r"(b0), "r"(b1));
}
static __device__ __forceinline__ void mma_f16(float* c, const uint32_t* a,
                                               uint32_t b0, uint32_t b1) {
    asm volatile(
        "mma.sync.aligned.m16n8k16.row.col.f32.f16.f16.f32 "
        "{%0,%1,%2,%3}, {%4,%5,%6,%7}, {%8,%9}, {%0,%1,%2,%3};"
        : "+f"(c[0]), "+f"(c[1]), "+f"(c[2]), "+f"(c[3])
        : "r"(a[0]), "r"(a[1]), "r"(a[2]), "r"(a[3]), "r"(b0), "r"(b1));
}
static __device__ __forceinline__ float ex2f(float x) {
    float y;
    asm("ex2.approx.f32 %0, %1;" : "=f"(y) : "f"(x));
    return y;
}
static __device__ __forceinline__ void split2(float v, __nv_bfloat16& h, __nv_bfloat16& l) {
    h = __float2bfloat16(v);
    l = __float2bfloat16(v - __bfloat162float(h));
}
static __device__ __forceinline__ void pack_hl(float x, float y,
                                               uint32_t& hi, uint32_t& lo) {
    __nv_bfloat16 hx, lx, hy, ly;
    split2(x, hx, lx);
    split2(y, hy, ly);
    __nv_bfloat162 H; H.x = hx; H.y = hy;
    __nv_bfloat162 L; L.x = lx; L.y = ly;
    hi = *(uint32_t*)&H;
    lo = *(uint32_t*)&L;
}
static __device__ __forceinline__ uint32_t pack2h(float x, float y) {
    __half2 h = __floats2half2_rn(x, y);
    return *(uint32_t*)&h;
}

// ---------------------------------------------------------------------------
// One-shot weight split (fp32 -> bf16 hi + bf16 lo), all matrices
// ---------------------------------------------------------------------------
#define NE4 (EMBED * EMBED / 4)       // 256K
#define NF4 (FFN * EMBED / 4)         // 1M
__global__ __launch_bounds__(256) void cvt_all(
    const float* __restrict__ wq, const float* __restrict__ wk,
    const float* __restrict__ wv, const float* __restrict__ wo,
    const float* __restrict__ w1, const float* __restrict__ w2,
    __nv_bfloat16* __restrict__ qkv_hi, __nv_bfloat16* __restrict__ qkv_lo,
    __nv_bfloat16* __restrict__ wo_hi,  __nv_bfloat16* __restrict__ wo_lo,
    __nv_bfloat16* __restrict__ w1_hi,  __nv_bfloat16* __restrict__ w1_lo,
    __nv_bfloat16* __restrict__ w2_hi,  __nv_bfloat16* __restrict__ w2_lo)
{
    int i = blockIdx.x * 256 + threadIdx.x;    // float4 index, < 3M
    const float* src;
    __nv_bfloat16 *dh, *dl;
    int j;
    if (i < 3 * NE4) {
        src = (i < NE4) ? wq : (i < 2 * NE4) ? wk : wv;
        j = (i < NE4) ? i : (i < 2 * NE4) ? i - NE4 : i - 2 * NE4;
        dh = qkv_hi + (size_t)(i - j) * 4; dl = qkv_lo + (size_t)(i - j) * 4;
    } else if (i < 4 * NE4) {
        src = wo; j = i - 3 * NE4; dh = wo_hi; dl = wo_lo;
    } else if (i < 4 * NE4 + NF4) {
        src = w1; j = i - 4 * NE4; dh = w1_hi; dl = w1_lo;
    } else {
        src = w2; j = i - 4 * NE4 - NF4; dh = w2_hi; dl = w2_lo;
    }
    float4 v = ((const float4*)src)[j];
    uint32_t h0, l0, h1, l1;
    pack_hl(v.x, v.y, h0, l0);
    pack_hl(v.z, v.w, h1, l1);
    uint2 H; H.x = h0; H.y = h1;
    uint2 L; L.x = l0; L.y = l1;
    ((uint2*)dh)[j] = H;
    ((uint2*)dl)[j] = L;
}

// ---------------------------------------------------------------------------
// LayerNorm: one block per row, writes (hi, lo) bf16
// ---------------------------------------------------------------------------
__global__ __launch_bounds__(256) void ln_kernel(
    const float* __restrict__ x, const float* __restrict__ g,
    const float* __restrict__ be, __nv_bfloat16* __restrict__ ohi,
    __nv_bfloat16* __restrict__ olo)
{
    const int N = EMBED;
    const size_t row = blockIdx.x;
    const float* xr = x + row * N;
    float s = 0.f, s2 = 0.f;
    #pragma unroll
    for (int i = threadIdx.x; i < N; i += 256) {
        float v = xr[i];
        s += v; s2 += v * v;
    }
    #pragma unroll
    for (int off = 16; off; off >>= 1) {
        s  += __shfl_xor_sync(0xffffffffu, s,  off);
        s2 += __shfl_xor_sync(0xffffffffu, s2, off);
    }
    __shared__ float red[16];
    __shared__ float mu_sh, rs_sh;
    int w = threadIdx.x >> 5, l = threadIdx.x & 31;
    if (l == 0) { red[w] = s; red[8 + w] = s2; }
    __syncthreads();
    if (threadIdx.x == 0) {
        float ts = 0.f, ts2 = 0.f;
        #pragma unroll
        for (int i = 0; i < 8; i++) { ts += red[i]; ts2 += red[8 + i]; }
        float mu  = ts / N;
        float var = ts2 / N - mu * mu;
        mu_sh = mu;
        rs_sh = rsqrtf(var + LN_EPS);
    }
    __syncthreads();
    float mu = mu_sh, rs = rs_sh;
    #pragma unroll
    for (int i = threadIdx.x; i < N; i += 256) {
        float y = (xr[i] - mu) * rs * g[i] + be[i];
        __nv_bfloat16 h, lo;
        split2(y, h, lo);
        ohi[row * N + i] = h;
        olo[row * N + i] = lo;
    }
}

// ---------------------------------------------------------------------------
// bf16-split GEMM: C[M,N] = A[M,K] @ W[N,K]^T (+bias,+relu,+res), 3 MMAs.
// CTA 128x128, warp tile 32x64, KTC 32 (SW64), 3-stage cp.async, 1 sync/iter.
// EPI: 2 = bias+res -> fp32; 5 = bias+relu -> (hi,lo) bf16;
//      6 = fused QKV (N=3072): q,k,v -> fp16 single, head layout
// ---------------------------------------------------------------------------
template <int EPI>
__global__ __launch_bounds__(256, 2) void gemm_mma(
    const __nv_bfloat16* __restrict__ Ah, const __nv_bfloat16* __restrict__ Al,
    const __nv_bfloat16* __restrict__ Bh, const __nv_bfloat16* __restrict__ Bl,
    const float* __restrict__ bias, const float* __restrict__ res,
    float* __restrict__ Cf, __nv_bfloat16* __restrict__ Chi,
    __nv_bfloat16* __restrict__ Clo, __half* __restrict__ Cq,
    int M, int N, int K)
{
    extern __shared__ char smem[];
    const uint32_t sb = s2u(smem);
    const int tid = threadIdx.x;
    const int lane = tid & 31, w = tid >> 5;
    const int bm = blockIdx.y * CTM, bn = blockIdx.x * CTN;
    const int wm = (w & 3) * 32, wn = (w >> 2) * 64;

    float acc[2][8][4];
    #pragma unroll
    for (int mt = 0; mt < 2; mt++)
        #pragma unroll
        for (int nt = 0; nt < 8; nt++)
            #pragma unroll
            for (int i = 0; i < 4; i++) acc[mt][nt][i] = 0.f;

    const int NC = K / KTC;

    auto load_chunk = [&](int c, int st) {
        const uint32_t s0 = sb + st * STG;
        const size_t k0 = (size_t)c * KTC;
        #pragma unroll
        for (int i = 0; i < 2; i++) {                 // A: 128 rows x 64B
            int idx = i * 256 + tid;
            int row = idx >> 2, c4 = idx & 3;
            uint32_t so = SW64((uint32_t)(row * 64 + c4 * 16));
            const size_t g = (size_t)(bm + row) * K + k0 + c4 * 8;
            cpa16(s0 + so,        Ah + g);
            cpa16(s0 + 8192 + so, Al + g);
        }
        #pragma unroll
        for (int i = 0; i < 2; i++) {                 // B: 128 rows x 64B
            int idx = i * 256 + tid;
            int row = idx >> 2, c4 = idx & 3;
            uint32_t so = SW64((uint32_t)(row * 64 + c4 * 16));
            const size_t g = (size_t)(bn + row) * K + k0 + c4 * 8;
            cpa16(s0 + 16384 + so, Bh + g);
            cpa16(s0 + 24576 + so, Bl + g);
        }
        asm volatile("cp.async.commit_group;" ::: "memory");
    };

    load_chunk(0, 0);
    load_chunk(1, 1);

    for (int c = 0; c < NC; c++) {
        if (c + 1 < NC) {
            asm volatile("cp.async.wait_group 1;" ::: "memory");
        } else {
            asm volatile("cp.async.wait_group 0;" ::: "memory");
        }
        __syncthreads();
        if (c + 2 < NC) load_chunk(c + 2, (c + 2) % 3);

        const uint32_t s0 = sb + (c % 3) * STG;
        #pragma unroll
        for (int ks = 0; ks < 2; ks++) {
            uint32_t ah[2][4], alr[2][4], bh[4][4], blr[4][4];
            const int arow = wm + (lane & 15);
            const int akb  = ks * 32 + (lane >> 4) * 16;
            #pragma unroll
            for (int mt = 0; mt < 2; mt++) {
                uint32_t ao = SW64((uint32_t)((arow + mt * 16) * 64 + akb));
                ldsm4(ah[mt],  s0 + ao);
                ldsm4(alr[mt], s0 + 8192 + ao);
            }
            const int brow = wn + ((lane >> 4) << 3) + (lane & 7);
            const int bkb  = ks * 32 + ((lane >> 3) & 1) * 16;
            #pragma unroll
            for (int np = 0; np < 4; np++) {
                uint32_t bo = SW64((uint32_t)((brow + np * 16) * 64 + bkb));
                ldsm4(bh[np],  s0 + 16384 + bo);
                ldsm4(blr[np], s0 + 24576 + bo);
            }
            #pragma unroll
            for (int mt = 0; mt < 2; mt++) {
                #pragma unroll
                for (int nt = 0; nt < 8; nt++) {
                    const int np = nt >> 1, ro = (nt & 1) * 2;
                    mma_bf16(acc[mt][nt], ah[mt],  bh[np][ro],  bh[np][ro + 1]);
                    mma_bf16(acc[mt][nt], ah[mt],  blr[np][ro], blr[np][ro + 1]);
                    mma_bf16(acc[mt][nt], alr[mt], bh[np][ro],  bh[np][ro + 1]);
                }
            }
        }
    }

    // ---- epilogue ----
    #pragma unroll
    for (int mt = 0; mt < 2; mt++) {
        #pragma unroll
        for (int nt = 0; nt < 8; nt++) {
            const int n = bn + wn + nt * 8 + (lane & 3) * 2;
            const float2 bs = *(const float2*)(bias + n);
            #pragma unroll
            for (int hh = 0; hh < 2; hh++) {
                const size_t m = (size_t)bm + wm + mt * 16 + (lane >> 2) + hh * 8;
                float v0 = acc[mt][nt][hh * 2]     + bs.x;
                float v1 = acc[mt][nt][hh * 2 + 1] + bs.y;
                if (EPI == 5) { v0 = fmaxf(v0, 0.f); v1 = fmaxf(v1, 0.f); }
                if (EPI == 2) {
                    float2 rr = *(const float2*)(res + m * N + n);
                    v0 += rr.x; v1 += rr.y;
                }
                if (EPI == 5) {
                    uint32_t ph, pl;
                    pack_hl(v0, v1, ph, pl);
                    *(uint32_t*)(Chi + m * N + n) = ph;
                    *(uint32_t*)(Clo + m * N + n) = pl;
                } else if (EPI == 6) {
                    const int which = n >> 10;
                    const int h_ = (n >> 6) & (HEADS - 1), d_ = n & 63;
                    const int b_ = (int)(m >> 11), s_ = (int)(m & 2047);
                    const size_t di = (size_t)which * HSZ
                        + (((size_t)b_ * HEADS + h_) * SEQ + s_) * DK + d_;
                    *(uint32_t*)(Cq + di) = pack2h(v0, v1);
                } else {
                    float2 o; o.x = v0; o.y = v1;
                    *(float2*)(Cf + m * N + n) = o;
                }
            }
        }
    }
}

// ---------------------------------------------------------------------------
// Flash attention: QK^T and PV both single fp16 (1 MMA each).
// grid = (SEQ/128, HEADS, BATCH), 256 threads (8 warps, 16 q rows each).
// Smem: Q 16K (fp16) + 3-stage ring of (K 8K | V 8K). 64 KB -> 2 CTA/SM.
// Output ao written bf16 (hi,lo) = exact, for split O-projection.
// ---------------------------------------------------------------------------
__global__ __launch_bounds__(256, 2) void attn_mma(
    const __half* __restrict__ Q, const __half* __restrict__ K,
    const __half* __restrict__ V,
    __nv_bfloat16* __restrict__ Ohi, __nv_bfloat16* __restrict__ Olo)
{
    extern __shared__ char smem[];
    const uint32_t sb  = s2u(smem);
    const uint32_t sKV = sb + 16384;
    const int tid = threadIdx.x, lane = tid & 31, w = tid >> 5;
    const int qt = blockIdx.x, hd = blockIdx.y, b = blockIdx.z;
    const size_t hb = ((size_t)b * HEADS + hd) * SEQ * DK;
    const int m0 = qt * 128;
    const int wm = w * 16;

    // Q load: 128 rows x 128B = 16 KB (own cp.async group)
    #pragma unroll
    for (int i = 0; i < 4; i++) {
        int idx = i * 256 + tid;
        int row = idx >> 3, c16 = idx & 7;
        uint32_t so = SW128((uint32_t)(row * 128 + c16 * 16));
        cpa16(sb + so, Q + hb + (size_t)(m0 + row) * DK + c16 * 8);
    }
    asm volatile("cp.async.commit_group;" ::: "memory");

    auto load_kv = [&](int c, int st) {
        const uint32_t s0 = sKV + st * ASTG;
        const int k0 = c * 64;
        #pragma unroll
        for (int i = 0; i < 2; i++) {
            int idx = i * 256 + tid;
            int row = idx >> 3, c16 = idx & 7;
            uint32_t so = SW128((uint32_t)(row * 128 + c16 * 16));
            const size_t g = hb + (size_t)(k0 + row) * DK + c16 * 8;
            cpa16(s0 + so,        K + g);
            cpa16(s0 + 8192 + so, V + g);
        }
        asm volatile("cp.async.commit_group;" ::: "memory");
    };
    load_kv(0, 0);
    load_kv(1, 1);

    // wait for Q (2 kv groups still outstanding), park in registers
    asm volatile("cp.async.wait_group 2;" ::: "memory");
    __syncthreads();
    uint32_t qf[4][4];
    #pragma unroll
    for (int ks = 0; ks < 4; ks++) {
        uint32_t ao = SW128((uint32_t)((wm + (lane & 15)) * 128
                                       + ks * 32 + (lane >> 4) * 16));
        ldsm4(qf[ks], sb + ao);
    }

    float o[8][4];
    #pragma unroll
    for (int j = 0; j < 8; j++)
        #pragma unroll
        for (int i = 0; i < 4; i++) o[j][i] = 0.f;
    float mr0 = -1e30f, mr1 = -1e30f, l0 = 0.f, l1 = 0.f;

    const int NC = SEQ / 64;
    for (int c = 0; c < NC; c++) {
        if (c + 1 < NC) {
            asm volatile("cp.async.wait_group 1;" ::: "memory");
        } else {
            asm volatile("cp.async.wait_group 0;" ::: "memory");
        }
        __syncthreads();
        if (c + 2 < NC) load_kv(c + 2, (c + 2) % 3);
        const uint32_t s0 = sKV + (c % 3) * ASTG;

        // ---- S = Q K^T  (single fp16 MMA) ----
        float sacc[8][4];
        #pragma unroll
        for (int j = 0; j < 8; j++)
            #pragma unroll
            for (int i = 0; i < 4; i++) sacc[j][i] = 0.f;

        #pragma unroll
        for (int ks = 0; ks < 4; ks++) {
            const int brow = ((lane >> 4) << 3) + (lane & 7);
            const int bkb  = ks * 32 + ((lane >> 3) & 1) * 16;
            #pragma unroll
            for (int np = 0; np < 4; np++) {
                uint32_t kf[4];
                uint32_t bo = SW128((uint32_t)((brow + np * 16) * 128 + bkb));
                ldsm4(kf, s0 + bo);
                mma_f16(sacc[np * 2],     qf[ks], kf[0], kf[1]);
                mma_f16(sacc[np * 2 + 1], qf[ks], kf[2], kf[3]);
            }
        }

        // ---- online softmax ----
        float cm0 = -1e30f, cm1 = -1e30f;
        #pragma unroll
        for (int j = 0; j < 8; j++) {
            cm0 = fmaxf(cm0, fmaxf(sacc[j][0], sacc[j][1]));
            cm1 = fmaxf(cm1, fmaxf(sacc[j][2], sacc[j][3]));
        }
        #pragma unroll
        for (int off = 1; off <= 2; off <<= 1) {
            cm0 = fmaxf(cm0, __shfl_xor_sync(0xffffffffu, cm0, off));
            cm1 = fmaxf(cm1, __shfl_xor_sync(0xffffffffu, cm1, off));
        }
        const float mn0 = fmaxf(mr0, cm0), mn1 = fmaxf(mr1, cm1);
        const float a0 = ex2f((mr0 - mn0) * SSC);
        const float a1 = ex2f((mr1 - mn1) * SSC);
        mr0 = mn0; mr1 = mn1;
        float sum0 = 0.f, sum1 = 0.f;
        #pragma unroll
        for (int j = 0; j < 8; j++) {
            sacc[j][0] = ex2f((sacc[j][0] - mn0) * SSC);
            sacc[j][1] = ex2f((sacc[j][1] - mn0) * SSC);
            sacc[j][2] = ex2f((sacc[j][2] - mn1) * SSC);
            sacc[j][3] = ex2f((sacc[j][3] - mn1) * SSC);
            sum0 += sacc[j][0] + sacc[j][1];
            sum1 += sacc[j][2] + sacc[j][3];
        }
        #pragma unroll
        for (int off = 1; off <= 2; off <<= 1) {
            sum0 += __shfl_xor_sync(0xffffffffu, sum0, off);
            sum1 += __shfl_xor_sync(0xffffffffu, sum1, off);
        }
        l0 = l0 * a0 + sum0;
        l1 = l1 * a1 + sum1;
        #pragma unroll
        for (int j = 0; j < 8; j++) {
            o[j][0] *= a0; o[j][1] *= a0;
            o[j][2] *= a1; o[j][3] *= a1;
        }

        // ---- O += P V  (single fp16 MMA) ----
        #pragma unroll
        for (int ks = 0; ks < 4; ks++) {
            uint32_t ap[4];
            ap[0] = pack2h(sacc[2 * ks][0],     sacc[2 * ks][1]);
            ap[1] = pack2h(sacc[2 * ks][2],     sacc[2 * ks][3]);
            ap[2] = pack2h(sacc[2 * ks + 1][0], sacc[2 * ks + 1][1]);
            ap[3] = pack2h(sacc[2 * ks + 1][2], sacc[2 * ks + 1][3]);
            const int vrow = ks * 16 + ((lane >> 3) & 1) * 8 + (lane & 7);
            #pragma unroll
            for (int np = 0; np < 4; np++) {
                uint32_t vf[4];
                uint32_t vo = SW128((uint32_t)(vrow * 128 + np * 32
                                               + (lane >> 4) * 16));
                ldsm4t(vf, s0 + 8192 + vo);
                mma_f16(o[np * 2],     ap, vf[0], vf[1]);
                mma_f16(o[np * 2 + 1], ap, vf[2], vf[3]);
            }
        }
    }

    // ---- epilogue ----
    const float inv0 = 1.f / l0, inv1 = 1.f / l1;
    const int s0r = m0 + wm + (lane >> 2);
    const size_t r0 = (size_t)b * SEQ + s0r;
    const size_t r1 = r0 + 8;
    #pragma unroll
    for (int f = 0; f < 8; f++) {
        const int col = hd * DK + f * 8 + 2 * (lane & 3);
        uint32_t ph, pl;
        pack_hl(o[f][0] * inv0, o[f][1] * inv0, ph, pl);
        *(uint32_t*)(Ohi + r0 * EMBED + col) = ph;
        *(uint32_t*)(Olo + r0 * EMBED + col) = pl;
        pack_hl(o[f][2] * inv1, o[f][3] * inv1, ph, pl);
        *(uint32_t*)(Ohi + r1 * EMBED + col) = ph;
        *(uint32_t*)(Olo + r1 * EMBED + col) = pl;
    }
}

// ---------------------------------------------------------------------------
// Launch
// ---------------------------------------------------------------------------
extern "C" void kernel_launch(void* const* d_in, const int* in_sizes, int n_in,
                              void* d_out, int out_size)
{
    const float* x   = (const float*)d_in[0];
    const float* Wq  = (const float*)d_in[1];
    const float* bq  = (const float*)d_in[2];
    const float* Wk  = (const float*)d_in[3];
    const float* bk  = (const float*)d_in[4];
    const float* Wv  = (const float*)d_in[5];
    const float* bv  = (const float*)d_in[6];
    const float* Wo  = (const float*)d_in[7];
    const float* bo  = (const float*)d_in[8];
    const float* W1  = (const float*)d_in[9];
    const float* b1  = (const float*)d_in[10];
    const float* W2  = (const float*)d_in[11];
    const float* b2  = (const float*)d_in[12];
    const float* g1  = (const float*)d_in[13];
    const float* be1 = (const float*)d_in[14];
    const float* g2  = (const float*)d_in[15];
    const float* be2 = (const float*)d_in[16];
    float* out = (float*)d_out;

    __nv_bfloat16 *h_hi, *h_lo, *ao_hi, *ao_lo;
    __nv_bfloat16 *h2_hi, *h2_lo, *f_hi, *f_lo;
    __nv_bfloat16 *wqkv_hi, *wqkv_lo, *wo_hi, *wo_lo, *w1_hi, *w1_lo, *w2_hi, *w2_lo;
    __half *qkv;
    float *x1, *bqkv;
    cudaGetSymbolAddress((void**)&h_hi,    g_h_hi);
    cudaGetSymbolAddress((void**)&h_lo,    g_h_lo);
    cudaGetSymbolAddress((void**)&qkv,     g_qkv);
    cudaGetSymbolAddress((void**)&ao_hi,   g_ao_hi);
    cudaGetSymbolAddress((void**)&ao_lo,   g_ao_lo);
    cudaGetSymbolAddress((void**)&x1,      g_x1);
    cudaGetSymbolAddress((void**)&h2_hi,   g_h2_hi);
    cudaGetSymbolAddress((void**)&h2_lo,   g_h2_lo);
    cudaGetSymbolAddress((void**)&f_hi,    g_f_hi);
    cudaGetSymbolAddress((void**)&f_lo,    g_f_lo);
    cudaGetSymbolAddress((void**)&wqkv_hi, g_wqkv_hi);
    cudaGetSymbolAddress((void**)&wqkv_lo, g_wqkv_lo);
    cudaGetSymbolAddress((void**)&wo_hi,   g_wo_hi);
    cudaGetSymbolAddress((void**)&wo_lo,   g_wo_lo);
    cudaGetSymbolAddress((void**)&w1_hi,   g_w1_hi);
    cudaGetSymbolAddress((void**)&w1_lo,   g_w1_lo);
    cudaGetSymbolAddress((void**)&w2_hi,   g_w2_hi);
    cudaGetSymbolAddress((void**)&w2_lo,   g_w2_lo);
    cudaGetSymbolAddress((void**)&bqkv,    g_bqkv);

    cudaFuncSetAttribute(gemm_mma<2>, cudaFuncAttributeMaxDynamicSharedMemorySize, SMEM_G);
    cudaFuncSetAttribute(gemm_mma<5>, cudaFuncAttributeMaxDynamicSharedMemorySize, SMEM_G);
    cudaFuncSetAttribute(gemm_mma<6>, cudaFuncAttributeMaxDynamicSharedMemorySize, SMEM_G);
    cudaFuncSetAttribute(attn_mma, cudaFuncAttributeMaxDynamicSharedMemorySize, SMEM_A);

    // bias concat (device-to-device, graph-capturable)
    cudaMemcpyAsync(bqkv,             bq, EMBED * sizeof(float), cudaMemcpyDeviceToDevice, 0);
    cudaMemcpyAsync(bqkv + EMBED,     bk, EMBED * sizeof(float), cudaMemcpyDeviceToDevice, 0);
    cudaMemcpyAsync(bqkv + 2 * EMBED, bv, EMBED * sizeof(float), cudaMemcpyDeviceToDevice, 0);

    // all weight splits in one kernel: 3M float4 elements
    cvt_all<<<(4 * NE4 + 2 * NF4) / 256, 256>>>(
        Wq, Wk, Wv, Wo, W1, W2,
        wqkv_hi, wqkv_lo, wo_hi, wo_lo, w1_hi, w1_lo, w2_hi, w2_lo);

    // LN1 -> (hi, lo)
    ln_kernel<<<MROWS, 256>>>(x, g1, be1, h_hi, h_lo);

    // Fused QKV projection -> q,k,v fp16 single, head layout
    {
        dim3 grid(3 * EMBED / CTN, MROWS / CTM);
        gemm_mma<6><<<grid, 256, SMEM_G>>>(h_hi, h_lo, wqkv_hi, wqkv_lo, bqkv,
                                           nullptr, nullptr, nullptr, nullptr, qkv,
                                           MROWS, 3 * EMBED, EMBED);
    }

    // Attention -> ao (hi, lo)
    {
        dim3 grid(SEQ / 128, HEADS, BATCH);
        attn_mma<<<grid, 256, SMEM_A>>>(qkv, qkv + HSZ, qkv + 2 * HSZ,
                                        ao_hi, ao_lo);
    }

    // O projection + residual: x1 = x + ao @ Wo^T + bo
    {
        dim3 grid(EMBED / CTN, MROWS / CTM);
        gemm_mma<2><<<grid, 256, SMEM_G>>>(ao_hi, ao_lo, wo_hi, wo_lo, bo, x,
                                           x1, nullptr, nullptr, nullptr,
                                           MROWS, EMBED, EMBED);
    }

    // LN2 -> (hi, lo)
    ln_kernel<<<MROWS, 256>>>(x1, g2, be2, h2_hi, h2_lo);

    // FFN1 + relu -> f (hi, lo)
    {
        dim3 grid(FFN / CTN, MROWS / CTM);
        gemm_mma<5><<<grid, 256, SMEM_G>>>(h2_hi, h2_lo, w1_hi, w1_lo, b1,
                                           nullptr, nullptr, f_hi, f_lo, nullptr,
                                           MROWS, FFN, EMBED);
    }

    // FFN2 + residual -> out
    {
        dim3 grid(EMBED / CTN, MROWS / CTM);
        gemm_mma<2><<<grid, 256, SMEM_G>>>(f_hi, f_lo, w2_hi, w2_lo, b2, x1,
                                           out, nullptr, nullptr, nullptr,
                                           MROWS, EMBED, FFN);
    }
}

// round 11
// speedup vs baseline: 1.3021x; 1.0775x over previous
#include <cuda_runtime.h>
#include <cuda_bf16.h>
#include <cuda_fp16.h>
#include <math.h>
#include <stdint.h>

// ---------------------------------------------------------------------------
// Problem constants
// ---------------------------------------------------------------------------
#define BATCH   2
#define SEQ     2048
#define EMBED   1024
#define HEADS   16
#define DK      64
#define FFN     4096
#define MROWS   (BATCH * SEQ)          // 4096
#define LN_EPS  1e-5f
#define SSC     0.1803368801111204f    // 0.125 * log2(e)
#define HSZ     (MROWS * EMBED)        // 4M elements

// GEMM tiling: CTA 128x128, K-chunk 32, 4 warps (warp tile 64x64)
#define CTM 128
#define CTN 128
#define KTC 32
#define STG 32768                      // Ah 8K + Al 8K + Bh 8K + Bl 8K
#define SMEM_G (3 * STG)               // 96 KB, 3-stage -> 2 CTA/SM

// Attention: Q 16K (fp16) + 3 stages x (K 8K + V 8K)
#define ASTG 16384
#define SMEM_A (16384 + 3 * ASTG)      // 64 KB -> 2 CTA/SM

#define SW128(o) ((o) ^ (((o) >> 3) & 0x70))
#define SW64(o)  ((o) ^ (((o) >> 3) & 0x30))

// ---------------------------------------------------------------------------
// Scratch buffers (allocation-free: __device__ globals)
// ---------------------------------------------------------------------------
__device__ __nv_bfloat16 g_h_hi [HSZ];
__device__ __nv_bfloat16 g_h_lo [HSZ];
__device__ __half        g_qkv  [3 * HSZ];   // q | k | v, fp16, [B,H,S,DK]
__device__ __nv_bfloat16 g_ao_hi[HSZ];
__device__ __nv_bfloat16 g_ao_lo[HSZ];
__device__ float         g_x1   [HSZ];
__device__ __nv_bfloat16 g_h2_hi[HSZ];
__device__ __nv_bfloat16 g_h2_lo[HSZ];
__device__ __nv_bfloat16 g_f_hi [MROWS * FFN];
__device__ __nv_bfloat16 g_f_lo [MROWS * FFN];

__device__ __nv_bfloat16 g_wqkv_hi[3 * EMBED * EMBED];  // Wq | Wk | Wv
__device__ __nv_bfloat16 g_wqkv_lo[3 * EMBED * EMBED];
__device__ __nv_bfloat16 g_wo_hi[EMBED * EMBED];
__device__ __nv_bfloat16 g_wo_lo[EMBED * EMBED];
__device__ __nv_bfloat16 g_w1_hi[FFN * EMBED];
__device__ __nv_bfloat16 g_w1_lo[FFN * EMBED];
__device__ __nv_bfloat16 g_w2_hi[EMBED * FFN];
__device__ __nv_bfloat16 g_w2_lo[EMBED * FFN];
__device__ float         g_bqkv[3 * EMBED];

// ---------------------------------------------------------------------------
// helpers
// ---------------------------------------------------------------------------
static __device__ __forceinline__ uint32_t s2u(const void* p) {
    uint32_t a;
    asm("{ .reg .u64 t; cvta.to.shared.u64 t, %1; cvt.u32.u64 %0, t; }"
        : "=r"(a) : "l"(p));
    return a;
}
static __device__ __forceinline__ void cpa16(uint32_t s, const void* g) {
    asm volatile("cp.async.cg.shared.global [%0], [%1], 16;"
                 :: "r"(s), "l"(g) : "memory");
}
static __device__ __forceinline__ void ldsm4(uint32_t* f, uint32_t a) {
    asm volatile("ldmatrix.sync.aligned.m8n8.x4.shared.b16 {%0,%1,%2,%3}, [%4];"
                 : "=r"(f[0]), "=r"(f[1]), "=r"(f[2]), "=r"(f[3]) : "r"(a));
}
static __device__ __forceinline__ void ldsm4t(uint32_t* f, uint32_t a) {
    asm volatile("ldmatrix.sync.aligned.m8n8.x4.trans.shared.b16 {%0,%1,%2,%3}, [%4];"
                 : "=r"(f[0]), "=r"(f[1]), "=r"(f[2]), "=r"(f[3]) : "r"(a));
}
static __device__ __forceinline__ void mma_bf16(float* c, const uint32_t* a,
                                                uint32_t b0, uint32_t b1) {
    asm volatile(
        "mma.sync.aligned.m16n8k16.row.col.f32.bf16.bf16.f32 "
        "{%0,%1,%2,%3}, {%4,%5,%6,%7}, {%8,%9}, {%0,%1,%2,%3};"
        : "+f"(c[0]), "+f"(c[1]), "+f"(c[2]), "+f"(c[3])
        : "r"(a[0]), "r"(a[1]), "r"(a[2]), "r"(a[3]), "r"(b0), "r"(b1));
}
static __device__ __forceinline__ void mma_f16(float* c, const uint32_t* a,
                                               uint32_t b0, uint32_t b1) {
    asm volatile(
        "mma.sync.aligned.m16n8k16.row.col.f32.f16.f16.f32 "
        "{%0,%1,%2,%3}, {%4,%5,%6,%7}, {%8,%9}, {%0,%1,%2,%3};"
        : "+f"(c[0]), "+f"(c[1]), "+f"(c[2]), "+f"(c[3])
        : "r"(a[0]), "r"(a[1]), "r"(a[2]), "r"(a[3]), "r"(b0), "r"(b1));
}
static __device__ __forceinline__ float ex2f(float x) {
    float y;
    asm("ex2.approx.f32 %0, %1;" : "=f"(y) : "f"(x));
    return y;
}
static __device__ __forceinline__ void split2(float v, __nv_bfloat16& h, __nv_bfloat16& l) {
    h = __float2bfloat16(v);
    l = __float2bfloat16(v - __bfloat162float(h));
}
static __device__ __forceinline__ void pack_hl(float x, float y,
                                               uint32_t& hi, uint32_t& lo) {
    __nv_bfloat16 hx, lx, hy, ly;
    split2(x, hx, lx);
    split2(y, hy, ly);
    __nv_bfloat162 H; H.x = hx; H.y = hy;
    __nv_bfloat162 L; L.x = lx; L.y = ly;
    hi = *(uint32_t*)&H;
    lo = *(uint32_t*)&L;
}
static __device__ __forceinline__ uint32_t pack2h(float x, float y) {
    __half2 h = __floats2half2_rn(x, y);
    return *(uint32_t*)&h;
}

// ---------------------------------------------------------------------------
// One-shot weight split (fp32 -> bf16 hi + bf16 lo), all matrices
// ---------------------------------------------------------------------------
#define NE4 (EMBED * EMBED / 4)       // 256K
#define NF4 (FFN * EMBED / 4)         // 1M
__global__ __launch_bounds__(256) void cvt_all(
    const float* __restrict__ wq, const float* __restrict__ wk,
    const float* __restrict__ wv, const float* __restrict__ wo,
    const float* __restrict__ w1, const float* __restrict__ w2,
    __nv_bfloat16* __restrict__ qkv_hi, __nv_bfloat16* __restrict__ qkv_lo,
    __nv_bfloat16* __restrict__ wo_hi,  __nv_bfloat16* __restrict__ wo_lo,
    __nv_bfloat16* __restrict__ w1_hi,  __nv_bfloat16* __restrict__ w1_lo,
    __nv_bfloat16* __restrict__ w2_hi,  __nv_bfloat16* __restrict__ w2_lo)
{
    int i = blockIdx.x * 256 + threadIdx.x;    // float4 index, < 3M
    const float* src;
    __nv_bfloat16 *dh, *dl;
    int j;
    if (i < 3 * NE4) {
        src = (i < NE4) ? wq : (i < 2 * NE4) ? wk : wv;
        j = (i < NE4) ? i : (i < 2 * NE4) ? i - NE4 : i - 2 * NE4;
        dh = qkv_hi + (size_t)(i - j) * 4; dl = qkv_lo + (size_t)(i - j) * 4;
    } else if (i < 4 * NE4) {
        src = wo; j = i - 3 * NE4; dh = wo_hi; dl = wo_lo;
    } else if (i < 4 * NE4 + NF4) {
        src = w1; j = i - 4 * NE4; dh = w1_hi; dl = w1_lo;
    } else {
        src = w2; j = i - 4 * NE4 - NF4; dh = w2_hi; dl = w2_lo;
    }
    float4 v = ((const float4*)src)[j];
    uint32_t h0, l0, h1, l1;
    pack_hl(v.x, v.y, h0, l0);
    pack_hl(v.z, v.w, h1, l1);
    uint2 H; H.x = h0; H.y = h1;
    uint2 L; L.x = l0; L.y = l1;
    ((uint2*)dh)[j] = H;
    ((uint2*)dl)[j] = L;
}

// ---------------------------------------------------------------------------
// LayerNorm: one block per row, writes (hi, lo) bf16
// ---------------------------------------------------------------------------
__global__ __launch_bounds__(256) void ln_kernel(
    const float* __restrict__ x, const float* __restrict__ g,
    const float* __restrict__ be, __nv_bfloat16* __restrict__ ohi,
    __nv_bfloat16* __restrict__ olo)
{
    const int N = EMBED;
    const size_t row = blockIdx.x;
    const float* xr = x + row * N;
    float s = 0.f, s2 = 0.f;
    #pragma unroll
    for (int i = threadIdx.x; i < N; i += 256) {
        float v = xr[i];
        s += v; s2 += v * v;
    }
    #pragma unroll
    for (int off = 16; off; off >>= 1) {
        s  += __shfl_xor_sync(0xffffffffu, s,  off);
        s2 += __shfl_xor_sync(0xffffffffu, s2, off);
    }
    __shared__ float red[16];
    __shared__ float mu_sh, rs_sh;
    int w = threadIdx.x >> 5, l = threadIdx.x & 31;
    if (l == 0) { red[w] = s; red[8 + w] = s2; }
    __syncthreads();
    if (threadIdx.x == 0) {
        float ts = 0.f, ts2 = 0.f;
        #pragma unroll
        for (int i = 0; i < 8; i++) { ts += red[i]; ts2 += red[8 + i]; }
        float mu  = ts / N;
        float var = ts2 / N - mu * mu;
        mu_sh = mu;
        rs_sh = rsqrtf(var + LN_EPS);
    }
    __syncthreads();
    float mu = mu_sh, rs = rs_sh;
    #pragma unroll
    for (int i = threadIdx.x; i < N; i += 256) {
        float y = (xr[i] - mu) * rs * g[i] + be[i];
        __nv_bfloat16 h, lo;
        split2(y, h, lo);
        ohi[row * N + i] = h;
        olo[row * N + i] = lo;
    }
}

// ---------------------------------------------------------------------------
// bf16-split GEMM: C[M,N] = A[M,K] @ W[N,K]^T (+bias,+relu,+res), 3 MMAs.
// CTA 128x128, 4 warps (warp tile 64x64), KTC 32 (SW64), 3-stage cp.async.
// 96 MMAs per 16 ldsm per k16-step (6:1 issue density).
// EPI: 2 = bias+res -> fp32; 5 = bias+relu -> (hi,lo) bf16;
//      6 = fused QKV (N=3072): q,k,v -> fp16 single, head layout
// ---------------------------------------------------------------------------
template <int EPI>
__global__ __launch_bounds__(128, 2) void gemm_mma(
    const __nv_bfloat16* __restrict__ Ah, const __nv_bfloat16* __restrict__ Al,
    const __nv_bfloat16* __restrict__ Bh, const __nv_bfloat16* __restrict__ Bl,
    const float* __restrict__ bias, const float* __restrict__ res,
    float* __restrict__ Cf, __nv_bfloat16* __restrict__ Chi,
    __nv_bfloat16* __restrict__ Clo, __half* __restrict__ Cq,
    int M, int N, int K)
{
    extern __shared__ char smem[];
    const uint32_t sb = s2u(smem);
    const int tid = threadIdx.x;
    const int lane = tid & 31, w = tid >> 5;
    const int bm = blockIdx.y * CTM, bn = blockIdx.x * CTN;
    const int wm = (w & 1) * 64, wn = (w >> 1) * 64;

    float acc[4][8][4];
    #pragma unroll
    for (int mt = 0; mt < 4; mt++)
        #pragma unroll
        for (int nt = 0; nt < 8; nt++)
            #pragma unroll
            for (int i = 0; i < 4; i++) acc[mt][nt][i] = 0.f;

    const int NC = K / KTC;

    auto load_chunk = [&](int c, int st) {
        const uint32_t s0 = sb + st * STG;
        const size_t k0 = (size_t)c * KTC;
        #pragma unroll
        for (int i = 0; i < 4; i++) {                 // A: 128 rows x 64B
            int idx = i * 128 + tid;
            int row = idx >> 2, c4 = idx & 3;
            uint32_t so = SW64((uint32_t)(row * 64 + c4 * 16));
            const size_t g = (size_t)(bm + row) * K + k0 + c4 * 8;
            cpa16(s0 + so,        Ah + g);
            cpa16(s0 + 8192 + so, Al + g);
        }
        #pragma unroll
        for (int i = 0; i < 4; i++) {                 // B: 128 rows x 64B
            int idx = i * 128 + tid;
            int row = idx >> 2, c4 = idx & 3;
            uint32_t so = SW64((uint32_t)(row * 64 + c4 * 16));
            const size_t g = (size_t)(bn + row) * K + k0 + c4 * 8;
            cpa16(s0 + 16384 + so, Bh + g);
            cpa16(s0 + 24576 + so, Bl + g);
        }
        asm volatile("cp.async.commit_group;" ::: "memory");
    };

    load_chunk(0, 0);
    load_chunk(1, 1);

    for (int c = 0; c < NC; c++) {
        if (c + 1 < NC) {
            asm volatile("cp.async.wait_group 1;" ::: "memory");
        } else {
            asm volatile("cp.async.wait_group 0;" ::: "memory");
        }
        __syncthreads();
        if (c + 2 < NC) load_chunk(c + 2, (c + 2) % 3);

        const uint32_t s0 = sb + (c % 3) * STG;
        #pragma unroll
        for (int ks = 0; ks < 2; ks++) {
            uint32_t ah[4][4], alr[4][4], bh[4][4], blr[4][4];
            const int arow = wm + (lane & 15);
            const int akb  = ks * 32 + (lane >> 4) * 16;
            #pragma unroll
            for (int mt = 0; mt < 4; mt++) {
                uint32_t ao = SW64((uint32_t)((arow + mt * 16) * 64 + akb));
                ldsm4(ah[mt],  s0 + ao);
                ldsm4(alr[mt], s0 + 8192 + ao);
            }
            const int brow = wn + ((lane >> 4) << 3) + (lane & 7);
            const int bkb  = ks * 32 + ((lane >> 3) & 1) * 16;
            #pragma unroll
            for (int np = 0; np < 4; np++) {
                uint32_t bo = SW64((uint32_t)((brow + np * 16) * 64 + bkb));
                ldsm4(bh[np],  s0 + 16384 + bo);
                ldsm4(blr[np], s0 + 24576 + bo);
            }
            #pragma unroll
            for (int mt = 0; mt < 4; mt++) {
                #pragma unroll
                for (int nt = 0; nt < 8; nt++) {
                    const int np = nt >> 1, ro = (nt & 1) * 2;
                    mma_bf16(acc[mt][nt], ah[mt],  bh[np][ro],  bh[np][ro + 1]);
                    mma_bf16(acc[mt][nt], ah[mt],  blr[np][ro], blr[np][ro + 1]);
                    mma_bf16(acc[mt][nt], alr[mt], bh[np][ro],  bh[np][ro + 1]);
                }
            }
        }
    }

    // ---- epilogue ----
    #pragma unroll
    for (int mt = 0; mt < 4; mt++) {
        #pragma unroll
        for (int nt = 0; nt < 8; nt++) {
            const int n = bn + wn + nt * 8 + (lane & 3) * 2;
            const float2 bs = *(const float2*)(bias + n);
            #pragma unroll
            for (int hh = 0; hh < 2; hh++) {
                const size_t m = (size_t)bm + wm + mt * 16 + (lane >> 2) + hh * 8;
                float v0 = acc[mt][nt][hh * 2]     + bs.x;
                float v1 = acc[mt][nt][hh * 2 + 1] + bs.y;
                if (EPI == 5) { v0 = fmaxf(v0, 0.f); v1 = fmaxf(v1, 0.f); }
                if (EPI == 2) {
                    float2 rr = *(const float2*)(res + m * N + n);
                    v0 += rr.x; v1 += rr.y;
                }
                if (EPI == 5) {
                    uint32_t ph, pl;
                    pack_hl(v0, v1, ph, pl);
                    *(uint32_t*)(Chi + m * N + n) = ph;
                    *(uint32_t*)(Clo + m * N + n) = pl;
                } else if (EPI == 6) {
                    const int which = n >> 10;
                    const int h_ = (n >> 6) & (HEADS - 1), d_ = n & 63;
                    const int b_ = (int)(m >> 11), s_ = (int)(m & 2047);
                    const size_t di = (size_t)which * HSZ
                        + (((size_t)b_ * HEADS + h_) * SEQ + s_) * DK + d_;
                    *(uint32_t*)(Cq + di) = pack2h(v0, v1);
                } else {
                    float2 o; o.x = v0; o.y = v1;
                    *(float2*)(Cf + m * N + n) = o;
                }
            }
        }
    }
}

// ---------------------------------------------------------------------------
// Flash attention: QK^T and PV both single fp16 (1 MMA each).
// grid = (SEQ/128, HEADS, BATCH), 256 threads (8 warps, 16 q rows each).
// Smem: Q 16K (fp16) + 3-stage ring of (K 8K | V 8K). 64 KB -> 2 CTA/SM.
// Output ao written bf16 (hi,lo) = exact, for split O-projection.
// ---------------------------------------------------------------------------
__global__ __launch_bounds__(256, 2) void attn_mma(
    const __half* __restrict__ Q, const __half* __restrict__ K,
    const __half* __restrict__ V,
    __nv_bfloat16* __restrict__ Ohi, __nv_bfloat16* __restrict__ Olo)
{
    extern __shared__ char smem[];
    const uint32_t sb  = s2u(smem);
    const uint32_t sKV = sb + 16384;
    const int tid = threadIdx.x, lane = tid & 31, w = tid >> 5;
    const int qt = blockIdx.x, hd = blockIdx.y, b = blockIdx.z;
    const size_t hb = ((size_t)b * HEADS + hd) * SEQ * DK;
    const int m0 = qt * 128;
    const int wm = w * 16;

    // Q load: 128 rows x 128B = 16 KB (own cp.async group)
    #pragma unroll
    for (int i = 0; i < 4; i++) {
        int idx = i * 256 + tid;
        int row = idx >> 3, c16 = idx & 7;
        uint32_t so = SW128((uint32_t)(row * 128 + c16 * 16));
        cpa16(sb + so, Q + hb + (size_t)(m0 + row) * DK + c16 * 8);
    }
    asm volatile("cp.async.commit_group;" ::: "memory");

    auto load_kv = [&](int c, int st) {
        const uint32_t s0 = sKV + st * ASTG;
        const int k0 = c * 64;
        #pragma unroll
        for (int i = 0; i < 2; i++) {
            int idx = i * 256 + tid;
            int row = idx >> 3, c16 = idx & 7;
            uint32_t so = SW128((uint32_t)(row * 128 + c16 * 16));
            const size_t g = hb + (size_t)(k0 + row) * DK + c16 * 8;
            cpa16(s0 + so,        K + g);
            cpa16(s0 + 8192 + so, V + g);
        }
        asm volatile("cp.async.commit_group;" ::: "memory");
    };
    load_kv(0, 0);
    load_kv(1, 1);

    // wait for Q (2 kv groups still outstanding), park in registers
    asm volatile("cp.async.wait_group 2;" ::: "memory");
    __syncthreads();
    uint32_t qf[4][4];
    #pragma unroll
    for (int ks = 0; ks < 4; ks++) {
        uint32_t ao = SW128((uint32_t)((wm + (lane & 15)) * 128
                                       + ks * 32 + (lane >> 4) * 16));
        ldsm4(qf[ks], sb + ao);
    }

    float o[8][4];
    #pragma unroll
    for (int j = 0; j < 8; j++)
        #pragma unroll
        for (int i = 0; i < 4; i++) o[j][i] = 0.f;
    float mr0 = -1e30f, mr1 = -1e30f, l0 = 0.f, l1 = 0.f;

    const int NC = SEQ / 64;
    for (int c = 0; c < NC; c++) {
        if (c + 1 < NC) {
            asm volatile("cp.async.wait_group 1;" ::: "memory");
        } else {
            asm volatile("cp.async.wait_group 0;" ::: "memory");
        }
        __syncthreads();
        if (c + 2 < NC) load_kv(c + 2, (c + 2) % 3);
        const uint32_t s0 = sKV + (c % 3) * ASTG;

        // ---- S = Q K^T  (single fp16 MMA) ----
        float sacc[8][4];
        #pragma unroll
        for (int j = 0; j < 8; j++)
            #pragma unroll
            for (int i = 0; i < 4; i++) sacc[j][i] = 0.f;

        #pragma unroll
        for (int ks = 0; ks < 4; ks++) {
            const int brow = ((lane >> 4) << 3) + (lane & 7);
            const int bkb  = ks * 32 + ((lane >> 3) & 1) * 16;
            #pragma unroll
            for (int np = 0; np < 4; np++) {
                uint32_t kf[4];
                uint32_t bo = SW128((uint32_t)((brow + np * 16) * 128 + bkb));
                ldsm4(kf, s0 + bo);
                mma_f16(sacc[np * 2],     qf[ks], kf[0], kf[1]);
                mma_f16(sacc[np * 2 + 1], qf[ks], kf[2], kf[3]);
            }
        }

        // ---- online softmax ----
        float cm0 = -1e30f, cm1 = -1e30f;
        #pragma unroll
        for (int j = 0; j < 8; j++) {
            cm0 = fmaxf(cm0, fmaxf(sacc[j][0], sacc[j][1]));
            cm1 = fmaxf(cm1, fmaxf(sacc[j][2], sacc[j][3]));
        }
        #pragma unroll
        for (int off = 1; off <= 2; off <<= 1) {
            cm0 = fmaxf(cm0, __shfl_xor_sync(0xffffffffu, cm0, off));
            cm1 = fmaxf(cm1, __shfl_xor_sync(0xffffffffu, cm1, off));
        }
        const float mn0 = fmaxf(mr0, cm0), mn1 = fmaxf(mr1, cm1);
        const float a0 = ex2f((mr0 - mn0) * SSC);
        const float a1 = ex2f((mr1 - mn1) * SSC);
        mr0 = mn0; mr1 = mn1;
        float sum0 = 0.f, sum1 = 0.f;
        #pragma unroll
        for (int j = 0; j < 8; j++) {
            sacc[j][0] = ex2f((sacc[j][0] - mn0) * SSC);
            sacc[j][1] = ex2f((sacc[j][1] - mn0) * SSC);
            sacc[j][2] = ex2f((sacc[j][2] - mn1) * SSC);
            sacc[j][3] = ex2f((sacc[j][3] - mn1) * SSC);
            sum0 += sacc[j][0] + sacc[j][1];
            sum1 += sacc[j][2] + sacc[j][3];
        }
        #pragma unroll
        for (int off = 1; off <= 2; off <<= 1) {
            sum0 += __shfl_xor_sync(0xffffffffu, sum0, off);
            sum1 += __shfl_xor_sync(0xffffffffu, sum1, off);
        }
        l0 = l0 * a0 + sum0;
        l1 = l1 * a1 + sum1;
        #pragma unroll
        for (int j = 0; j < 8; j++) {
            o[j][0] *= a0; o[j][1] *= a0;
            o[j][2] *= a1; o[j][3] *= a1;
        }

        // ---- O += P V  (single fp16 MMA) ----
        #pragma unroll
        for (int ks = 0; ks < 4; ks++) {
            uint32_t ap[4];
            ap[0] = pack2h(sacc[2 * ks][0],     sacc[2 * ks][1]);
            ap[1] = pack2h(sacc[2 * ks][2],     sacc[2 * ks][3]);
            ap[2] = pack2h(sacc[2 * ks + 1][0], sacc[2 * ks + 1][1]);
            ap[3] = pack2h(sacc[2 * ks + 1][2], sacc[2 * ks + 1][3]);
            const int vrow = ks * 16 + ((lane >> 3) & 1) * 8 + (lane & 7);
            #pragma unroll
            for (int np = 0; np < 4; np++) {
                uint32_t vf[4];
                uint32_t vo = SW128((uint32_t)(vrow * 128 + np * 32
                                               + (lane >> 4) * 16));
                ldsm4t(vf, s0 + 8192 + vo);
                mma_f16(o[np * 2],     ap, vf[0], vf[1]);
                mma_f16(o[np * 2 + 1], ap, vf[2], vf[3]);
            }
        }
    }

    // ---- epilogue ----
    const float inv0 = 1.f / l0, inv1 = 1.f / l1;
    const int s0r = m0 + wm + (lane >> 2);
    const size_t r0 = (size_t)b * SEQ + s0r;
    const size_t r1 = r0 + 8;
    #pragma unroll
    for (int f = 0; f < 8; f++) {
        const int col = hd * DK + f * 8 + 2 * (lane & 3);
        uint32_t ph, pl;
        pack_hl(o[f][0] * inv0, o[f][1] * inv0, ph, pl);
        *(uint32_t*)(Ohi + r0 * EMBED + col) = ph;
        *(uint32_t*)(Olo + r0 * EMBED + col) = pl;
        pack_hl(o[f][2] * inv1, o[f][3] * inv1, ph, pl);
        *(uint32_t*)(Ohi + r1 * EMBED + col) = ph;
        *(uint32_t*)(Olo + r1 * EMBED + col) = pl;
    }
}

// ---------------------------------------------------------------------------
// Launch
// ---------------------------------------------------------------------------
extern "C" void kernel_launch(void* const* d_in, const int* in_sizes, int n_in,
                              void* d_out, int out_size)
{
    const float* x   = (const float*)d_in[0];
    const float* Wq  = (const float*)d_in[1];
    const float* bq  = (const float*)d_in[2];
    const float* Wk  = (const float*)d_in[3];
    const float* bk  = (const float*)d_in[4];
    const float* Wv  = (const float*)d_in[5];
    const float* bv  = (const float*)d_in[6];
    const float* Wo  = (const float*)d_in[7];
    const float* bo  = (const float*)d_in[8];
    const float* W1  = (const float*)d_in[9];
    const float* b1  = (const float*)d_in[10];
    const float* W2  = (const float*)d_in[11];
    const float* b2  = (const float*)d_in[12];
    const float* g1  = (const float*)d_in[13];
    const float* be1 = (const float*)d_in[14];
    const float* g2  = (const float*)d_in[15];
    const float* be2 = (const float*)d_in[16];
    float* out = (float*)d_out;

    __nv_bfloat16 *h_hi, *h_lo, *ao_hi, *ao_lo;
    __nv_bfloat16 *h2_hi, *h2_lo, *f_hi, *f_lo;
    __nv_bfloat16 *wqkv_hi, *wqkv_lo, *wo_hi, *wo_lo, *w1_hi, *w1_lo, *w2_hi, *w2_lo;
    __half *qkv;
    float *x1, *bqkv;
    cudaGetSymbolAddress((void**)&h_hi,    g_h_hi);
    cudaGetSymbolAddress((void**)&h_lo,    g_h_lo);
    cudaGetSymbolAddress((void**)&qkv,     g_qkv);
    cudaGetSymbolAddress((void**)&ao_hi,   g_ao_hi);
    cudaGetSymbolAddress((void**)&ao_lo,   g_ao_lo);
    cudaGetSymbolAddress((void**)&x1,      g_x1);
    cudaGetSymbolAddress((void**)&h2_hi,   g_h2_hi);
    cudaGetSymbolAddress((void**)&h2_lo,   g_h2_lo);
    cudaGetSymbolAddress((void**)&f_hi,    g_f_hi);
    cudaGetSymbolAddress((void**)&f_lo,    g_f_lo);
    cudaGetSymbolAddress((void**)&wqkv_hi, g_wqkv_hi);
    cudaGetSymbolAddress((void**)&wqkv_lo, g_wqkv_lo);
    cudaGetSymbolAddress((void**)&wo_hi,   g_wo_hi);
    cudaGetSymbolAddress((void**)&wo_lo,   g_wo_lo);
    cudaGetSymbolAddress((void**)&w1_hi,   g_w1_hi);
    cudaGetSymbolAddress((void**)&w1_lo,   g_w1_lo);
    cudaGetSymbolAddress((void**)&w2_hi,   g_w2_hi);
    cudaGetSymbolAddress((void**)&w2_lo,   g_w2_lo);
    cudaGetSymbolAddress((void**)&bqkv,    g_bqkv);

    cudaFuncSetAttribute(gemm_mma<2>, cudaFuncAttributeMaxDynamicSharedMemorySize, SMEM_G);
    cudaFuncSetAttribute(gemm_mma<5>, cudaFuncAttributeMaxDynamicSharedMemorySize, SMEM_G);
    cudaFuncSetAttribute(gemm_mma<6>, cudaFuncAttributeMaxDynamicSharedMemorySize, SMEM_G);
    cudaFuncSetAttribute(attn_mma, cudaFuncAttributeMaxDynamicSharedMemorySize, SMEM_A);

    // bias concat (device-to-device, graph-capturable)
    cudaMemcpyAsync(bqkv,             bq, EMBED * sizeof(float), cudaMemcpyDeviceToDevice, 0);
    cudaMemcpyAsync(bqkv + EMBED,     bk, EMBED * sizeof(float), cudaMemcpyDeviceToDevice, 0);
    cudaMemcpyAsync(bqkv + 2 * EMBED, bv, EMBED * sizeof(float), cudaMemcpyDeviceToDevice, 0);

    // all weight splits in one kernel: 3M float4 elements
    cvt_all<<<(4 * NE4 + 2 * NF4) / 256, 256>>>(
        Wq, Wk, Wv, Wo, W1, W2,
        wqkv_hi, wqkv_lo, wo_hi, wo_lo, w1_hi, w1_lo, w2_hi, w2_lo);

    // LN1 -> (hi, lo)
    ln_kernel<<<MROWS, 256>>>(x, g1, be1, h_hi, h_lo);

    // Fused QKV projection -> q,k,v fp16 single, head layout
    {
        dim3 grid(3 * EMBED / CTN, MROWS / CTM);
        gemm_mma<6><<<grid, 128, SMEM_G>>>(h_hi, h_lo, wqkv_hi, wqkv_lo, bqkv,
                                           nullptr, nullptr, nullptr, nullptr, qkv,
                                           MROWS, 3 * EMBED, EMBED);
    }

    // Attention -> ao (hi, lo)
    {
        dim3 grid(SEQ / 128, HEADS, BATCH);
        attn_mma<<<grid, 256, SMEM_A>>>(qkv, qkv + HSZ, qkv + 2 * HSZ,
                                        ao_hi, ao_lo);
    }

    // O projection + residual: x1 = x + ao @ Wo^T + bo
    {
        dim3 grid(EMBED / CTN, MROWS / CTM);
        gemm_mma<2><<<grid, 128, SMEM_G>>>(ao_hi, ao_lo, wo_hi, wo_lo, bo, x,
                                           x1, nullptr, nullptr, nullptr,
                                           MROWS, EMBED, EMBED);
    }

    // LN2 -> (hi, lo)
    ln_kernel<<<MROWS, 256>>>(x1, g2, be2, h2_hi, h2_lo);

    // FFN1 + relu -> f (hi, lo)
    {
        dim3 grid(FFN / CTN, MROWS / CTM);
        gemm_mma<5><<<grid, 128, SMEM_G>>>(h2_hi, h2_lo, w1_hi, w1_lo, b1,
                                           nullptr, nullptr, f_hi, f_lo, nullptr,
                                           MROWS, FFN, EMBED);
    }

    // FFN2 + residual -> out
    {
        dim3 grid(EMBED / CTN, MROWS / CTM);
        gemm_mma<2><<<grid, 128, SMEM_G>>>(f_hi, f_lo, w2_hi, w2_lo, b2, x1,
                                           out, nullptr, nullptr, nullptr,
                                           MROWS, EMBED, FFN);
    }
}

// round 12
// speedup vs baseline: 1.3278x; 1.0197x over previous
#include <cuda_runtime.h>
#include <cuda_bf16.h>
#include <cuda_fp16.h>
#include <math.h>
#include <stdint.h>

// ---------------------------------------------------------------------------
// Problem constants
// ---------------------------------------------------------------------------
#define BATCH   2
#define SEQ     2048
#define EMBED   1024
#define HEADS   16
#define DK      64
#define FFN     4096
#define MROWS   (BATCH * SEQ)          // 4096
#define LN_EPS  1e-5f
#define SSC     0.1803368801111204f    // 0.125 * log2(e)
#define HSZ     (MROWS * EMBED)        // 4M elements

// GEMM tiling: CTA 128x128, K-chunk 32, 4 warps (warp tile 64x64)
#define CTM 128
#define CTN 128
#define KTC 32
#define STG 32768                      // Ah 8K + Al 8K + Bh 8K + Bl 8K
#define SMEM_G (3 * STG)               // 96 KB, 3-stage -> 2 CTA/SM

// Attention: Q 16K (fp16) + 3 stages x (K 8K + V 8K)
#define ASTG 16384
#define SMEM_A (16384 + 3 * ASTG)      // 64 KB -> 2 CTA/SM

#define SW128(o) ((o) ^ (((o) >> 3) & 0x70))
#define SW64(o)  ((o) ^ (((o) >> 3) & 0x30))

// ---------------------------------------------------------------------------
// Scratch buffers (allocation-free: __device__ globals)
// ---------------------------------------------------------------------------
__device__ __nv_bfloat16 g_h_hi [HSZ];
__device__ __nv_bfloat16 g_h_lo [HSZ];
__device__ __half        g_qkv  [3 * HSZ];   // q | k | v, fp16, [B,H,S,DK]
__device__ __nv_bfloat16 g_ao_hi[HSZ];
__device__ __nv_bfloat16 g_ao_lo[HSZ];
__device__ float         g_x1   [HSZ];
__device__ __nv_bfloat16 g_h2_hi[HSZ];
__device__ __nv_bfloat16 g_h2_lo[HSZ];
__device__ __nv_bfloat16 g_f_hi [MROWS * FFN];
__device__ __nv_bfloat16 g_f_lo [MROWS * FFN];

__device__ __nv_bfloat16 g_wqkv_hi[3 * EMBED * EMBED];  // Wq | Wk | Wv
__device__ __nv_bfloat16 g_wqkv_lo[3 * EMBED * EMBED];
__device__ __nv_bfloat16 g_wo_hi[EMBED * EMBED];
__device__ __nv_bfloat16 g_wo_lo[EMBED * EMBED];
__device__ __nv_bfloat16 g_w1_hi[FFN * EMBED];
__device__ __nv_bfloat16 g_w1_lo[FFN * EMBED];
__device__ __nv_bfloat16 g_w2_hi[EMBED * FFN];
__device__ __nv_bfloat16 g_w2_lo[EMBED * FFN];
__device__ float         g_bqkv[3 * EMBED];

// ---------------------------------------------------------------------------
// helpers
// ---------------------------------------------------------------------------
static __device__ __forceinline__ uint32_t s2u(const void* p) {
    uint32_t a;
    asm("{ .reg .u64 t; cvta.to.shared.u64 t, %1; cvt.u32.u64 %0, t; }"
        : "=r"(a) : "l"(p));
    return a;
}
static __device__ __forceinline__ void cpa16(uint32_t s, const void* g) {
    asm volatile("cp.async.cg.shared.global [%0], [%1], 16;"
                 :: "r"(s), "l"(g) : "memory");
}
static __device__ __forceinline__ void ldsm4(uint32_t* f, uint32_t a) {
    asm volatile("ldmatrix.sync.aligned.m8n8.x4.shared.b16 {%0,%1,%2,%3}, [%4];"
                 : "=r"(f[0]), "=r"(f[1]), "=r"(f[2]), "=r"(f[3]) : "r"(a));
}
static __device__ __forceinline__ void ldsm4t(uint32_t* f, uint32_t a) {
    asm volatile("ldmatrix.sync.aligned.m8n8.x4.trans.shared.b16 {%0,%1,%2,%3}, [%4];"
                 : "=r"(f[0]), "=r"(f[1]), "=r"(f[2]), "=r"(f[3]) : "r"(a));
}
static __device__ __forceinline__ void mma_bf16(float* c, const uint32_t* a,
                                                uint32_t b0, uint32_t b1) {
    asm volatile(
        "mma.sync.aligned.m16n8k16.row.col.f32.bf16.bf16.f32 "
        "{%0,%1,%2,%3}, {%4,%5,%6,%7}, {%8,%9}, {%0,%1,%2,%3};"
        : "+f"(c[0]), "+f"(c[1]), "+f"(c[2]), "+f"(c[3])
        : "r"(a[0]), "r"(a[1]), "r"(a[2]), "r"(a[3]), "r"(b0), "r"(b1));
}
static __device__ __forceinline__ void mma_f16(float* c, const uint32_t* a,
                                               uint32_t b0, uint32_t b1) {
    asm volatile(
        "mma.sync.aligned.m16n8k16.row.col.f32.f16.f16.f32 "
        "{%0,%1,%2,%3}, {%4,%5,%6,%7}, {%8,%9}, {%0,%1,%2,%3};"
        : "+f"(c[0]), "+f"(c[1]), "+f"(c[2]), "+f"(c[3])
        : "r"(a[0]), "r"(a[1]), "r"(a[2]), "r"(a[3]), "r"(b0), "r"(b1));
}
static __device__ __forceinline__ float ex2f(float x) {
    float y;
    asm("ex2.approx.f32 %0, %1;" : "=f"(y) : "f"(x));
    return y;
}
static __device__ __forceinline__ uint32_t ex2h2(uint32_t a) {
    asm("ex2.approx.f16x2 %0, %0;" : "+r"(a));
    return a;
}
static __device__ __forceinline__ uint32_t hadd2u(uint32_t a, uint32_t b) {
    uint32_t d;
    asm("add.f16x2 %0, %1, %2;" : "=r"(d) : "r"(a), "r"(b));
    return d;
}
static __device__ __forceinline__ void split2(float v, __nv_bfloat16& h, __nv_bfloat16& l) {
    h = __float2bfloat16(v);
    l = __float2bfloat16(v - __bfloat162float(h));
}
static __device__ __forceinline__ void pack_hl(float x, float y,
                                               uint32_t& hi, uint32_t& lo) {
    __nv_bfloat16 hx, lx, hy, ly;
    split2(x, hx, lx);
    split2(y, hy, ly);
    __nv_bfloat162 H; H.x = hx; H.y = hy;
    __nv_bfloat162 L; L.x = lx; L.y = ly;
    hi = *(uint32_t*)&H;
    lo = *(uint32_t*)&L;
}
static __device__ __forceinline__ uint32_t pack2h(float x, float y) {
    __half2 h = __floats2half2_rn(x, y);
    return *(uint32_t*)&h;
}

// ---------------------------------------------------------------------------
// One-shot weight split (fp32 -> bf16 hi + bf16 lo) + fused bias concat.
// ---------------------------------------------------------------------------
#define NE4 (EMBED * EMBED / 4)       // 256K
#define NF4 (FFN * EMBED / 4)         // 1M
#define WT4 (4 * NE4 + 2 * NF4)       // weight float4 count (3M)
__global__ __launch_bounds__(256) void cvt_all(
    const float* __restrict__ wq, const float* __restrict__ wk,
    const float* __restrict__ wv, const float* __restrict__ wo,
    const float* __restrict__ w1, const float* __restrict__ w2,
    const float* __restrict__ bq, const float* __restrict__ bk,
    const float* __restrict__ bv, float* __restrict__ bqkv,
    __nv_bfloat16* __restrict__ qkv_hi, __nv_bfloat16* __restrict__ qkv_lo,
    __nv_bfloat16* __restrict__ wo_hi,  __nv_bfloat16* __restrict__ wo_lo,
    __nv_bfloat16* __restrict__ w1_hi,  __nv_bfloat16* __restrict__ w1_lo,
    __nv_bfloat16* __restrict__ w2_hi,  __nv_bfloat16* __restrict__ w2_lo)
{
    int i = blockIdx.x * 256 + threadIdx.x;    // float4 index
    if (i >= WT4) {                            // bias concat tail: 768 float4
        int j = i - WT4;
        if (j < 768) {
            const float* bs = (j < 256) ? bq : (j < 512) ? bk : bv;
            int jj = (j < 256) ? j : (j < 512) ? j - 256 : j - 512;
            ((float4*)bqkv)[j] = ((const float4*)bs)[jj];
        }
        return;
    }
    const float* src;
    __nv_bfloat16 *dh, *dl;
    int j;
    if (i < 3 * NE4) {
        src = (i < NE4) ? wq : (i < 2 * NE4) ? wk : wv;
        j = (i < NE4) ? i : (i < 2 * NE4) ? i - NE4 : i - 2 * NE4;
        dh = qkv_hi + (size_t)(i - j) * 4; dl = qkv_lo + (size_t)(i - j) * 4;
    } else if (i < 4 * NE4) {
        src = wo; j = i - 3 * NE4; dh = wo_hi; dl = wo_lo;
    } else if (i < 4 * NE4 + NF4) {
        src = w1; j = i - 4 * NE4; dh = w1_hi; dl = w1_lo;
    } else {
        src = w2; j = i - 4 * NE4 - NF4; dh = w2_hi; dl = w2_lo;
    }
    float4 v = ((const float4*)src)[j];
    uint32_t h0, l0, h1, l1;
    pack_hl(v.x, v.y, h0, l0);
    pack_hl(v.z, v.w, h1, l1);
    uint2 H; H.x = h0; H.y = h1;
    uint2 L; L.x = l0; L.y = l1;
    ((uint2*)dh)[j] = H;
    ((uint2*)dl)[j] = L;
}

// ---------------------------------------------------------------------------
// LayerNorm: one block per row, writes (hi, lo) bf16
// ---------------------------------------------------------------------------
__global__ __launch_bounds__(256) void ln_kernel(
    const float* __restrict__ x, const float* __restrict__ g,
    const float* __restrict__ be, __nv_bfloat16* __restrict__ ohi,
    __nv_bfloat16* __restrict__ olo)
{
    const int N = EMBED;
    const size_t row = blockIdx.x;
    const float* xr = x + row * N;
    float s = 0.f, s2 = 0.f;
    #pragma unroll
    for (int i = threadIdx.x; i < N; i += 256) {
        float v = xr[i];
        s += v; s2 += v * v;
    }
    #pragma unroll
    for (int off = 16; off; off >>= 1) {
        s  += __shfl_xor_sync(0xffffffffu, s,  off);
        s2 += __shfl_xor_sync(0xffffffffu, s2, off);
    }
    __shared__ float red[16];
    __shared__ float mu_sh, rs_sh;
    int w = threadIdx.x >> 5, l = threadIdx.x & 31;
    if (l == 0) { red[w] = s; red[8 + w] = s2; }
    __syncthreads();
    if (threadIdx.x == 0) {
        float ts = 0.f, ts2 = 0.f;
        #pragma unroll
        for (int i = 0; i < 8; i++) { ts += red[i]; ts2 += red[8 + i]; }
        float mu  = ts / N;
        float var = ts2 / N - mu * mu;
        mu_sh = mu;
        rs_sh = rsqrtf(var + LN_EPS);
    }
    __syncthreads();
    float mu = mu_sh, rs = rs_sh;
    #pragma unroll
    for (int i = threadIdx.x; i < N; i += 256) {
        float y = (xr[i] - mu) * rs * g[i] + be[i];
        __nv_bfloat16 h, lo;
        split2(y, h, lo);
        ohi[row * N + i] = h;
        olo[row * N + i] = lo;
    }
}

// ---------------------------------------------------------------------------
// bf16-split GEMM: C[M,N] = A[M,K] @ W[N,K]^T (+bias,+relu,+res), 3 MMAs.
// CTA 128x128, 4 warps (warp tile 64x64), KTC 32 (SW64), 3-stage cp.async.
// EPI: 2 = bias+res -> fp32; 5 = bias+relu -> (hi,lo) bf16;
//      6 = fused QKV (N=3072): q,k,v -> fp16 single, head layout
// ---------------------------------------------------------------------------
template <int EPI>
__global__ __launch_bounds__(128, 2) void gemm_mma(
    const __nv_bfloat16* __restrict__ Ah, const __nv_bfloat16* __restrict__ Al,
    const __nv_bfloat16* __restrict__ Bh, const __nv_bfloat16* __restrict__ Bl,
    const float* __restrict__ bias, const float* __restrict__ res,
    float* __restrict__ Cf, __nv_bfloat16* __restrict__ Chi,
    __nv_bfloat16* __restrict__ Clo, __half* __restrict__ Cq,
    int M, int N, int K)
{
    extern __shared__ char smem[];
    const uint32_t sb = s2u(smem);
    const int tid = threadIdx.x;
    const int lane = tid & 31, w = tid >> 5;
    const int bm = blockIdx.y * CTM, bn = blockIdx.x * CTN;
    const int wm = (w & 1) * 64, wn = (w >> 1) * 64;

    float acc[4][8][4];
    #pragma unroll
    for (int mt = 0; mt < 4; mt++)
        #pragma unroll
        for (int nt = 0; nt < 8; nt++)
            #pragma unroll
            for (int i = 0; i < 4; i++) acc[mt][nt][i] = 0.f;

    const int NC = K / KTC;

    auto load_chunk = [&](int c, int st) {
        const uint32_t s0 = sb + st * STG;
        const size_t k0 = (size_t)c * KTC;
        #pragma unroll
        for (int i = 0; i < 4; i++) {                 // A: 128 rows x 64B
            int idx = i * 128 + tid;
            int row = idx >> 2, c4 = idx & 3;
            uint32_t so = SW64((uint32_t)(row * 64 + c4 * 16));
            const size_t g = (size_t)(bm + row) * K + k0 + c4 * 8;
            cpa16(s0 + so,        Ah + g);
            cpa16(s0 + 8192 + so, Al + g);
        }
        #pragma unroll
        for (int i = 0; i < 4; i++) {                 // B: 128 rows x 64B
            int idx = i * 128 + tid;
            int row = idx >> 2, c4 = idx & 3;
            uint32_t so = SW64((uint32_t)(row * 64 + c4 * 16));
            const size_t g = (size_t)(bn + row) * K + k0 + c4 * 8;
            cpa16(s0 + 16384 + so, Bh + g);
            cpa16(s0 + 24576 + so, Bl + g);
        }
        asm volatile("cp.async.commit_group;" ::: "memory");
    };

    load_chunk(0, 0);
    load_chunk(1, 1);

    for (int c = 0; c < NC; c++) {
        if (c + 1 < NC) {
            asm volatile("cp.async.wait_group 1;" ::: "memory");
        } else {
            asm volatile("cp.async.wait_group 0;" ::: "memory");
        }
        __syncthreads();
        if (c + 2 < NC) load_chunk(c + 2, (c + 2) % 3);

        const uint32_t s0 = sb + (c % 3) * STG;
        #pragma unroll
        for (int ks = 0; ks < 2; ks++) {
            uint32_t ah[4][4], alr[4][4], bh[4][4], blr[4][4];
            const int arow = wm + (lane & 15);
            const int akb  = ks * 32 + (lane >> 4) * 16;
            #pragma unroll
            for (int mt = 0; mt < 4; mt++) {
                uint32_t ao = SW64((uint32_t)((arow + mt * 16) * 64 + akb));
                ldsm4(ah[mt],  s0 + ao);
                ldsm4(alr[mt], s0 + 8192 + ao);
            }
            const int brow = wn + ((lane >> 4) << 3) + (lane & 7);
            const int bkb  = ks * 32 + ((lane >> 3) & 1) * 16;
            #pragma unroll
            for (int np = 0; np < 4; np++) {
                uint32_t bo = SW64((uint32_t)((brow + np * 16) * 64 + bkb));
                ldsm4(bh[np],  s0 + 16384 + bo);
                ldsm4(blr[np], s0 + 24576 + bo);
            }
            #pragma unroll
            for (int mt = 0; mt < 4; mt++) {
                #pragma unroll
                for (int nt = 0; nt < 8; nt++) {
                    const int np = nt >> 1, ro = (nt & 1) * 2;
                    mma_bf16(acc[mt][nt], ah[mt],  bh[np][ro],  bh[np][ro + 1]);
                    mma_bf16(acc[mt][nt], ah[mt],  blr[np][ro], blr[np][ro + 1]);
                    mma_bf16(acc[mt][nt], alr[mt], bh[np][ro],  bh[np][ro + 1]);
                }
            }
        }
    }

    // ---- epilogue ----
    #pragma unroll
    for (int mt = 0; mt < 4; mt++) {
        #pragma unroll
        for (int nt = 0; nt < 8; nt++) {
            const int n = bn + wn + nt * 8 + (lane & 3) * 2;
            const float2 bs = *(const float2*)(bias + n);
            #pragma unroll
            for (int hh = 0; hh < 2; hh++) {
                const size_t m = (size_t)bm + wm + mt * 16 + (lane >> 2) + hh * 8;
                float v0 = acc[mt][nt][hh * 2]     + bs.x;
                float v1 = acc[mt][nt][hh * 2 + 1] + bs.y;
                if (EPI == 5) { v0 = fmaxf(v0, 0.f); v1 = fmaxf(v1, 0.f); }
                if (EPI == 2) {
                    float2 rr = *(const float2*)(res + m * N + n);
                    v0 += rr.x; v1 += rr.y;
                }
                if (EPI == 5) {
                    uint32_t ph, pl;
                    pack_hl(v0, v1, ph, pl);
                    *(uint32_t*)(Chi + m * N + n) = ph;
                    *(uint32_t*)(Clo + m * N + n) = pl;
                } else if (EPI == 6) {
                    const int which = n >> 10;
                    const int h_ = (n >> 6) & (HEADS - 1), d_ = n & 63;
                    const int b_ = (int)(m >> 11), s_ = (int)(m & 2047);
                    const size_t di = (size_t)which * HSZ
                        + (((size_t)b_ * HEADS + h_) * SEQ + s_) * DK + d_;
                    *(uint32_t*)(Cq + di) = pack2h(v0, v1);
                } else {
                    float2 o; o.x = v0; o.y = v1;
                    *(float2*)(Cf + m * N + n) = o;
                }
            }
        }
    }
}

// ---------------------------------------------------------------------------
// Flash attention: QK^T and PV single fp16 MMA; softmax exp via
// ex2.approx.f16x2 (halves MUFU pressure, output is the packed P fragment).
// grid = (SEQ/128, HEADS, BATCH), 256 threads (8 warps, 16 q rows each).
// Smem: Q 16K (fp16) + 3-stage ring of (K 8K | V 8K). 64 KB -> 2 CTA/SM.
// ---------------------------------------------------------------------------
__global__ __launch_bounds__(256, 2) void attn_mma(
    const __half* __restrict__ Q, const __half* __restrict__ K,
    const __half* __restrict__ V,
    __nv_bfloat16* __restrict__ Ohi, __nv_bfloat16* __restrict__ Olo)
{
    extern __shared__ char smem[];
    const uint32_t sb  = s2u(smem);
    const uint32_t sKV = sb + 16384;
    const int tid = threadIdx.x, lane = tid & 31, w = tid >> 5;
    const int qt = blockIdx.x, hd = blockIdx.y, b = blockIdx.z;
    const size_t hb = ((size_t)b * HEADS + hd) * SEQ * DK;
    const int m0 = qt * 128;
    const int wm = w * 16;

    // Q load: 128 rows x 128B = 16 KB (own cp.async group)
    #pragma unroll
    for (int i = 0; i < 4; i++) {
        int idx = i * 256 + tid;
        int row = idx >> 3, c16 = idx & 7;
        uint32_t so = SW128((uint32_t)(row * 128 + c16 * 16));
        cpa16(sb + so, Q + hb + (size_t)(m0 + row) * DK + c16 * 8);
    }
    asm volatile("cp.async.commit_group;" ::: "memory");

    auto load_kv = [&](int c, int st) {
        const uint32_t s0 = sKV + st * ASTG;
        const int k0 = c * 64;
        #pragma unroll
        for (int i = 0; i < 2; i++) {
            int idx = i * 256 + tid;
            int row = idx >> 3, c16 = idx & 7;
            uint32_t so = SW128((uint32_t)(row * 128 + c16 * 16));
            const size_t g = hb + (size_t)(k0 + row) * DK + c16 * 8;
            cpa16(s0 + so,        K + g);
            cpa16(s0 + 8192 + so, V + g);
        }
        asm volatile("cp.async.commit_group;" ::: "memory");
    };
    load_kv(0, 0);
    load_kv(1, 1);

    // wait for Q (2 kv groups still outstanding), park in registers
    asm volatile("cp.async.wait_group 2;" ::: "memory");
    __syncthreads();
    uint32_t qf[4][4];
    #pragma unroll
    for (int ks = 0; ks < 4; ks++) {
        uint32_t ao = SW128((uint32_t)((wm + (lane & 15)) * 128
                                       + ks * 32 + (lane >> 4) * 16));
        ldsm4(qf[ks], sb + ao);
    }

    float o[8][4];
    #pragma unroll
    for (int j = 0; j < 8; j++)
        #pragma unroll
        for (int i = 0; i < 4; i++) o[j][i] = 0.f;
    float mr0 = -1e30f, mr1 = -1e30f, l0 = 0.f, l1 = 0.f;

    const int NC = SEQ / 64;
    for (int c = 0; c < NC; c++) {
        if (c + 1 < NC) {
            asm volatile("cp.async.wait_group 1;" ::: "memory");
        } else {
            asm volatile("cp.async.wait_group 0;" ::: "memory");
        }
        __syncthreads();
        if (c + 2 < NC) load_kv(c + 2, (c + 2) % 3);
        const uint32_t s0 = sKV + (c % 3) * ASTG;

        // ---- S = Q K^T  (single fp16 MMA) ----
        float sacc[8][4];
        #pragma unroll
        for (int j = 0; j < 8; j++)
            #pragma unroll
            for (int i = 0; i < 4; i++) sacc[j][i] = 0.f;

        #pragma unroll
        for (int ks = 0; ks < 4; ks++) {
            const int brow = ((lane >> 4) << 3) + (lane & 7);
            const int bkb  = ks * 32 + ((lane >> 3) & 1) * 16;
            #pragma unroll
            for (int np = 0; np < 4; np++) {
                uint32_t kf[4];
                uint32_t bo = SW128((uint32_t)((brow + np * 16) * 128 + bkb));
                ldsm4(kf, s0 + bo);
                mma_f16(sacc[np * 2],     qf[ks], kf[0], kf[1]);
                mma_f16(sacc[np * 2 + 1], qf[ks], kf[2], kf[3]);
            }
        }

        // ---- online softmax (ex2.approx.f16x2 path) ----
        float cm0 = -1e30f, cm1 = -1e30f;
        #pragma unroll
        for (int j = 0; j < 8; j++) {
            cm0 = fmaxf(cm0, fmaxf(sacc[j][0], sacc[j][1]));
            cm1 = fmaxf(cm1, fmaxf(sacc[j][2], sacc[j][3]));
        }
        #pragma unroll
        for (int off = 1; off <= 2; off <<= 1) {
            cm0 = fmaxf(cm0, __shfl_xor_sync(0xffffffffu, cm0, off));
            cm1 = fmaxf(cm1, __shfl_xor_sync(0xffffffffu, cm1, off));
        }
        const float mn0 = fmaxf(mr0, cm0), mn1 = fmaxf(mr1, cm1);
        const float a0 = ex2f((mr0 - mn0) * SSC);
        const float a1 = ex2f((mr1 - mn1) * SSC);
        mr0 = mn0; mr1 = mn1;
        const float c0 = mn0 * SSC, c1 = mn1 * SSC;

        // P = 2^(s*SSC - mn*SSC), packed fp16 pairs; pair-sums in fp16.
        uint32_t p01[8], p23[8];
        uint32_t s01 = 0u, s23 = 0u;
        #pragma unroll
        for (int j = 0; j < 8; j++) {
            p01[j] = ex2h2(pack2h(fmaf(sacc[j][0], SSC, -c0),
                                  fmaf(sacc[j][1], SSC, -c0)));
            p23[j] = ex2h2(pack2h(fmaf(sacc[j][2], SSC, -c1),
                                  fmaf(sacc[j][3], SSC, -c1)));
            s01 = hadd2u(s01, p01[j]);
            s23 = hadd2u(s23, p23[j]);
        }
        __half2 hs0 = *(__half2*)&s01;
        __half2 hs1 = *(__half2*)&s23;
        float sum0 = __half2float(hs0.x) + __half2float(hs0.y);
        float sum1 = __half2float(hs1.x) + __half2float(hs1.y);
        #pragma unroll
        for (int off = 1; off <= 2; off <<= 1) {
            sum0 += __shfl_xor_sync(0xffffffffu, sum0, off);
            sum1 += __shfl_xor_sync(0xffffffffu, sum1, off);
        }
        l0 = l0 * a0 + sum0;
        l1 = l1 * a1 + sum1;
        #pragma unroll
        for (int j = 0; j < 8; j++) {
            o[j][0] *= a0; o[j][1] *= a0;
            o[j][2] *= a1; o[j][3] *= a1;
        }

        // ---- O += P V  (single fp16 MMA; P already packed) ----
        #pragma unroll
        for (int ks = 0; ks < 4; ks++) {
            uint32_t ap[4];
            ap[0] = p01[2 * ks];
            ap[1] = p23[2 * ks];
            ap[2] = p01[2 * ks + 1];
            ap[3] = p23[2 * ks + 1];
            const int vrow = ks * 16 + ((lane >> 3) & 1) * 8 + (lane & 7);
            #pragma unroll
            for (int np = 0; np < 4; np++) {
                uint32_t vf[4];
                uint32_t vo = SW128((uint32_t)(vrow * 128 + np * 32
                                               + (lane >> 4) * 16));
                ldsm4t(vf, s0 + 8192 + vo);
                mma_f16(o[np * 2],     ap, vf[0], vf[1]);
                mma_f16(o[np * 2 + 1], ap, vf[2], vf[3]);
            }
        }
    }

    // ---- epilogue ----
    const float inv0 = 1.f / l0, inv1 = 1.f / l1;
    const int s0r = m0 + wm + (lane >> 2);
    const size_t r0 = (size_t)b * SEQ + s0r;
    const size_t r1 = r0 + 8;
    #pragma unroll
    for (int f = 0; f < 8; f++) {
        const int col = hd * DK + f * 8 + 2 * (lane & 3);
        uint32_t ph, pl;
        pack_hl(o[f][0] * inv0, o[f][1] * inv0, ph, pl);
        *(uint32_t*)(Ohi + r0 * EMBED + col) = ph;
        *(uint32_t*)(Olo + r0 * EMBED + col) = pl;
        pack_hl(o[f][2] * inv1, o[f][3] * inv1, ph, pl);
        *(uint32_t*)(Ohi + r1 * EMBED + col) = ph;
        *(uint32_t*)(Olo + r1 * EMBED + col) = pl;
    }
}

// ---------------------------------------------------------------------------
// Launch
// ---------------------------------------------------------------------------
extern "C" void kernel_launch(void* const* d_in, const int* in_sizes, int n_in,
                              void* d_out, int out_size)
{
    const float* x   = (const float*)d_in[0];
    const float* Wq  = (const float*)d_in[1];
    const float* bq  = (const float*)d_in[2];
    const float* Wk  = (const float*)d_in[3];
    const float* bk  = (const float*)d_in[4];
    const float* Wv  = (const float*)d_in[5];
    const float* bv  = (const float*)d_in[6];
    const float* Wo  = (const float*)d_in[7];
    const float* bo  = (const float*)d_in[8];
    const float* W1  = (const float*)d_in[9];
    const float* b1  = (const float*)d_in[10];
    const float* W2  = (const float*)d_in[11];
    const float* b2  = (const float*)d_in[12];
    const float* g1  = (const float*)d_in[13];
    const float* be1 = (const float*)d_in[14];
    const float* g2  = (const float*)d_in[15];
    const float* be2 = (const float*)d_in[16];
    float* out = (float*)d_out;

    __nv_bfloat16 *h_hi, *h_lo, *ao_hi, *ao_lo;
    __nv_bfloat16 *h2_hi, *h2_lo, *f_hi, *f_lo;
    __nv_bfloat16 *wqkv_hi, *wqkv_lo, *wo_hi, *wo_lo, *w1_hi, *w1_lo, *w2_hi, *w2_lo;
    __half *qkv;
    float *x1, *bqkv;
    cudaGetSymbolAddress((void**)&h_hi,    g_h_hi);
    cudaGetSymbolAddress((void**)&h_lo,    g_h_lo);
    cudaGetSymbolAddress((void**)&qkv,     g_qkv);
    cudaGetSymbolAddress((void**)&ao_hi,   g_ao_hi);
    cudaGetSymbolAddress((void**)&ao_lo,   g_ao_lo);
    cudaGetSymbolAddress((void**)&x1,      g_x1);
    cudaGetSymbolAddress((void**)&h2_hi,   g_h2_hi);
    cudaGetSymbolAddress((void**)&h2_lo,   g_h2_lo);
    cudaGetSymbolAddress((void**)&f_hi,    g_f_hi);
    cudaGetSymbolAddress((void**)&f_lo,    g_f_lo);
    cudaGetSymbolAddress((void**)&wqkv_hi, g_wqkv_hi);
    cudaGetSymbolAddress((void**)&wqkv_lo, g_wqkv_lo);
    cudaGetSymbolAddress((void**)&wo_hi,   g_wo_hi);
    cudaGetSymbolAddress((void**)&wo_lo,   g_wo_lo);
    cudaGetSymbolAddress((void**)&w1_hi,   g_w1_hi);
    cudaGetSymbolAddress((void**)&w1_lo,   g_w1_lo);
    cudaGetSymbolAddress((void**)&w2_hi,   g_w2_hi);
    cudaGetSymbolAddress((void**)&w2_lo,   g_w2_lo);
    cudaGetSymbolAddress((void**)&bqkv,    g_bqkv);

    cudaFuncSetAttribute(gemm_mma<2>, cudaFuncAttributeMaxDynamicSharedMemorySize, SMEM_G);
    cudaFuncSetAttribute(gemm_mma<5>, cudaFuncAttributeMaxDynamicSharedMemorySize, SMEM_G);
    cudaFuncSetAttribute(gemm_mma<6>, cudaFuncAttributeMaxDynamicSharedMemorySize, SMEM_G);
    cudaFuncSetAttribute(attn_mma, cudaFuncAttributeMaxDynamicSharedMemorySize, SMEM_A);

    // all weight splits + bias concat in one kernel
    cvt_all<<<WT4 / 256 + 3, 256>>>(
        Wq, Wk, Wv, Wo, W1, W2, bq, bk, bv, bqkv,
        wqkv_hi, wqkv_lo, wo_hi, wo_lo, w1_hi, w1_lo, w2_hi, w2_lo);

    // LN1 -> (hi, lo)
    ln_kernel<<<MROWS, 256>>>(x, g1, be1, h_hi, h_lo);

    // Fused QKV projection -> q,k,v fp16 single, head layout
    {
        dim3 grid(3 * EMBED / CTN, MROWS / CTM);
        gemm_mma<6><<<grid, 128, SMEM_G>>>(h_hi, h_lo, wqkv_hi, wqkv_lo, bqkv,
                                           nullptr, nullptr, nullptr, nullptr, qkv,
                                           MROWS, 3 * EMBED, EMBED);
    }

    // Attention -> ao (hi, lo)
    {
        dim3 grid(SEQ / 128, HEADS, BATCH);
        attn_mma<<<grid, 256, SMEM_A>>>(qkv, qkv + HSZ, qkv + 2 * HSZ,
                                        ao_hi, ao_lo);
    }

    // O projection + residual: x1 = x + ao @ Wo^T + bo
    {
        dim3 grid(EMBED / CTN, MROWS / CTM);
        gemm_mma<2><<<grid, 128, SMEM_G>>>(ao_hi, ao_lo, wo_hi, wo_lo, bo, x,
                                           x1, nullptr, nullptr, nullptr,
                                           MROWS, EMBED, EMBED);
    }

    // LN2 -> (hi, lo)
    ln_kernel<<<MROWS, 256>>>(x1, g2, be2, h2_hi, h2_lo);

    // FFN1 + relu -> f (hi, lo)
    {
        dim3 grid(FFN / CTN, MROWS / CTM);
        gemm_mma<5><<<grid, 128, SMEM_G>>>(h2_hi, h2_lo, w1_hi, w1_lo, b1,
                                           nullptr, nullptr, f_hi, f_lo, nullptr,
                                           MROWS, FFN, EMBED);
    }

    // FFN2 + residual -> out
    {
        dim3 grid(EMBED / CTN, MROWS / CTM);
        gemm_mma<2><<<grid, 128, SMEM_G>>>(f_hi, f_lo, w2_hi, w2_lo, b2, x1,
                                           out, nullptr, nullptr, nullptr,
                                           MROWS, EMBED, FFN);
    }
}

// round 13
// speedup vs baseline: 2.0454x; 1.5405x over previous
#include <cuda_runtime.h>
#include <cuda_bf16.h>
#include <cuda_fp16.h>
#include <math.h>
#include <stdint.h>

// ---------------------------------------------------------------------------
// Problem constants
// ---------------------------------------------------------------------------
#define BATCH   2
#define SEQ     2048
#define EMBED   1024
#define HEADS   16
#define DK      64
#define FFN     4096
#define MROWS   (BATCH * SEQ)          // 4096
#define LN_EPS  1e-5f
#define SSC     0.1803368801111204f    // 0.125 * log2(e)
#define HSZ     (MROWS * EMBED)        // 4M elements

// GEMM tiling: CTA 128x128, K-chunk 32, 4 warps (warp tile 64x64)
#define CTM 128
#define CTN 128
#define KTC 32
// split (bf16 hi/lo) GEMM: stage 32K, 3 stages
#define STG_S 32768
#define SMEM_S (3 * STG_S)             // 96 KB -> 2 CTA/SM
// all-fp16 GEMM: stage 16K, 3 stages
#define STG_F 16384
#define SMEM_F (3 * STG_F)             // 48 KB -> 2 CTA/SM

// Attention: Q 16K (fp16) + 3 stages x (K 8K + V 8K)
#define ASTG 16384
#define SMEM_A (16384 + 3 * ASTG)      // 64 KB -> 2 CTA/SM

#define SW128(o) ((o) ^ (((o) >> 3) & 0x70))
#define SW64(o)  ((o) ^ (((o) >> 3) & 0x30))

// ---------------------------------------------------------------------------
// Scratch buffers (allocation-free: __device__ globals)
// ---------------------------------------------------------------------------
__device__ __half        g_h    [HSZ];        // LN1 out, fp16
__device__ __half        g_qkv  [3 * HSZ];    // q | k | v, fp16, [B,H,S,DK]
__device__ __half        g_ao   [HSZ];        // attention out, fp16
__device__ float         g_x1   [HSZ];
__device__ __nv_bfloat16 g_h2_hi[HSZ];        // LN2 out, exact bf16 split
__device__ __nv_bfloat16 g_h2_lo[HSZ];
__device__ __half        g_f    [MROWS * FFN]; // relu FFN1 out, fp16

__device__ __half        g_wqkv [3 * EMBED * EMBED];  // fp16
__device__ __half        g_wo   [EMBED * EMBED];      // fp16
__device__ __nv_bfloat16 g_w1_hi[FFN * EMBED];        // bf16 split
__device__ __nv_bfloat16 g_w1_lo[FFN * EMBED];
__device__ __half        g_w2   [EMBED * FFN];        // fp16
__device__ float         g_bqkv [3 * EMBED];

// ---------------------------------------------------------------------------
// helpers
// ---------------------------------------------------------------------------
static __device__ __forceinline__ uint32_t s2u(const void* p) {
    uint32_t a;
    asm("{ .reg .u64 t; cvta.to.shared.u64 t, %1; cvt.u32.u64 %0, t; }"
        : "=r"(a) : "l"(p));
    return a;
}
static __device__ __forceinline__ void cpa16(uint32_t s, const void* g) {
    asm volatile("cp.async.cg.shared.global [%0], [%1], 16;"
                 :: "r"(s), "l"(g) : "memory");
}
static __device__ __forceinline__ void ldsm4(uint32_t* f, uint32_t a) {
    asm volatile("ldmatrix.sync.aligned.m8n8.x4.shared.b16 {%0,%1,%2,%3}, [%4];"
                 : "=r"(f[0]), "=r"(f[1]), "=r"(f[2]), "=r"(f[3]) : "r"(a));
}
static __device__ __forceinline__ void ldsm4t(uint32_t* f, uint32_t a) {
    asm volatile("ldmatrix.sync.aligned.m8n8.x4.trans.shared.b16 {%0,%1,%2,%3}, [%4];"
                 : "=r"(f[0]), "=r"(f[1]), "=r"(f[2]), "=r"(f[3]) : "r"(a));
}
static __device__ __forceinline__ void mma_bf16(float* c, const uint32_t* a,
                                                uint32_t b0, uint32_t b1) {
    asm volatile(
        "mma.sync.aligned.m16n8k16.row.col.f32.bf16.bf16.f32 "
        "{%0,%1,%2,%3}, {%4,%5,%6,%7}, {%8,%9}, {%0,%1,%2,%3};"
        : "+f"(c[0]), "+f"(c[1]), "+f"(c[2]), "+f"(c[3])
        : "r"(a[0]), "r"(a[1]), "r"(a[2]), "r"(a[3]), "r"(b0), "r"(b1));
}
static __device__ __forceinline__ void mma_f16(float* c, const uint32_t* a,
                                               uint32_t b0, uint32_t b1) {
    asm volatile(
        "mma.sync.aligned.m16n8k16.row.col.f32.f16.f16.f32 "
        "{%0,%1,%2,%3}, {%4,%5,%6,%7}, {%8,%9}, {%0,%1,%2,%3};"
        : "+f"(c[0]), "+f"(c[1]), "+f"(c[2]), "+f"(c[3])
        : "r"(a[0]), "r"(a[1]), "r"(a[2]), "r"(a[3]), "r"(b0), "r"(b1));
}
static __device__ __forceinline__ float ex2f(float x) {
    float y;
    asm("ex2.approx.f32 %0, %1;" : "=f"(y) : "f"(x));
    return y;
}
static __device__ __forceinline__ uint32_t ex2h2(uint32_t a) {
    asm("ex2.approx.f16x2 %0, %0;" : "+r"(a));
    return a;
}
static __device__ __forceinline__ uint32_t hadd2u(uint32_t a, uint32_t b) {
    uint32_t d;
    asm("add.f16x2 %0, %1, %2;" : "=r"(d) : "r"(a), "r"(b));
    return d;
}
static __device__ __forceinline__ void split2(float v, __nv_bfloat16& h, __nv_bfloat16& l) {
    h = __float2bfloat16(v);
    l = __float2bfloat16(v - __bfloat162float(h));
}
static __device__ __forceinline__ void pack_hl(float x, float y,
                                               uint32_t& hi, uint32_t& lo) {
    __nv_bfloat16 hx, lx, hy, ly;
    split2(x, hx, lx);
    split2(y, hy, ly);
    __nv_bfloat162 H; H.x = hx; H.y = hy;
    __nv_bfloat162 L; L.x = lx; L.y = ly;
    hi = *(uint32_t*)&H;
    lo = *(uint32_t*)&L;
}
static __device__ __forceinline__ uint32_t pack2h(float x, float y) {
    __half2 h = __floats2half2_rn(x, y);
    return *(uint32_t*)&h;
}

// ---------------------------------------------------------------------------
// One-shot weight conversion + bias concat.
// Segments (float4 units): wqkv->fp16 (3*NE4) | wo->fp16 (NE4) |
//                          w1->bf16 split (NF4) | w2->fp16 (NF4) | bias tail
// ---------------------------------------------------------------------------
#define NE4 (EMBED * EMBED / 4)       // 256K
#define NF4 (FFN * EMBED / 4)         // 1M
#define WT4 (4 * NE4 + 2 * NF4)       // 3M
__global__ __launch_bounds__(256) void cvt_all(
    const float* __restrict__ wq, const float* __restrict__ wk,
    const float* __restrict__ wv, const float* __restrict__ wo,
    const float* __restrict__ w1, const float* __restrict__ w2,
    const float* __restrict__ bq, const float* __restrict__ bk,
    const float* __restrict__ bv, float* __restrict__ bqkv,
    __half* __restrict__ wqkv_h, __half* __restrict__ wo_h,
    __nv_bfloat16* __restrict__ w1_hi, __nv_bfloat16* __restrict__ w1_lo,
    __half* __restrict__ w2_h)
{
    int i = blockIdx.x * 256 + threadIdx.x;    // float4 index
    if (i >= WT4) {                            // bias concat tail
        int j = i - WT4;
        if (j < 768) {
            const float* bs = (j < 256) ? bq : (j < 512) ? bk : bv;
            int jj = (j < 256) ? j : (j < 512) ? j - 256 : j - 512;
            ((float4*)bqkv)[j] = ((const float4*)bs)[jj];
        }
        return;
    }
    if (i < 4 * NE4 || i >= 4 * NE4 + NF4) {
        // fp16-single segments
        const float* src;
        __half* dst;
        int j;
        if (i < 3 * NE4) {
            src = (i < NE4) ? wq : (i < 2 * NE4) ? wk : wv;
            j = (i < NE4) ? i : (i < 2 * NE4) ? i - NE4 : i - 2 * NE4;
            dst = wqkv_h + (size_t)(i - j) * 4;
        } else if (i < 4 * NE4) {
            src = wo; j = i - 3 * NE4; dst = wo_h;
        } else {
            src = w2; j = i - 4 * NE4 - NF4; dst = w2_h;
        }
        float4 v = ((const float4*)src)[j];
        uint2 H;
        H.x = pack2h(v.x, v.y);
        H.y = pack2h(v.z, v.w);
        ((uint2*)dst)[j] = H;
    } else {
        // bf16-split segment (W1)
        int j = i - 4 * NE4;
        float4 v = ((const float4*)w1)[j];
        uint32_t h0, l0, h1, l1;
        pack_hl(v.x, v.y, h0, l0);
        pack_hl(v.z, v.w, h1, l1);
        uint2 H; H.x = h0; H.y = h1;
        uint2 L; L.x = l0; L.y = l1;
        ((uint2*)w1_hi)[j] = H;
        ((uint2*)w1_lo)[j] = L;
    }
}

// ---------------------------------------------------------------------------
// LayerNorm. MODE 0: fp16 single out. MODE 1: bf16 (hi, lo) out.
// ---------------------------------------------------------------------------
template <int MODE>
__global__ __launch_bounds__(256) void ln_kernel(
    const float* __restrict__ x, const float* __restrict__ g,
    const float* __restrict__ be, __half* __restrict__ oh,
    __nv_bfloat16* __restrict__ ohi, __nv_bfloat16* __restrict__ olo)
{
    const int N = EMBED;
    const size_t row = blockIdx.x;
    const float* xr = x + row * N;
    float s = 0.f, s2 = 0.f;
    #pragma unroll
    for (int i = threadIdx.x; i < N; i += 256) {
        float v = xr[i];
        s += v; s2 += v * v;
    }
    #pragma unroll
    for (int off = 16; off; off >>= 1) {
        s  += __shfl_xor_sync(0xffffffffu, s,  off);
        s2 += __shfl_xor_sync(0xffffffffu, s2, off);
    }
    __shared__ float red[16];
    __shared__ float mu_sh, rs_sh;
    int w = threadIdx.x >> 5, l = threadIdx.x & 31;
    if (l == 0) { red[w] = s; red[8 + w] = s2; }
    __syncthreads();
    if (threadIdx.x == 0) {
        float ts = 0.f, ts2 = 0.f;
        #pragma unroll
        for (int i = 0; i < 8; i++) { ts += red[i]; ts2 += red[8 + i]; }
        float mu  = ts / N;
        float var = ts2 / N - mu * mu;
        mu_sh = mu;
        rs_sh = rsqrtf(var + LN_EPS);
    }
    __syncthreads();
    float mu = mu_sh, rs = rs_sh;
    #pragma unroll
    for (int i = threadIdx.x; i < N; i += 256) {
        float y = (xr[i] - mu) * rs * g[i] + be[i];
        if (MODE == 0) {
            oh[row * N + i] = __float2half_rn(y);
        } else {
            __nv_bfloat16 h, lo;
            split2(y, h, lo);
            ohi[row * N + i] = h;
            olo[row * N + i] = lo;
        }
    }
}

// ---------------------------------------------------------------------------
// All-fp16 GEMM (1 MMA): C[M,N] = A[M,K] @ W[N,K]^T (+bias, +res)
// CTA 128x128, 4 warps (64x64), KTC 32 (SW64), 3-stage cp.async, 48KB smem.
// EPI: 2 = bias+res -> fp32; 6 = fused QKV (N=3072) -> fp16 head layout
// ---------------------------------------------------------------------------
template <int EPI>
__global__ __launch_bounds__(128, 2) void gemm_f16(
    const __half* __restrict__ A, const __half* __restrict__ B,
    const float* __restrict__ bias, const float* __restrict__ res,
    float* __restrict__ Cf, __half* __restrict__ Ch, int M, int N, int K)
{
    extern __shared__ char smem[];
    const uint32_t sb = s2u(smem);
    const int tid = threadIdx.x;
    const int lane = tid & 31, w = tid >> 5;
    const int bm = blockIdx.y * CTM, bn = blockIdx.x * CTN;
    const int wm = (w & 1) * 64, wn = (w >> 1) * 64;

    float acc[4][8][4];
    #pragma unroll
    for (int mt = 0; mt < 4; mt++)
        #pragma unroll
        for (int nt = 0; nt < 8; nt++)
            #pragma unroll
            for (int i = 0; i < 4; i++) acc[mt][nt][i] = 0.f;

    const int NC = K / KTC;

    auto load_chunk = [&](int c, int st) {
        const uint32_t s0 = sb + st * STG_F;
        const size_t k0 = (size_t)c * KTC;
        #pragma unroll
        for (int i = 0; i < 4; i++) {                 // A: 128 rows x 64B
            int idx = i * 128 + tid;
            int row = idx >> 2, c4 = idx & 3;
            uint32_t so = SW64((uint32_t)(row * 64 + c4 * 16));
            cpa16(s0 + so, A + (size_t)(bm + row) * K + k0 + c4 * 8);
        }
        #pragma unroll
        for (int i = 0; i < 4; i++) {                 // B: 128 rows x 64B
            int idx = i * 128 + tid;
            int row = idx >> 2, c4 = idx & 3;
            uint32_t so = SW64((uint32_t)(row * 64 + c4 * 16));
            cpa16(s0 + 8192 + so, B + (size_t)(bn + row) * K + k0 + c4 * 8);
        }
        asm volatile("cp.async.commit_group;" ::: "memory");
    };

    load_chunk(0, 0);
    load_chunk(1, 1);

    for (int c = 0; c < NC; c++) {
        if (c + 1 < NC) {
            asm volatile("cp.async.wait_group 1;" ::: "memory");
        } else {
            asm volatile("cp.async.wait_group 0;" ::: "memory");
        }
        __syncthreads();
        if (c + 2 < NC) load_chunk(c + 2, (c + 2) % 3);

        const uint32_t s0 = sb + (c % 3) * STG_F;
        #pragma unroll
        for (int ks = 0; ks < 2; ks++) {
            uint32_t af[4][4], bf[4][4];
            const int arow = wm + (lane & 15);
            const int akb  = ks * 32 + (lane >> 4) * 16;
            #pragma unroll
            for (int mt = 0; mt < 4; mt++) {
                uint32_t ao = SW64((uint32_t)((arow + mt * 16) * 64 + akb));
                ldsm4(af[mt], s0 + ao);
            }
            const int brow = wn + ((lane >> 4) << 3) + (lane & 7);
            const int bkb  = ks * 32 + ((lane >> 3) & 1) * 16;
            #pragma unroll
            for (int np = 0; np < 4; np++) {
                uint32_t bo = SW64((uint32_t)((brow + np * 16) * 64 + bkb));
                ldsm4(bf[np], s0 + 8192 + bo);
            }
            #pragma unroll
            for (int mt = 0; mt < 4; mt++) {
                #pragma unroll
                for (int nt = 0; nt < 8; nt++) {
                    const int np = nt >> 1, ro = (nt & 1) * 2;
                    mma_f16(acc[mt][nt], af[mt], bf[np][ro], bf[np][ro + 1]);
                }
            }
        }
    }

    // ---- epilogue ----
    #pragma unroll
    for (int mt = 0; mt < 4; mt++) {
        #pragma unroll
        for (int nt = 0; nt < 8; nt++) {
            const int n = bn + wn + nt * 8 + (lane & 3) * 2;
            const float2 bs = *(const float2*)(bias + n);
            #pragma unroll
            for (int hh = 0; hh < 2; hh++) {
                const size_t m = (size_t)bm + wm + mt * 16 + (lane >> 2) + hh * 8;
                float v0 = acc[mt][nt][hh * 2]     + bs.x;
                float v1 = acc[mt][nt][hh * 2 + 1] + bs.y;
                if (EPI == 2) {
                    float2 rr = *(const float2*)(res + m * N + n);
                    v0 += rr.x; v1 += rr.y;
                    float2 o; o.x = v0; o.y = v1;
                    *(float2*)(Cf + m * N + n) = o;
                } else {  // EPI 6: fused QKV head layout
                    const int which = n >> 10;
                    const int h_ = (n >> 6) & (HEADS - 1), d_ = n & 63;
                    const int b_ = (int)(m >> 11), s_ = (int)(m & 2047);
                    const size_t di = (size_t)which * HSZ
                        + (((size_t)b_ * HEADS + h_) * SEQ + s_) * DK + d_;
                    *(uint32_t*)(Ch + di) = pack2h(v0, v1);
                }
            }
        }
    }
}

// ---------------------------------------------------------------------------
// bf16-split GEMM (3 MMAs) — FFN1 only: exact h2 x exact W1 + relu -> fp16 f.
// CTA 128x128, 4 warps (64x64), KTC 32 (SW64), 3-stage cp.async, 96KB smem.
// ---------------------------------------------------------------------------
__global__ __launch_bounds__(128, 2) void gemm_split_relu(
    const __nv_bfloat16* __restrict__ Ah, const __nv_bfloat16* __restrict__ Al,
    const __nv_bfloat16* __restrict__ Bh, const __nv_bfloat16* __restrict__ Bl,
    const float* __restrict__ bias, __half* __restrict__ Ch, int M, int N, int K)
{
    extern __shared__ char smem[];
    const uint32_t sb = s2u(smem);
    const int tid = threadIdx.x;
    const int lane = tid & 31, w = tid >> 5;
    const int bm = blockIdx.y * CTM, bn = blockIdx.x * CTN;
    const int wm = (w & 1) * 64, wn = (w >> 1) * 64;

    float acc[4][8][4];
    #pragma unroll
    for (int mt = 0; mt < 4; mt++)
        #pragma unroll
        for (int nt = 0; nt < 8; nt++)
            #pragma unroll
            for (int i = 0; i < 4; i++) acc[mt][nt][i] = 0.f;

    const int NC = K / KTC;

    auto load_chunk = [&](int c, int st) {
        const uint32_t s0 = sb + st * STG_S;
        const size_t k0 = (size_t)c * KTC;
        #pragma unroll
        for (int i = 0; i < 4; i++) {
            int idx = i * 128 + tid;
            int row = idx >> 2, c4 = idx & 3;
            uint32_t so = SW64((uint32_t)(row * 64 + c4 * 16));
            const size_t g = (size_t)(bm + row) * K + k0 + c4 * 8;
            cpa16(s0 + so,        Ah + g);
            cpa16(s0 + 8192 + so, Al + g);
        }
        #pragma unroll
        for (int i = 0; i < 4; i++) {
            int idx = i * 128 + tid;
            int row = idx >> 2, c4 = idx & 3;
            uint32_t so = SW64((uint32_t)(row * 64 + c4 * 16));
            const size_t g = (size_t)(bn + row) * K + k0 + c4 * 8;
            cpa16(s0 + 16384 + so, Bh + g);
            cpa16(s0 + 24576 + so, Bl + g);
        }
        asm volatile("cp.async.commit_group;" ::: "memory");
    };

    load_chunk(0, 0);
    load_chunk(1, 1);

    for (int c = 0; c < NC; c++) {
        if (c + 1 < NC) {
            asm volatile("cp.async.wait_group 1;" ::: "memory");
        } else {
            asm volatile("cp.async.wait_group 0;" ::: "memory");
        }
        __syncthreads();
        if (c + 2 < NC) load_chunk(c + 2, (c + 2) % 3);

        const uint32_t s0 = sb + (c % 3) * STG_S;
        #pragma unroll
        for (int ks = 0; ks < 2; ks++) {
            uint32_t ah[4][4], alr[4][4], bh[4][4], blr[4][4];
            const int arow = wm + (lane & 15);
            const int akb  = ks * 32 + (lane >> 4) * 16;
            #pragma unroll
            for (int mt = 0; mt < 4; mt++) {
                uint32_t ao = SW64((uint32_t)((arow + mt * 16) * 64 + akb));
                ldsm4(ah[mt],  s0 + ao);
                ldsm4(alr[mt], s0 + 8192 + ao);
            }
            const int brow = wn + ((lane >> 4) << 3) + (lane & 7);
            const int bkb  = ks * 32 + ((lane >> 3) & 1) * 16;
            #pragma unroll
            for (int np = 0; np < 4; np++) {
                uint32_t bo = SW64((uint32_t)((brow + np * 16) * 64 + bkb));
                ldsm4(bh[np],  s0 + 16384 + bo);
                ldsm4(blr[np], s0 + 24576 + bo);
            }
            #pragma unroll
            for (int mt = 0; mt < 4; mt++) {
                #pragma unroll
                for (int nt = 0; nt < 8; nt++) {
                    const int np = nt >> 1, ro = (nt & 1) * 2;
                    mma_bf16(acc[mt][nt], ah[mt],  bh[np][ro],  bh[np][ro + 1]);
                    mma_bf16(acc[mt][nt], ah[mt],  blr[np][ro], blr[np][ro + 1]);
                    mma_bf16(acc[mt][nt], alr[mt], bh[np][ro],  bh[np][ro + 1]);
                }
            }
        }
    }

    // ---- epilogue: bias + relu -> fp16 ----
    #pragma unroll
    for (int mt = 0; mt < 4; mt++) {
        #pragma unroll
        for (int nt = 0; nt < 8; nt++) {
            const int n = bn + wn + nt * 8 + (lane & 3) * 2;
            const float2 bs = *(const float2*)(bias + n);
            #pragma unroll
            for (int hh = 0; hh < 2; hh++) {
                const size_t m = (size_t)bm + wm + mt * 16 + (lane >> 2) + hh * 8;
                float v0 = fmaxf(acc[mt][nt][hh * 2]     + bs.x, 0.f);
                float v1 = fmaxf(acc[mt][nt][hh * 2 + 1] + bs.y, 0.f);
                *(uint32_t*)(Ch + m * N + n) = pack2h(v0, v1);
            }
        }
    }
}

// ---------------------------------------------------------------------------
// Flash attention (all fp16 MMAs, f16x2 softmax), fp16 output.
// grid = (SEQ/128, HEADS, BATCH), 256 threads (8 warps, 16 q rows each).
// ---------------------------------------------------------------------------
__global__ __launch_bounds__(256, 2) void attn_mma(
    const __half* __restrict__ Q, const __half* __restrict__ K,
    const __half* __restrict__ V, __half* __restrict__ O)
{
    extern __shared__ char smem[];
    const uint32_t sb  = s2u(smem);
    const uint32_t sKV = sb + 16384;
    const int tid = threadIdx.x, lane = tid & 31, w = tid >> 5;
    const int qt = blockIdx.x, hd = blockIdx.y, b = blockIdx.z;
    const size_t hb = ((size_t)b * HEADS + hd) * SEQ * DK;
    const int m0 = qt * 128;
    const int wm = w * 16;

    #pragma unroll
    for (int i = 0; i < 4; i++) {
        int idx = i * 256 + tid;
        int row = idx >> 3, c16 = idx & 7;
        uint32_t so = SW128((uint32_t)(row * 128 + c16 * 16));
        cpa16(sb + so, Q + hb + (size_t)(m0 + row) * DK + c16 * 8);
    }
    asm volatile("cp.async.commit_group;" ::: "memory");

    auto load_kv = [&](int c, int st) {
        const uint32_t s0 = sKV + st * ASTG;
        const int k0 = c * 64;
        #pragma unroll
        for (int i = 0; i < 2; i++) {
            int idx = i * 256 + tid;
            int row = idx >> 3, c16 = idx & 7;
            uint32_t so = SW128((uint32_t)(row * 128 + c16 * 16));
            const size_t g = hb + (size_t)(k0 + row) * DK + c16 * 8;
            cpa16(s0 + so,        K + g);
            cpa16(s0 + 8192 + so, V + g);
        }
        asm volatile("cp.async.commit_group;" ::: "memory");
    };
    load_kv(0, 0);
    load_kv(1, 1);

    asm volatile("cp.async.wait_group 2;" ::: "memory");
    __syncthreads();
    uint32_t qf[4][4];
    #pragma unroll
    for (int ks = 0; ks < 4; ks++) {
        uint32_t ao = SW128((uint32_t)((wm + (lane & 15)) * 128
                                       + ks * 32 + (lane >> 4) * 16));
        ldsm4(qf[ks], sb + ao);
    }

    float o[8][4];
    #pragma unroll
    for (int j = 0; j < 8; j++)
        #pragma unroll
        for (int i = 0; i < 4; i++) o[j][i] = 0.f;
    float mr0 = -1e30f, mr1 = -1e30f, l0 = 0.f, l1 = 0.f;

    const int NC = SEQ / 64;
    for (int c = 0; c < NC; c++) {
        if (c + 1 < NC) {
            asm volatile("cp.async.wait_group 1;" ::: "memory");
        } else {
            asm volatile("cp.async.wait_group 0;" ::: "memory");
        }
        __syncthreads();
        if (c + 2 < NC) load_kv(c + 2, (c + 2) % 3);
        const uint32_t s0 = sKV + (c % 3) * ASTG;

        float sacc[8][4];
        #pragma unroll
        for (int j = 0; j < 8; j++)
            #pragma unroll
            for (int i = 0; i < 4; i++) sacc[j][i] = 0.f;

        #pragma unroll
        for (int ks = 0; ks < 4; ks++) {
            const int brow = ((lane >> 4) << 3) + (lane & 7);
            const int bkb  = ks * 32 + ((lane >> 3) & 1) * 16;
            #pragma unroll
            for (int np = 0; np < 4; np++) {
                uint32_t kf[4];
                uint32_t bo = SW128((uint32_t)((brow + np * 16) * 128 + bkb));
                ldsm4(kf, s0 + bo);
                mma_f16(sacc[np * 2],     qf[ks], kf[0], kf[1]);
                mma_f16(sacc[np * 2 + 1], qf[ks], kf[2], kf[3]);
            }
        }

        float cm0 = -1e30f, cm1 = -1e30f;
        #pragma unroll
        for (int j = 0; j < 8; j++) {
            cm0 = fmaxf(cm0, fmaxf(sacc[j][0], sacc[j][1]));
            cm1 = fmaxf(cm1, fmaxf(sacc[j][2], sacc[j][3]));
        }
        #pragma unroll
        for (int off = 1; off <= 2; off <<= 1) {
            cm0 = fmaxf(cm0, __shfl_xor_sync(0xffffffffu, cm0, off));
            cm1 = fmaxf(cm1, __shfl_xor_sync(0xffffffffu, cm1, off));
        }
        const float mn0 = fmaxf(mr0, cm0), mn1 = fmaxf(mr1, cm1);
        const float a0 = ex2f((mr0 - mn0) * SSC);
        const float a1 = ex2f((mr1 - mn1) * SSC);
        mr0 = mn0; mr1 = mn1;
        const float c0 = mn0 * SSC, c1 = mn1 * SSC;

        uint32_t p01[8], p23[8];
        uint32_t s01 = 0u, s23 = 0u;
        #pragma unroll
        for (int j = 0; j < 8; j++) {
            p01[j] = ex2h2(pack2h(fmaf(sacc[j][0], SSC, -c0),
                                  fmaf(sacc[j][1], SSC, -c0)));
            p23[j] = ex2h2(pack2h(fmaf(sacc[j][2], SSC, -c1),
                                  fmaf(sacc[j][3], SSC, -c1)));
            s01 = hadd2u(s01, p01[j]);
            s23 = hadd2u(s23, p23[j]);
        }
        __half2 hs0 = *(__half2*)&s01;
        __half2 hs1 = *(__half2*)&s23;
        float sum0 = __half2float(hs0.x) + __half2float(hs0.y);
        float sum1 = __half2float(hs1.x) + __half2float(hs1.y);
        #pragma unroll
        for (int off = 1; off <= 2; off <<= 1) {
            sum0 += __shfl_xor_sync(0xffffffffu, sum0, off);
            sum1 += __shfl_xor_sync(0xffffffffu, sum1, off);
        }
        l0 = l0 * a0 + sum0;
        l1 = l1 * a1 + sum1;
        #pragma unroll
        for (int j = 0; j < 8; j++) {
            o[j][0] *= a0; o[j][1] *= a0;
            o[j][2] *= a1; o[j][3] *= a1;
        }

        #pragma unroll
        for (int ks = 0; ks < 4; ks++) {
            uint32_t ap[4];
            ap[0] = p01[2 * ks];
            ap[1] = p23[2 * ks];
            ap[2] = p01[2 * ks + 1];
            ap[3] = p23[2 * ks + 1];
            const int vrow = ks * 16 + ((lane >> 3) & 1) * 8 + (lane & 7);
            #pragma unroll
            for (int np = 0; np < 4; np++) {
                uint32_t vf[4];
                uint32_t vo = SW128((uint32_t)(vrow * 128 + np * 32
                                               + (lane >> 4) * 16));
                ldsm4t(vf, s0 + 8192 + vo);
                mma_f16(o[np * 2],     ap, vf[0], vf[1]);
                mma_f16(o[np * 2 + 1], ap, vf[2], vf[3]);
            }
        }
    }

    // ---- epilogue: fp16 single ao ----
    const float inv0 = 1.f / l0, inv1 = 1.f / l1;
    const int s0r = m0 + wm + (lane >> 2);
    const size_t r0 = (size_t)b * SEQ + s0r;
    const size_t r1 = r0 + 8;
    #pragma unroll
    for (int f = 0; f < 8; f++) {
        const int col = hd * DK + f * 8 + 2 * (lane & 3);
        *(uint32_t*)(O + r0 * EMBED + col) = pack2h(o[f][0] * inv0, o[f][1] * inv0);
        *(uint32_t*)(O + r1 * EMBED + col) = pack2h(o[f][2] * inv1, o[f][3] * inv1);
    }
}

// ---------------------------------------------------------------------------
// Launch
// ---------------------------------------------------------------------------
extern "C" void kernel_launch(void* const* d_in, const int* in_sizes, int n_in,
                              void* d_out, int out_size)
{
    const float* x   = (const float*)d_in[0];
    const float* Wq  = (const float*)d_in[1];
    const float* bq  = (const float*)d_in[2];
    const float* Wk  = (const float*)d_in[3];
    const float* bk  = (const float*)d_in[4];
    const float* Wv  = (const float*)d_in[5];
    const float* bv  = (const float*)d_in[6];
    const float* Wo  = (const float*)d_in[7];
    const float* bo  = (const float*)d_in[8];
    const float* W1  = (const float*)d_in[9];
    const float* b1  = (const float*)d_in[10];
    const float* W2  = (const float*)d_in[11];
    const float* b2  = (const float*)d_in[12];
    const float* g1  = (const float*)d_in[13];
    const float* be1 = (const float*)d_in[14];
    const float* g2  = (const float*)d_in[15];
    const float* be2 = (const float*)d_in[16];
    float* out = (float*)d_out;

    __half *h, *qkv, *ao, *f, *wqkv, *wo, *w2;
    __nv_bfloat16 *h2_hi, *h2_lo, *w1_hi, *w1_lo;
    float *x1, *bqkv;
    cudaGetSymbolAddress((void**)&h,     g_h);
    cudaGetSymbolAddress((void**)&qkv,   g_qkv);
    cudaGetSymbolAddress((void**)&ao,    g_ao);
    cudaGetSymbolAddress((void**)&x1,    g_x1);
    cudaGetSymbolAddress((void**)&h2_hi, g_h2_hi);
    cudaGetSymbolAddress((void**)&h2_lo, g_h2_lo);
    cudaGetSymbolAddress((void**)&f,     g_f);
    cudaGetSymbolAddress((void**)&wqkv,  g_wqkv);
    cudaGetSymbolAddress((void**)&wo,    g_wo);
    cudaGetSymbolAddress((void**)&w1_hi, g_w1_hi);
    cudaGetSymbolAddress((void**)&w1_lo, g_w1_lo);
    cudaGetSymbolAddress((void**)&w2,    g_w2);
    cudaGetSymbolAddress((void**)&bqkv,  g_bqkv);

    cudaFuncSetAttribute(gemm_f16<2>, cudaFuncAttributeMaxDynamicSharedMemorySize, SMEM_F);
    cudaFuncSetAttribute(gemm_f16<6>, cudaFuncAttributeMaxDynamicSharedMemorySize, SMEM_F);
    cudaFuncSetAttribute(gemm_split_relu, cudaFuncAttributeMaxDynamicSharedMemorySize, SMEM_S);
    cudaFuncSetAttribute(attn_mma, cudaFuncAttributeMaxDynamicSharedMemorySize, SMEM_A);

    // all weight conversions + bias concat in one kernel
    cvt_all<<<WT4 / 256 + 3, 256>>>(
        Wq, Wk, Wv, Wo, W1, W2, bq, bk, bv, bqkv,
        wqkv, wo, w1_hi, w1_lo, w2);

    // LN1 -> fp16 single
    ln_kernel<0><<<MROWS, 256>>>(x, g1, be1, h, nullptr, nullptr);

    // Fused QKV projection (all fp16, 1 MMA) -> head layout fp16
    {
        dim3 grid(3 * EMBED / CTN, MROWS / CTM);
        gemm_f16<6><<<grid, 128, SMEM_F>>>(h, wqkv, bqkv, nullptr,
                                           nullptr, qkv, MROWS, 3 * EMBED, EMBED);
    }

    // Attention -> ao fp16
    {
        dim3 grid(SEQ / 128, HEADS, BATCH);
        attn_mma<<<grid, 256, SMEM_A>>>(qkv, qkv + HSZ, qkv + 2 * HSZ, ao);
    }

    // O projection + residual (all fp16, 1 MMA): x1 = x + ao @ Wo^T + bo
    {
        dim3 grid(EMBED / CTN, MROWS / CTM);
        gemm_f16<2><<<grid, 128, SMEM_F>>>(ao, wo, bo, x,
                                           x1, nullptr, MROWS, EMBED, EMBED);
    }

    // LN2 -> bf16 (hi, lo) exact
    ln_kernel<1><<<MROWS, 256>>>(x1, g2, be2, nullptr, h2_hi, h2_lo);

    // FFN1 + relu (bf16 split, 3 MMAs) -> f fp16
    {
        dim3 grid(FFN / CTN, MROWS / CTM);
        gemm_split_relu<<<grid, 128, SMEM_S>>>(h2_hi, h2_lo, w1_hi, w1_lo, b1,
                                               f, MROWS, FFN, EMBED);
    }

    // FFN2 + residual (all fp16, 1 MMA) -> out fp32
    {
        dim3 grid(EMBED / CTN, MROWS / CTM);
        gemm_f16<2><<<grid, 128, SMEM_F>>>(f, w2, b2, x1,
                                           out, nullptr, MROWS, EMBED, FFN);
    }
}